// round 5
// baseline (speedup 1.0000x reference)
#include <cuda_runtime.h>
#include <math.h>

#define BB 64
#define NN 512
#define DD 128
#define KT 16

typedef unsigned long long ull;

__device__ __forceinline__ float2 unpack2(ull v){
    float2 f; asm("mov.b64 {%0, %1}, %2;" : "=f"(f.x), "=f"(f.y) : "l"(v)); return f;
}
__device__ __forceinline__ void fma2(ull &d, ull a, ull b){
    asm("fma.rn.f32x2 %0, %1, %2, %0;" : "+l"(d) : "l"(a), "l"(b));
}
__device__ __forceinline__ unsigned sm32(const void* p){
    return (unsigned)__cvta_generic_to_shared(p);
}
__device__ __forceinline__ void cp16(unsigned dst, const void* src){
    asm volatile("cp.async.cg.shared.global [%0], [%1], 16;" :: "r"(dst), "l"(src));
}
__device__ __forceinline__ void cp_commit(){ asm volatile("cp.async.commit_group;"); }
__device__ __forceinline__ void cp_wait0(){ asm volatile("cp.async.wait_group 0;" ::: "memory"); }

// Scratch (static device globals; no allocation)
__device__ float g_ET [BB*DD*NN];           // E^T per batch: [b][d][i]          (16 MB)
__device__ float g_ETd[BB*DD*2*NN];         // E^T duplicated: [b][d][2i]=(e,e)  (32 MB)
__device__ float g_zd [BB*NN*2*DD];         // z duplicated:   [b][i][2d]=(z,z)  (32 MB)
__device__ float g_P  [(size_t)BB*NN*NN];   // masked exp weights                (64 MB)
__device__ float g_el[BB*NN];
__device__ float g_er[BB*NN];
__device__ float g_th[BB];
__device__ float g_cs[BB*4*NN];             // partial colsums per slot
__device__ float g_pool[BB*4*DD];           // partial pooled sums per j-tile

__constant__ int c_it[10] = {0,0,0,0,1,1,1,2,2,3};
__constant__ int c_jt[10] = {0,1,2,3,1,2,3,2,3,3};

// 32 FFMA2, zero MOVs: A pairs pre-duplicated in smem, B pairs natural
#define FMA_BLOCK \
    fma2(acc[0][0],A0.x,B0.x); fma2(acc[0][1],A0.x,B0.y); fma2(acc[0][2],A0.x,B1.x); fma2(acc[0][3],A0.x,B1.y); \
    fma2(acc[1][0],A0.y,B0.x); fma2(acc[1][1],A0.y,B0.y); fma2(acc[1][2],A0.y,B1.x); fma2(acc[1][3],A0.y,B1.y); \
    fma2(acc[2][0],A1.x,B0.x); fma2(acc[2][1],A1.x,B0.y); fma2(acc[2][2],A1.x,B1.x); fma2(acc[2][3],A1.x,B1.y); \
    fma2(acc[3][0],A1.y,B0.x); fma2(acc[3][1],A1.y,B0.y); fma2(acc[3][2],A1.y,B1.x); fma2(acc[3][3],A1.y,B1.y); \
    fma2(acc[4][0],A2.x,B0.x); fma2(acc[4][1],A2.x,B0.y); fma2(acc[4][2],A2.x,B1.x); fma2(acc[4][3],A2.x,B1.y); \
    fma2(acc[5][0],A2.y,B0.x); fma2(acc[5][1],A2.y,B0.y); fma2(acc[5][2],A2.y,B1.x); fma2(acc[5][3],A2.y,B1.y); \
    fma2(acc[6][0],A3.x,B0.x); fma2(acc[6][1],A3.x,B0.y); fma2(acc[6][2],A3.x,B1.x); fma2(acc[6][3],A3.x,B1.y); \
    fma2(acc[7][0],A3.y,B0.x); fma2(acc[7][1],A3.y,B0.y); fma2(acc[7][2],A3.y,B1.x); fma2(acc[7][3],A3.y,B1.y);

// Prefetch chunk k0: A = duplicated rows (256 floats/row), B = natural (128 floats/row)
#define CPAB(bufidx, k0v, Abase, lda, Bbase, ldb) do { \
    int _k0 = (k0v); \
    _Pragma("unroll") \
    for (int _p = 0; _p < 4; _p++){ \
        int _f = tid + 256*_p; int _kk = _f >> 6; int _cc = (_f & 63) * 4; \
        cp16(sm32(&As[bufidx][_kk][_cc]), (Abase) + (size_t)(_k0+_kk)*(lda) + _cc); \
    } \
    _Pragma("unroll") \
    for (int _p = 0; _p < 2; _p++){ \
        int _f = tid + 256*_p; int _kk = _f >> 5; int _cc = (_f & 31) * 4; \
        cp16(sm32(&Bs[bufidx][_kk][_cc]), (Bbase) + (size_t)(_k0+_kk)*(ldb) + _cc); \
    } \
    cp_commit(); \
} while(0)

#define GEMM_CP(NC, Abase, lda, Bbase, ldb) \
    CPAB(0, 0, Abase, lda, Bbase, ldb); \
    cp_wait0(); \
    __syncthreads(); \
    _Pragma("unroll 1") \
    for (int c = 0; c < (NC); c++){ \
        int buf = c & 1; \
        if (c + 1 < (NC)) CPAB(buf^1, (c+1)*KT, Abase, lda, Bbase, ldb); \
        _Pragma("unroll") \
        for (int k = 0; k < KT; k++){ \
            ulonglong2 A0 = *(const ulonglong2*)&As[buf][k][8*ty]; \
            ulonglong2 A1 = *(const ulonglong2*)&As[buf][k][8*ty+4]; \
            ulonglong2 A2 = *(const ulonglong2*)&As[buf][k][128+8*ty]; \
            ulonglong2 A3 = *(const ulonglong2*)&As[buf][k][128+8*ty+4]; \
            ulonglong2 B0 = *(const ulonglong2*)&Bs[buf][k][4*tx]; \
            ulonglong2 B1 = *(const ulonglong2*)&Bs[buf][k][64+4*tx]; \
            FMA_BLOCK \
        } \
        if (c + 1 < (NC)){ cp_wait0(); __syncthreads(); } \
    }

// ---------------- transpose: ET + duplicated ETd ----------------
__global__ void k_T(const float* __restrict__ E){
    __shared__ float t[32][33];
    int b  = blockIdx.z;
    int i0 = blockIdx.x * 32;
    int d0 = blockIdx.y * 32;
    int tx = threadIdx.x, ty = threadIdx.y;   // (32, 8)
    const float* Eb = E + (size_t)b*NN*DD;
    #pragma unroll
    for (int yy = 0; yy < 32; yy += 8)
        t[ty+yy][tx] = Eb[(size_t)(i0+ty+yy)*DD + d0 + tx];
    __syncthreads();
    float* ETb  = g_ET  + (size_t)b*DD*NN;
    float* ETdb = g_ETd + (size_t)b*DD*2*NN;
    #pragma unroll
    for (int yy = 0; yy < 32; yy += 8){
        float v = t[tx][ty+yy];
        ETb[(size_t)(d0+ty+yy)*NN + i0 + tx] = v;
        *(float2*)&ETdb[(size_t)(d0+ty+yy)*2*NN + 2*(i0 + tx)] = make_float2(v, v);
    }
}

// ---------------- thresh[b] = ||sum_i e_i||^2 / N^2 ----------------
__global__ void k_thresh(const float* __restrict__ E){
    int b = blockIdx.x; int t = threadIdx.x;  // 128 threads
    const float* Eb = E + (size_t)b*NN*DD;
    float s = 0.f;
    for (int i = 0; i < NN; i++) s += Eb[(size_t)i*DD + t];
    __shared__ float red[DD];
    red[t] = s * s;
    __syncthreads();
    for (int o = 64; o > 0; o >>= 1){
        if (t < o) red[t] += red[t+o];
        __syncthreads();
    }
    if (t == 0) g_th[b] = red[0] * (1.f / ((float)NN * (float)NN));
}

// ---------------- z = E @ W  (writes z DUPLICATED; + fused el/er) ----------------
__global__ void __launch_bounds__(256,2) k_z(const float* __restrict__ W,
                                             const float* __restrict__ attn_l,
                                             const float* __restrict__ attn_r){
    __shared__ float As[2][KT][256];
    __shared__ float Bs[2][KT][128];
    int it = blockIdx.x, b = blockIdx.y;
    int tid = threadIdx.x, tx = tid & 15, ty = tid >> 4;
    const float* Ad = g_ETd + (size_t)b*DD*2*NN + 2*(it*128);
    int i0 = it * 128;

    ull acc[8][4];
    #pragma unroll
    for (int r = 0; r < 8; r++)
        #pragma unroll
        for (int p = 0; p < 4; p++) acc[r][p] = 0ull;

    GEMM_CP(DD/KT, Ad, 2*NN, W, DD)

    float al[8], ar[8];
    #pragma unroll
    for (int s = 0; s < 8; s++){
        int d = tx*4 + (s&3) + ((s>>2)<<6);
        al[s] = attn_l[d]; ar[s] = attn_r[d];
    }
    float elp[8], erp[8];
    float* zdb = g_zd + (size_t)b*NN*2*DD;
    #pragma unroll
    for (int r = 0; r < 8; r++){
        int i = i0 + ty*4 + (r&3) + ((r>>2)<<6);
        float v[8];
        #pragma unroll
        for (int p = 0; p < 4; p++){ float2 u = unpack2(acc[r][p]); v[p*2] = u.x; v[p*2+1] = u.y; }
        // duplicated z row: [i][2d]=(z,z)
        *(float4*)&zdb[(size_t)i*2*DD + 8*tx]       = make_float4(v[0],v[0],v[1],v[1]);
        *(float4*)&zdb[(size_t)i*2*DD + 8*tx + 4]   = make_float4(v[2],v[2],v[3],v[3]);
        *(float4*)&zdb[(size_t)i*2*DD + 128 + 8*tx]     = make_float4(v[4],v[4],v[5],v[5]);
        *(float4*)&zdb[(size_t)i*2*DD + 128 + 8*tx + 4] = make_float4(v[6],v[6],v[7],v[7]);
        float pe = 0.f, pr = 0.f;
        #pragma unroll
        for (int s = 0; s < 8; s++){ pe += v[s]*al[s]; pr += v[s]*ar[s]; }
        elp[r] = pe; erp[r] = pr;
    }
    __syncthreads();
    float* redl = &As[0][0][0];
    float* redr = redl + 2048;
    #pragma unroll
    for (int r = 0; r < 8; r++){
        int il = ty*4 + (r&3) + ((r>>2)<<6);
        redl[tx*128 + il] = elp[r];
        redr[tx*128 + il] = erp[r];
    }
    __syncthreads();
    if (tid < 128){
        float se = 0.f, sr = 0.f;
        #pragma unroll
        for (int x = 0; x < 16; x++){ se += redl[x*128 + tid]; sr += redr[x*128 + tid]; }
        g_el[b*NN + i0 + tid] = se;
        g_er[b*NN + i0 + tid] = sr;
    }
}

// ---------------- scores (triangular) -> P both blocks, colsum partials ----------------
__global__ void __launch_bounds__(256,2) k_scoresS(){
    __shared__ float As[2][KT][256];
    __shared__ float Bs[2][KT][128];
    int pr_ = blockIdx.x, b = blockIdx.y;  // grid (10, 64)
    int it = c_it[pr_], jt = c_jt[pr_];
    int tid = threadIdx.x, tx = tid & 15, ty = tid >> 4;
    const float* ETb = g_ET + (size_t)b*DD*NN;
    int i0 = it * 128, j0 = jt * 128;
    const float* Ad = g_ETd + (size_t)b*DD*2*NN + 2*i0;
    const float* Bbase = ETb + j0;

    ull acc[8][4];
    #pragma unroll
    for (int r = 0; r < 8; r++)
        #pragma unroll
        for (int p = 0; p < 4; p++) acc[r][p] = 0ull;

    GEMM_CP(DD/KT, Ad, 2*NN, Bbase, NN)

    float th = g_th[b];
    int gi[8], gj[8]; float eli[8], erj[8], elj[8], eri[8];
    #pragma unroll
    for (int r = 0; r < 8; r++){
        gi[r] = i0 + ty*4 + (r&3) + ((r>>2)<<6);
        eli[r] = g_el[b*NN + gi[r]]; eri[r] = g_er[b*NN + gi[r]];
    }
    #pragma unroll
    for (int s = 0; s < 8; s++){
        gj[s] = j0 + tx*4 + (s&3) + ((s>>2)<<6);
        erj[s] = g_er[b*NN + gj[s]]; elj[s] = g_el[b*NN + gj[s]];
    }

    // ---- primary block P[i][j]; colsum over i (slot it, colblock jt)
    float cs[8];
    #pragma unroll
    for (int s = 0; s < 8; s++) cs[s] = 0.f;
    float* Pb = g_P + (size_t)b*NN*NN;
    #pragma unroll
    for (int r = 0; r < 8; r++){
        float v[8];
        #pragma unroll
        for (int p = 0; p < 4; p++){ float2 u = unpack2(acc[r][p]); v[p*2] = u.x; v[p*2+1] = u.y; }
        float pv[8];
        #pragma unroll
        for (int s = 0; s < 8; s++){
            float e = eli[r] + erj[s];
            e = e > 0.f ? e : 0.2f * e;
            float p = (v[s] > th || gi[r] == gj[s]) ? __expf(e) : 0.f;
            pv[s] = p; cs[s] += p;
        }
        *(float4*)&Pb[(size_t)gi[r]*NN + j0 + tx*4]      = make_float4(pv[0],pv[1],pv[2],pv[3]);
        *(float4*)&Pb[(size_t)gi[r]*NN + j0 + 64 + tx*4] = make_float4(pv[4],pv[5],pv[6],pv[7]);
    }
    float* red = &Bs[0][0][0];        // Bs[0] region: disjoint from last-chunk reads (buf 1)
    #pragma unroll
    for (int s = 0; s < 8; s++) red[ty*128 + (gj[s]-j0)] = cs[s];
    __syncthreads();
    if (tid < 128){
        float t = 0.f;
        #pragma unroll
        for (int x = 0; x < 16; x++) t += red[x*128 + tid];
        g_cs[(b*4 + it)*NN + j0 + tid] = t;
    }

    if (it == jt) return;

    // ---- mirrored block P[j][i] straight from registers
    float cs2[8];
    #pragma unroll
    for (int r = 0; r < 8; r++) cs2[r] = 0.f;
    #pragma unroll
    for (int s = 0; s < 8; s++){
        float tv[8];
        #pragma unroll
        for (int r = 0; r < 8; r++){
            float2 u = unpack2(acc[r][s>>1]);
            float vrs = (s & 1) ? u.y : u.x;
            float e = elj[s] + eri[r];
            e = e > 0.f ? e : 0.2f * e;
            float p = (vrs > th || gi[r] == gj[s]) ? __expf(e) : 0.f;
            tv[r] = p; cs2[r] += p;
        }
        size_t rowb = (size_t)gj[s]*NN + i0;
        *(float4*)&Pb[rowb + ty*4]      = make_float4(tv[0],tv[1],tv[2],tv[3]);
        *(float4*)&Pb[rowb + 64 + ty*4] = make_float4(tv[4],tv[5],tv[6],tv[7]);
    }
    float* red2 = &Bs[0][0][0] + 2048;   // Bs[1] region: post-sync, GEMM reads done
    #pragma unroll
    for (int r = 0; r < 8; r++) red2[tx*128 + (gi[r]-i0)] = cs2[r];
    __syncthreads();
    if (tid < 128){
        float t = 0.f;
        #pragma unroll
        for (int x = 0; x < 16; x++) t += red2[x*128 + tid];
        g_cs[(b*4 + jt)*NN + i0 + tid] = t;
    }
}

// ---------------- h^T = z^T P: out[d][j]; /colsum, +bias, elu, pool ----------------
__global__ void __launch_bounds__(256,2) k_pv(const float* __restrict__ bias){
    __shared__ float As[2][KT][256];
    __shared__ float Bs[2][KT][128];
    int jt = blockIdx.x, b = blockIdx.y;
    int tid = threadIdx.x, tx = tid & 15, ty = tid >> 4;
    const float* Pb = g_P + (size_t)b*NN*NN;
    const float* Ad = g_zd + (size_t)b*NN*2*DD;   // A[k=i][m=d] duplicated
    int j0 = jt * 128;
    const float* Bbase = Pb + j0;                 // B[k=i][n=j] natural

    ull acc[8][4];
    #pragma unroll
    for (int r = 0; r < 8; r++)
        #pragma unroll
        for (int p = 0; p < 4; p++) acc[r][p] = 0ull;

    GEMM_CP(NN/KT, Ad, 2*DD, Bbase, NN)

    // inv colsum per column j (s-indexed)
    float inv[8];
    #pragma unroll
    for (int s = 0; s < 8; s++){
        int j = j0 + tx*4 + (s&3) + ((s>>2)<<6);
        float c0 = g_cs[(b*4 + 0)*NN + j] + g_cs[(b*4 + 1)*NN + j]
                 + g_cs[(b*4 + 2)*NN + j] + g_cs[(b*4 + 3)*NN + j];
        inv[s] = 1.f / c0;
    }
    // bias per row d (r-indexed)
    float bi[8]; int dr[8];
    #pragma unroll
    for (int r = 0; r < 8; r++){ dr[r] = ty*4 + (r&3) + ((r>>2)<<6); bi[r] = bias[dr[r]]; }

    float pd[8];
    #pragma unroll
    for (int r = 0; r < 8; r++) pd[r] = 0.f;
    #pragma unroll
    for (int r = 0; r < 8; r++){
        float v[8];
        #pragma unroll
        for (int p = 0; p < 4; p++){ float2 u = unpack2(acc[r][p]); v[p*2] = u.x; v[p*2+1] = u.y; }
        #pragma unroll
        for (int s = 0; s < 8; s++){
            float h = v[s]*inv[s] + bi[r];
            h = h > 0.f ? h : expm1f(h);
            pd[r] += h;
        }
    }
    __syncthreads();
    float* red = &As[0][0][0];
    #pragma unroll
    for (int r = 0; r < 8; r++) red[tx*128 + dr[r]] = pd[r];
    __syncthreads();
    if (tid < 128){
        float t = 0.f;
        #pragma unroll
        for (int x = 0; x < 16; x++) t += red[x*128 + tid];
        g_pool[(b*4 + jt)*DD + tid] = t;
    }
}

// ---------------- final: mean over nodes ----------------
__global__ void k_out(float* __restrict__ out){
    int b = blockIdx.x, d = threadIdx.x;
    float s = g_pool[(b*4+0)*DD + d] + g_pool[(b*4+1)*DD + d]
            + g_pool[(b*4+2)*DD + d] + g_pool[(b*4+3)*DD + d];
    out[b*DD + d] = s * (1.f / (float)NN);
}

extern "C" void kernel_launch(void* const* d_in, const int* in_sizes, int n_in,
                              void* d_out, int out_size){
    const float* E    = (const float*)d_in[0];
    const float* W    = (const float*)d_in[1];
    const float* al   = (const float*)d_in[2];
    const float* ar   = (const float*)d_in[3];
    const float* bias = (const float*)d_in[4];
    float* out = (float*)d_out;

    k_T      <<<dim3(16,4,64), dim3(32,8)>>>(E);
    k_thresh <<<64, 128>>>(E);
    k_z      <<<dim3(4,64),   256>>>(W, al, ar);
    k_scoresS<<<dim3(10,64),  256>>>();
    k_pv     <<<dim3(4,64),   256>>>(bias);
    k_out    <<<64, 128>>>(out);
}

// round 7
// speedup vs baseline: 1.2059x; 1.2059x over previous
#include <cuda_runtime.h>
#include <cuda_bf16.h>
#include <math.h>
#include <stdint.h>

#define BB 64
#define NN 512
#define DD 128
#define KT 16
#define PITCH 136   // bf16 elems per smem row (272B): conflict-free ldmatrix

typedef unsigned long long ull;

__device__ __forceinline__ ull pack2(float lo, float hi){
    ull r; asm("mov.b64 %0, {%1, %2};" : "=l"(r) : "f"(lo), "f"(hi)); return r;
}
__device__ __forceinline__ float2 unpack2(ull v){
    float2 f; asm("mov.b64 {%0, %1}, %2;" : "=f"(f.x), "=f"(f.y) : "l"(v)); return f;
}
__device__ __forceinline__ void fma2(ull &d, ull a, ull b){
    asm("fma.rn.f32x2 %0, %1, %2, %0;" : "+l"(d) : "l"(a), "l"(b));
}
__device__ __forceinline__ unsigned sm32(const void* p){
    return (unsigned)__cvta_generic_to_shared(p);
}
__device__ __forceinline__ void cp16(unsigned dst, const void* src){
    asm volatile("cp.async.cg.shared.global [%0], [%1], 16;" :: "r"(dst), "l"(src));
}
__device__ __forceinline__ void cp_commit(){ asm volatile("cp.async.commit_group;"); }
__device__ __forceinline__ void cp_wait0(){ asm volatile("cp.async.wait_group 0;" ::: "memory"); }

// ---- warp-level MMA primitives (standard PTX, compute_103-safe) ----
__device__ __forceinline__ void ldmA(uint32_t* a, uint32_t addr){
    asm volatile("ldmatrix.sync.aligned.m8n8.x4.shared.b16 {%0,%1,%2,%3}, [%4];"
        : "=r"(a[0]), "=r"(a[1]), "=r"(a[2]), "=r"(a[3]) : "r"(addr));
}
__device__ __forceinline__ void ldmB(uint32_t* b, uint32_t addr){
    asm volatile("ldmatrix.sync.aligned.m8n8.x2.shared.b16 {%0,%1}, [%2];"
        : "=r"(b[0]), "=r"(b[1]) : "r"(addr));
}
__device__ __forceinline__ void mma16816(float* d, const uint32_t* a, const uint32_t* b){
    asm volatile("mma.sync.aligned.m16n8k16.row.col.f32.bf16.bf16.f32 "
        "{%0,%1,%2,%3}, {%4,%5,%6,%7}, {%8,%9}, {%0,%1,%2,%3};"
        : "+f"(d[0]), "+f"(d[1]), "+f"(d[2]), "+f"(d[3])
        : "r"(a[0]), "r"(a[1]), "r"(a[2]), "r"(a[3]), "r"(b[0]), "r"(b[1]));
}

// Scratch (static device globals; no allocation)
__device__ float g_ET[BB*DD*NN];            // E^T per batch: [b][d][i]
__device__ float g_z [BB*NN*DD];            // z = E @ W
__device__ float g_P [(size_t)BB*NN*NN];    // masked exp weights (fp32)
__device__ __nv_bfloat16 g_Ehi[(size_t)BB*NN*DD];
__device__ __nv_bfloat16 g_Elo[(size_t)BB*NN*DD];
__device__ float g_eel [BB*NN];             // exp(el)
__device__ float g_eel2[BB*NN];             // exp(0.2 el)
__device__ float g_eer [BB*NN];             // exp(er)
__device__ float g_eer2[BB*NN];             // exp(0.2 er)
__device__ float g_th[BB];
__device__ float g_cs[BB*4*NN];             // partial colsums per i-slot
__device__ float g_pool[BB*4*DD];

// ---- R4 FFMA2 GEMM core (k_z, k_pv) ----
#define FMA_BLOCK \
    { ull s; \
      s = pack2(a0.x,a0.x); fma2(acc[0][0],s,B0.x); fma2(acc[0][1],s,B0.y); fma2(acc[0][2],s,B1.x); fma2(acc[0][3],s,B1.y); \
      s = pack2(a0.y,a0.y); fma2(acc[1][0],s,B0.x); fma2(acc[1][1],s,B0.y); fma2(acc[1][2],s,B1.x); fma2(acc[1][3],s,B1.y); \
      s = pack2(a0.z,a0.z); fma2(acc[2][0],s,B0.x); fma2(acc[2][1],s,B0.y); fma2(acc[2][2],s,B1.x); fma2(acc[2][3],s,B1.y); \
      s = pack2(a0.w,a0.w); fma2(acc[3][0],s,B0.x); fma2(acc[3][1],s,B0.y); fma2(acc[3][2],s,B1.x); fma2(acc[3][3],s,B1.y); \
      s = pack2(a1.x,a1.x); fma2(acc[4][0],s,B0.x); fma2(acc[4][1],s,B0.y); fma2(acc[4][2],s,B1.x); fma2(acc[4][3],s,B1.y); \
      s = pack2(a1.y,a1.y); fma2(acc[5][0],s,B0.x); fma2(acc[5][1],s,B0.y); fma2(acc[5][2],s,B1.x); fma2(acc[5][3],s,B1.y); \
      s = pack2(a1.z,a1.z); fma2(acc[6][0],s,B0.x); fma2(acc[6][1],s,B0.y); fma2(acc[6][2],s,B1.x); fma2(acc[6][3],s,B1.y); \
      s = pack2(a1.w,a1.w); fma2(acc[7][0],s,B0.x); fma2(acc[7][1],s,B0.y); fma2(acc[7][2],s,B1.x); fma2(acc[7][3],s,B1.y); }

#define CPAB(bufidx, k0v, Abase, lda, Bbase, ldb) do { \
    int _k0 = (k0v); \
    _Pragma("unroll") \
    for (int _p = 0; _p < 2; _p++){ \
        int _f = tid + 256*_p; int _kk = _f >> 5; int _cc = (_f & 31) * 4; \
        cp16(sm32(&As[bufidx][_kk][_cc]), (Abase) + (size_t)(_k0+_kk)*(lda) + _cc); \
        cp16(sm32(&Bs[bufidx][_kk][_cc]), (Bbase) + (size_t)(_k0+_kk)*(ldb) + _cc); \
    } \
    cp_commit(); \
} while(0)

#define GEMM_CP(NC, Abase, lda, Bbase, ldb) \
    CPAB(0, 0, Abase, lda, Bbase, ldb); \
    cp_wait0(); \
    __syncthreads(); \
    _Pragma("unroll 1") \
    for (int c = 0; c < (NC); c++){ \
        int buf = c & 1; \
        if (c + 1 < (NC)) CPAB(buf^1, (c+1)*KT, Abase, lda, Bbase, ldb); \
        _Pragma("unroll") \
        for (int k = 0; k < KT; k++){ \
            float4 a0 = *(const float4*)&As[buf][k][ty*4]; \
            float4 a1 = *(const float4*)&As[buf][k][64 + ty*4]; \
            ulonglong2 B0 = *(const ulonglong2*)&Bs[buf][k][4*tx]; \
            ulonglong2 B1 = *(const ulonglong2*)&Bs[buf][k][64+4*tx]; \
            FMA_BLOCK \
        } \
        if (c + 1 < (NC)){ cp_wait0(); __syncthreads(); } \
    }

// ---------------- transpose + bf16 split ----------------
__global__ void k_T(const float* __restrict__ E){
    __shared__ float t[32][33];
    int b  = blockIdx.z;
    int i0 = blockIdx.x * 32;
    int d0 = blockIdx.y * 32;
    int tx = threadIdx.x, ty = threadIdx.y;   // (32, 8)
    const float* Eb = E + (size_t)b*NN*DD;
    __nv_bfloat16* Ehb = g_Ehi + (size_t)b*NN*DD;
    __nv_bfloat16* Elb = g_Elo + (size_t)b*NN*DD;
    #pragma unroll
    for (int yy = 0; yy < 32; yy += 8){
        size_t idx = (size_t)(i0+ty+yy)*DD + d0 + tx;
        float v = Eb[idx];
        t[ty+yy][tx] = v;
        __nv_bfloat16 h = __float2bfloat16(v);
        Ehb[idx] = h;
        Elb[idx] = __float2bfloat16(v - __bfloat162float(h));
    }
    __syncthreads();
    float* ETb = g_ET + (size_t)b*DD*NN;
    #pragma unroll
    for (int yy = 0; yy < 32; yy += 8)
        ETb[(size_t)(d0+ty+yy)*NN + i0 + tx] = t[tx][ty+yy];
}

// ---------------- thresh[b] = ||sum_i e_i||^2 / N^2 ----------------
__global__ void k_thresh(const float* __restrict__ E){
    int b = blockIdx.x; int t = threadIdx.x;
    const float* Eb = E + (size_t)b*NN*DD;
    float s = 0.f;
    for (int i = 0; i < NN; i++) s += Eb[(size_t)i*DD + t];
    __shared__ float red[DD];
    red[t] = s * s;
    __syncthreads();
    for (int o = 64; o > 0; o >>= 1){
        if (t < o) red[t] += red[t+o];
        __syncthreads();
    }
    if (t == 0) g_th[b] = red[0] * (1.f / ((float)NN * (float)NN));
}

// ---------------- z = E @ W  (+ fused el/er exp tables) ----------------
__global__ void __launch_bounds__(256,2) k_z(const float* __restrict__ W,
                                             const float* __restrict__ attn_l,
                                             const float* __restrict__ attn_r){
    __shared__ float As[2][KT][128];
    __shared__ float Bs[2][KT][128];
    int it = blockIdx.x, b = blockIdx.y;
    int tid = threadIdx.x, tx = tid & 15, ty = tid >> 4;
    const float* ETb = g_ET + (size_t)b*DD*NN;
    int i0 = it * 128;
    const float* Abase = ETb + i0;

    ull acc[8][4];
    #pragma unroll
    for (int r = 0; r < 8; r++)
        #pragma unroll
        for (int p = 0; p < 4; p++) acc[r][p] = 0ull;

    GEMM_CP(DD/KT, Abase, NN, W, DD)

    float al[8], ar[8];
    #pragma unroll
    for (int s = 0; s < 8; s++){
        int d = tx*4 + (s&3) + ((s>>2)<<6);
        al[s] = attn_l[d]; ar[s] = attn_r[d];
    }
    float elp[8], erp[8];
    float* zb = g_z + (size_t)b*NN*DD;
    #pragma unroll
    for (int r = 0; r < 8; r++){
        int i = i0 + ty*4 + (r&3) + ((r>>2)<<6);
        float v[8];
        #pragma unroll
        for (int p = 0; p < 4; p++){ float2 u = unpack2(acc[r][p]); v[p*2] = u.x; v[p*2+1] = u.y; }
        *(float4*)&zb[(size_t)i*DD + tx*4]      = make_float4(v[0],v[1],v[2],v[3]);
        *(float4*)&zb[(size_t)i*DD + 64 + tx*4] = make_float4(v[4],v[5],v[6],v[7]);
        float pe = 0.f, pr = 0.f;
        #pragma unroll
        for (int s = 0; s < 8; s++){ pe += v[s]*al[s]; pr += v[s]*ar[s]; }
        elp[r] = pe; erp[r] = pr;
    }
    __syncthreads();
    float* redl = &As[0][0][0];
    float* redr = redl + 2048;
    #pragma unroll
    for (int r = 0; r < 8; r++){
        int il = ty*4 + (r&3) + ((r>>2)<<6);
        redl[tx*128 + il] = elp[r];
        redr[tx*128 + il] = erp[r];
    }
    __syncthreads();
    if (tid < 128){
        float se = 0.f, sr = 0.f;
        #pragma unroll
        for (int x = 0; x < 16; x++){ se += redl[x*128 + tid]; sr += redr[x*128 + tid]; }
        int gi = b*NN + i0 + tid;
        g_eel [gi] = __expf(se);
        g_eel2[gi] = __expf(0.2f*se);
        g_eer [gi] = __expf(sr);
        g_eer2[gi] = __expf(0.2f*sr);
    }
}

// ---------------- HMMA scores -> P + colsum partials ----------------
// D[m=j 0..127][n=i 0..127] = sum_d E[j][d] E[i][d], 3-way bf16 split
#define SM_A   0
#define SM_B   (128*PITCH*2)
#define SM_ELI (SM_B + 128*PITCH*2)             // 128 floats
#define SM_ELI2 (SM_ELI + 512)
#define SM_ERJ  (SM_ELI2 + 512)
#define SM_ERJ2 (SM_ERJ + 512)
#define SM_RED  (SM_ERJ2 + 512)                 // 128*4 floats
#define SMEM_MMA (SM_RED + 2048)

__global__ void __launch_bounds__(256,2) k_scores_mma(){
    extern __shared__ char smem[];
    __nv_bfloat16* Asm = (__nv_bfloat16*)(smem + SM_A);
    __nv_bfloat16* Bsm = (__nv_bfloat16*)(smem + SM_B);
    float* sEli  = (float*)(smem + SM_ELI);
    float* sEli2 = (float*)(smem + SM_ELI2);
    float* sErj  = (float*)(smem + SM_ERJ);
    float* sErj2 = (float*)(smem + SM_ERJ2);
    float* red   = (float*)(smem + SM_RED);

    int tid = threadIdx.x;
    int wid = tid >> 5, lane = tid & 31;
    int warp_m = wid >> 2, warp_n = wid & 3;     // 2 x 4 warps
    int g = lane >> 2, t = lane & 3;
    int it = blockIdx.x & 3, jt = blockIdx.x >> 2;
    int b = blockIdx.y;
    int i0 = it * 128, j0 = jt * 128;

    // exp tables
    if (tid < 128){
        sEli [tid] = g_eel [b*NN + i0 + tid];
        sEli2[tid] = g_eel2[b*NN + i0 + tid];
        sErj [tid] = g_eer [b*NN + j0 + tid];
        sErj2[tid] = g_eer2[b*NN + j0 + tid];
    }

    // fragment smem addresses (bytes)
    uint32_t aaddr[4], baddr[4];
    #pragma unroll
    for (int mt = 0; mt < 4; mt++)
        aaddr[mt] = sm32(Asm + (warp_m*64 + mt*16 + (lane & 15))*PITCH + (lane >> 4)*8);
    #pragma unroll
    for (int nt = 0; nt < 4; nt++)
        baddr[nt] = sm32(Bsm + (warp_n*32 + nt*8 + (lane & 7))*PITCH + ((lane >> 3) & 1)*8);

    float d[4][4][4];
    #pragma unroll
    for (int mt = 0; mt < 4; mt++)
        #pragma unroll
        for (int nt = 0; nt < 4; nt++)
            #pragma unroll
            for (int c = 0; c < 4; c++) d[mt][nt][c] = 0.f;

    const __nv_bfloat16* Eh = g_Ehi + (size_t)b*NN*DD;
    const __nv_bfloat16* El = g_Elo + (size_t)b*NN*DD;
    const __nv_bfloat16* Asrc[3] = {Eh + (size_t)j0*DD, Eh + (size_t)j0*DD, El + (size_t)j0*DD};
    const __nv_bfloat16* Bsrc[3] = {Eh + (size_t)i0*DD, El + (size_t)i0*DD, Eh + (size_t)i0*DD};

    #pragma unroll 1
    for (int s = 0; s < 3; s++){
        if (s) __syncthreads();   // previous compute done before overwrite
        #pragma unroll
        for (int p = 0; p < 8; p++){
            int cid = tid + 256*p;
            int row = cid >> 4, kc = cid & 15;
            cp16(sm32(Asm + row*PITCH + kc*8), Asrc[s] + (size_t)row*DD + kc*8);
            cp16(sm32(Bsm + row*PITCH + kc*8), Bsrc[s] + (size_t)row*DD + kc*8);
        }
        cp_commit();
        cp_wait0();
        __syncthreads();
        #pragma unroll 1
        for (int ks = 0; ks < 8; ks++){
            uint32_t af[4][4], bf[4][2];
            #pragma unroll
            for (int mt = 0; mt < 4; mt++) ldmA(af[mt], aaddr[mt] + ks*32);
            #pragma unroll
            for (int nt = 0; nt < 4; nt++) ldmB(bf[nt], baddr[nt] + ks*32);
            #pragma unroll
            for (int mt = 0; mt < 4; mt++)
                #pragma unroll
                for (int nt = 0; nt < 4; nt++)
                    mma16816(d[mt][nt], af[mt], bf[nt]);
        }
    }

    // epilogue
    float th = g_th[b];
    float* Pb = g_P + (size_t)b*NN*NN;
    float cs_p[8];
    #pragma unroll
    for (int mt = 0; mt < 4; mt++){
        #pragma unroll
        for (int half = 0; half < 2; half++){
            int jloc = warp_m*64 + mt*16 + g + 8*half;
            int jg = j0 + jloc;
            float Er = sErj[jloc], Er2 = sErj2[jloc];
            float csl = 0.f;
            #pragma unroll
            for (int nt = 0; nt < 4; nt++){
                #pragma unroll
                for (int par = 0; par < 2; par++){
                    int iloc = warp_n*32 + nt*8 + 2*t + par;
                    int ig = i0 + iloc;
                    float sv = d[mt][nt][half*2 + par];
                    float p = 0.f;
                    if (sv > th || ig == jg){
                        float q = sEli[iloc] * Er;
                        p = (q > 1.f) ? q : sEli2[iloc] * Er2;
                    }
                    csl += p;
                    Pb[(size_t)ig*NN + jg] = p;
                }
            }
            cs_p[mt*2 + half] = csl;
        }
    }
    #pragma unroll
    for (int h = 0; h < 8; h++){
        cs_p[h] += __shfl_xor_sync(0xFFFFFFFFu, cs_p[h], 1);
        cs_p[h] += __shfl_xor_sync(0xFFFFFFFFu, cs_p[h], 2);
    }
    __syncthreads();
    if (t == 0){
        #pragma unroll
        for (int h = 0; h < 8; h++){
            int mt = h >> 1, half = h & 1;
            int jloc = warp_m*64 + mt*16 + g + 8*half;
            red[jloc*4 + warp_n] = cs_p[h];
        }
    }
    __syncthreads();
    if (tid < 128){
        float tcs = red[tid*4] + red[tid*4+1] + red[tid*4+2] + red[tid*4+3];
        g_cs[(b*4 + it)*NN + j0 + tid] = tcs;
    }
}

// ---------------- h = P^T z / colsum; elu(+bias); partial pool ----------------
__global__ void __launch_bounds__(256,2) k_pv(const float* __restrict__ bias){
    __shared__ float As[2][KT][128];
    __shared__ float Bs[2][KT][128];
    int jt = blockIdx.x, b = blockIdx.y;
    int tid = threadIdx.x, tx = tid & 15, ty = tid >> 4;
    const float* Pb = g_P + (size_t)b*NN*NN;
    const float* zb = g_z + (size_t)b*NN*DD;
    int j0 = jt * 128;
    const float* Abase = Pb + j0;

    ull acc[8][4];
    #pragma unroll
    for (int r = 0; r < 8; r++)
        #pragma unroll
        for (int p = 0; p < 4; p++) acc[r][p] = 0ull;

    GEMM_CP(NN/KT, Abase, NN, zb, DD)

    float inv[8];
    #pragma unroll
    for (int r = 0; r < 8; r++){
        int j = j0 + ty*4 + (r&3) + ((r>>2)<<6);
        float c0 = g_cs[(b*4 + 0)*NN + j] + g_cs[(b*4 + 1)*NN + j]
                 + g_cs[(b*4 + 2)*NN + j] + g_cs[(b*4 + 3)*NN + j];
        inv[r] = 1.f / c0;
    }
    float bi[8]; int dl[8];
    #pragma unroll
    for (int s = 0; s < 8; s++){ dl[s] = tx*4 + (s&3) + ((s>>2)<<6); bi[s] = bias[dl[s]]; }

    float pd[8];
    #pragma unroll
    for (int s = 0; s < 8; s++) pd[s] = 0.f;
    #pragma unroll
    for (int r = 0; r < 8; r++){
        float v[8];
        #pragma unroll
        for (int p = 0; p < 4; p++){ float2 u = unpack2(acc[r][p]); v[p*2] = u.x; v[p*2+1] = u.y; }
        #pragma unroll
        for (int s = 0; s < 8; s++){
            float h = v[s]*inv[r] + bi[s];
            h = h > 0.f ? h : expm1f(h);
            pd[s] += h;
        }
    }
    __syncthreads();
    float* red = &As[0][0][0];
    #pragma unroll
    for (int s = 0; s < 8; s++) red[ty*128 + dl[s]] = pd[s];
    __syncthreads();
    if (tid < 128){
        float t = 0.f;
        #pragma unroll
        for (int x = 0; x < 16; x++) t += red[x*128 + tid];
        g_pool[(b*4 + jt)*DD + tid] = t;
    }
}

// ---------------- final: mean over nodes ----------------
__global__ void k_out(float* __restrict__ out){
    int b = blockIdx.x, d = threadIdx.x;
    float s = g_pool[(b*4+0)*DD + d] + g_pool[(b*4+1)*DD + d]
            + g_pool[(b*4+2)*DD + d] + g_pool[(b*4+3)*DD + d];
    out[b*DD + d] = s * (1.f / (float)NN);
}

extern "C" void kernel_launch(void* const* d_in, const int* in_sizes, int n_in,
                              void* d_out, int out_size){
    const float* E    = (const float*)d_in[0];
    const float* W    = (const float*)d_in[1];
    const float* al   = (const float*)d_in[2];
    const float* ar   = (const float*)d_in[3];
    const float* bias = (const float*)d_in[4];
    float* out = (float*)d_out;

    cudaFuncSetAttribute(k_scores_mma, cudaFuncAttributeMaxDynamicSharedMemorySize, SMEM_MMA);

    k_T         <<<dim3(16,4,64), dim3(32,8)>>>(E);
    k_thresh    <<<64, 128>>>(E);
    k_z         <<<dim3(4,64),  256>>>(W, al, ar);
    k_scores_mma<<<dim3(16,64), 256, SMEM_MMA>>>();
    k_pv        <<<dim3(4,64),  256>>>(bias);
    k_out       <<<64, 128>>>(out);
}

// round 8
// speedup vs baseline: 1.3805x; 1.1448x over previous
#include <cuda_runtime.h>
#include <cuda_bf16.h>
#include <math.h>
#include <stdint.h>

#define BB 64
#define NN 512
#define DD 128
#define KT 16
#define PITCH 136   // bf16 elems per smem row (272B): conflict-free ldmatrix
#define PITCH2 40   // bf16 elems per smem row for 32-wide k-chunks (80B)

typedef unsigned long long ull;

__device__ __forceinline__ ull pack2(float lo, float hi){
    ull r; asm("mov.b64 %0, {%1, %2};" : "=l"(r) : "f"(lo), "f"(hi)); return r;
}
__device__ __forceinline__ float2 unpack2(ull v){
    float2 f; asm("mov.b64 {%0, %1}, %2;" : "=f"(f.x), "=f"(f.y) : "l"(v)); return f;
}
__device__ __forceinline__ void fma2(ull &d, ull a, ull b){
    asm("fma.rn.f32x2 %0, %1, %2, %0;" : "+l"(d) : "l"(a), "l"(b));
}
__device__ __forceinline__ unsigned sm32(const void* p){
    return (unsigned)__cvta_generic_to_shared(p);
}
__device__ __forceinline__ void cp16(unsigned dst, const void* src){
    asm volatile("cp.async.cg.shared.global [%0], [%1], 16;" :: "r"(dst), "l"(src));
}
__device__ __forceinline__ void cp_commit(){ asm volatile("cp.async.commit_group;"); }
__device__ __forceinline__ void cp_wait0(){ asm volatile("cp.async.wait_group 0;" ::: "memory"); }

// ---- warp-level MMA primitives (standard PTX, compute_103-safe) ----
__device__ __forceinline__ void ldmA(uint32_t* a, uint32_t addr){
    asm volatile("ldmatrix.sync.aligned.m8n8.x4.shared.b16 {%0,%1,%2,%3}, [%4];"
        : "=r"(a[0]), "=r"(a[1]), "=r"(a[2]), "=r"(a[3]) : "r"(addr));
}
__device__ __forceinline__ void ldmB(uint32_t* b, uint32_t addr){
    asm volatile("ldmatrix.sync.aligned.m8n8.x2.shared.b16 {%0,%1}, [%2];"
        : "=r"(b[0]), "=r"(b[1]) : "r"(addr));
}
__device__ __forceinline__ void mma16816(float* d, const uint32_t* a, const uint32_t* b){
    asm volatile("mma.sync.aligned.m16n8k16.row.col.f32.bf16.bf16.f32 "
        "{%0,%1,%2,%3}, {%4,%5,%6,%7}, {%8,%9}, {%0,%1,%2,%3};"
        : "+f"(d[0]), "+f"(d[1]), "+f"(d[2]), "+f"(d[3])
        : "r"(a[0]), "r"(a[1]), "r"(a[2]), "r"(a[3]), "r"(b[0]), "r"(b[1]));
}

// Scratch (static device globals; no allocation)
__device__ float g_ET[BB*DD*NN];            // E^T per batch: [b][d][i]
__device__ float g_z [BB*NN*DD];            // z = E @ W
__device__ __nv_bfloat16 g_Ehi[(size_t)BB*NN*DD];
__device__ __nv_bfloat16 g_Elo[(size_t)BB*NN*DD];
__device__ __nv_bfloat16 g_Pthi[(size_t)BB*NN*NN];  // P^T hi: [b][j][i] (32 MB)
__device__ __nv_bfloat16 g_Ptlo[(size_t)BB*NN*NN];  // P^T lo             (32 MB)
__device__ __nv_bfloat16 g_zThi[(size_t)BB*DD*NN];  // z^T hi: [b][d][i]
__device__ __nv_bfloat16 g_zTlo[(size_t)BB*DD*NN];
__device__ float g_eel [BB*NN];             // exp(el)
__device__ float g_eel2[BB*NN];             // exp(0.2 el)
__device__ float g_eer [BB*NN];             // exp(er)
__device__ float g_eer2[BB*NN];             // exp(0.2 er)
__device__ float g_th[BB];
__device__ float g_cs[BB*4*NN];             // partial colsums per i-slot
__device__ float g_pool[BB*4*DD];

// ---- R4 FFMA2 GEMM core (k_z only) ----
#define FMA_BLOCK \
    { ull s; \
      s = pack2(a0.x,a0.x); fma2(acc[0][0],s,B0.x); fma2(acc[0][1],s,B0.y); fma2(acc[0][2],s,B1.x); fma2(acc[0][3],s,B1.y); \
      s = pack2(a0.y,a0.y); fma2(acc[1][0],s,B0.x); fma2(acc[1][1],s,B0.y); fma2(acc[1][2],s,B1.x); fma2(acc[1][3],s,B1.y); \
      s = pack2(a0.z,a0.z); fma2(acc[2][0],s,B0.x); fma2(acc[2][1],s,B0.y); fma2(acc[2][2],s,B1.x); fma2(acc[2][3],s,B1.y); \
      s = pack2(a0.w,a0.w); fma2(acc[3][0],s,B0.x); fma2(acc[3][1],s,B0.y); fma2(acc[3][2],s,B1.x); fma2(acc[3][3],s,B1.y); \
      s = pack2(a1.x,a1.x); fma2(acc[4][0],s,B0.x); fma2(acc[4][1],s,B0.y); fma2(acc[4][2],s,B1.x); fma2(acc[4][3],s,B1.y); \
      s = pack2(a1.y,a1.y); fma2(acc[5][0],s,B0.x); fma2(acc[5][1],s,B0.y); fma2(acc[5][2],s,B1.x); fma2(acc[5][3],s,B1.y); \
      s = pack2(a1.z,a1.z); fma2(acc[6][0],s,B0.x); fma2(acc[6][1],s,B0.y); fma2(acc[6][2],s,B1.x); fma2(acc[6][3],s,B1.y); \
      s = pack2(a1.w,a1.w); fma2(acc[7][0],s,B0.x); fma2(acc[7][1],s,B0.y); fma2(acc[7][2],s,B1.x); fma2(acc[7][3],s,B1.y); }

#define CPAB(bufidx, k0v, Abase, lda, Bbase, ldb) do { \
    int _k0 = (k0v); \
    _Pragma("unroll") \
    for (int _p = 0; _p < 2; _p++){ \
        int _f = tid + 256*_p; int _kk = _f >> 5; int _cc = (_f & 31) * 4; \
        cp16(sm32(&As[bufidx][_kk][_cc]), (Abase) + (size_t)(_k0+_kk)*(lda) + _cc); \
        cp16(sm32(&Bs[bufidx][_kk][_cc]), (Bbase) + (size_t)(_k0+_kk)*(ldb) + _cc); \
    } \
    cp_commit(); \
} while(0)

#define GEMM_CP(NC, Abase, lda, Bbase, ldb) \
    CPAB(0, 0, Abase, lda, Bbase, ldb); \
    cp_wait0(); \
    __syncthreads(); \
    _Pragma("unroll 1") \
    for (int c = 0; c < (NC); c++){ \
        int buf = c & 1; \
        if (c + 1 < (NC)) CPAB(buf^1, (c+1)*KT, Abase, lda, Bbase, ldb); \
        _Pragma("unroll") \
        for (int k = 0; k < KT; k++){ \
            float4 a0 = *(const float4*)&As[buf][k][ty*4]; \
            float4 a1 = *(const float4*)&As[buf][k][64 + ty*4]; \
            ulonglong2 B0 = *(const ulonglong2*)&Bs[buf][k][4*tx]; \
            ulonglong2 B1 = *(const ulonglong2*)&Bs[buf][k][64+4*tx]; \
            FMA_BLOCK \
        } \
        if (c + 1 < (NC)){ cp_wait0(); __syncthreads(); } \
    }

// ---------------- transpose + bf16 split of E ----------------
__global__ void k_T(const float* __restrict__ E){
    __shared__ float t[32][33];
    int b  = blockIdx.z;
    int i0 = blockIdx.x * 32;
    int d0 = blockIdx.y * 32;
    int tx = threadIdx.x, ty = threadIdx.y;   // (32, 8)
    const float* Eb = E + (size_t)b*NN*DD;
    __nv_bfloat16* Ehb = g_Ehi + (size_t)b*NN*DD;
    __nv_bfloat16* Elb = g_Elo + (size_t)b*NN*DD;
    #pragma unroll
    for (int yy = 0; yy < 32; yy += 8){
        size_t idx = (size_t)(i0+ty+yy)*DD + d0 + tx;
        float v = Eb[idx];
        t[ty+yy][tx] = v;
        __nv_bfloat16 h = __float2bfloat16(v);
        Ehb[idx] = h;
        Elb[idx] = __float2bfloat16(v - __bfloat162float(h));
    }
    __syncthreads();
    float* ETb = g_ET + (size_t)b*DD*NN;
    #pragma unroll
    for (int yy = 0; yy < 32; yy += 8)
        ETb[(size_t)(d0+ty+yy)*NN + i0 + tx] = t[tx][ty+yy];
}

// ---------------- thresh[b] = ||sum_i e_i||^2 / N^2 ----------------
__global__ void k_thresh(const float* __restrict__ E){
    int b = blockIdx.x; int t = threadIdx.x;
    const float* Eb = E + (size_t)b*NN*DD;
    float s = 0.f;
    for (int i = 0; i < NN; i++) s += Eb[(size_t)i*DD + t];
    __shared__ float red[DD];
    red[t] = s * s;
    __syncthreads();
    for (int o = 64; o > 0; o >>= 1){
        if (t < o) red[t] += red[t+o];
        __syncthreads();
    }
    if (t == 0) g_th[b] = red[0] * (1.f / ((float)NN * (float)NN));
}

// ---------------- z = E @ W  (+ fused el/er exp tables) ----------------
__global__ void __launch_bounds__(256,2) k_z(const float* __restrict__ W,
                                             const float* __restrict__ attn_l,
                                             const float* __restrict__ attn_r){
    __shared__ float As[2][KT][128];
    __shared__ float Bs[2][KT][128];
    int it = blockIdx.x, b = blockIdx.y;
    int tid = threadIdx.x, tx = tid & 15, ty = tid >> 4;
    const float* ETb = g_ET + (size_t)b*DD*NN;
    int i0 = it * 128;
    const float* Abase = ETb + i0;

    ull acc[8][4];
    #pragma unroll
    for (int r = 0; r < 8; r++)
        #pragma unroll
        for (int p = 0; p < 4; p++) acc[r][p] = 0ull;

    GEMM_CP(DD/KT, Abase, NN, W, DD)

    float al[8], ar[8];
    #pragma unroll
    for (int s = 0; s < 8; s++){
        int d = tx*4 + (s&3) + ((s>>2)<<6);
        al[s] = attn_l[d]; ar[s] = attn_r[d];
    }
    float elp[8], erp[8];
    float* zb = g_z + (size_t)b*NN*DD;
    #pragma unroll
    for (int r = 0; r < 8; r++){
        int i = i0 + ty*4 + (r&3) + ((r>>2)<<6);
        float v[8];
        #pragma unroll
        for (int p = 0; p < 4; p++){ float2 u = unpack2(acc[r][p]); v[p*2] = u.x; v[p*2+1] = u.y; }
        *(float4*)&zb[(size_t)i*DD + tx*4]      = make_float4(v[0],v[1],v[2],v[3]);
        *(float4*)&zb[(size_t)i*DD + 64 + tx*4] = make_float4(v[4],v[5],v[6],v[7]);
        float pe = 0.f, pr = 0.f;
        #pragma unroll
        for (int s = 0; s < 8; s++){ pe += v[s]*al[s]; pr += v[s]*ar[s]; }
        elp[r] = pe; erp[r] = pr;
    }
    __syncthreads();
    float* redl = &As[0][0][0];
    float* redr = redl + 2048;
    #pragma unroll
    for (int r = 0; r < 8; r++){
        int il = ty*4 + (r&3) + ((r>>2)<<6);
        redl[tx*128 + il] = elp[r];
        redr[tx*128 + il] = erp[r];
    }
    __syncthreads();
    if (tid < 128){
        float se = 0.f, sr = 0.f;
        #pragma unroll
        for (int x = 0; x < 16; x++){ se += redl[x*128 + tid]; sr += redr[x*128 + tid]; }
        int gi = b*NN + i0 + tid;
        g_eel [gi] = __expf(se);
        g_eel2[gi] = __expf(0.2f*se);
        g_eer [gi] = __expf(sr);
        g_eer2[gi] = __expf(0.2f*sr);
    }
}

// ---------------- z transpose + bf16 split: zT[d][i] ----------------
__global__ void k_zT(){
    __shared__ float t[32][33];
    int b  = blockIdx.z;
    int i0 = blockIdx.x * 32;
    int d0 = blockIdx.y * 32;
    int tx = threadIdx.x, ty = threadIdx.y;   // (32, 8)
    const float* zb = g_z + (size_t)b*NN*DD;
    #pragma unroll
    for (int yy = 0; yy < 32; yy += 8)
        t[ty+yy][tx] = zb[(size_t)(i0+ty+yy)*DD + d0 + tx];
    __syncthreads();
    __nv_bfloat16* zh = g_zThi + (size_t)b*DD*NN;
    __nv_bfloat16* zl = g_zTlo + (size_t)b*DD*NN;
    #pragma unroll
    for (int yy = 0; yy < 32; yy += 8){
        float v = t[tx][ty+yy];                  // z[i0+tx][d0+ty+yy]
        size_t idx = (size_t)(d0+ty+yy)*NN + i0 + tx;
        __nv_bfloat16 h = __float2bfloat16(v);
        zh[idx] = h;
        zl[idx] = __float2bfloat16(v - __bfloat162float(h));
    }
}

// ---------------- HMMA scores -> Pt (bf16 hi/lo) + colsum partials ----------------
#define SM_A   0
#define SM_B   (128*PITCH*2)
#define SM_ELI (SM_B + 128*PITCH*2)
#define SM_ELI2 (SM_ELI + 512)
#define SM_ERJ  (SM_ELI2 + 512)
#define SM_ERJ2 (SM_ERJ + 512)
#define SM_RED  (SM_ERJ2 + 512)
#define SMEM_MMA (SM_RED + 2048)

__global__ void __launch_bounds__(256,2) k_scores_mma(){
    extern __shared__ char smem[];
    __nv_bfloat16* Asm = (__nv_bfloat16*)(smem + SM_A);
    __nv_bfloat16* Bsm = (__nv_bfloat16*)(smem + SM_B);
    float* sEli  = (float*)(smem + SM_ELI);
    float* sEli2 = (float*)(smem + SM_ELI2);
    float* sErj  = (float*)(smem + SM_ERJ);
    float* sErj2 = (float*)(smem + SM_ERJ2);
    float* red   = (float*)(smem + SM_RED);

    int tid = threadIdx.x;
    int wid = tid >> 5, lane = tid & 31;
    int warp_m = wid >> 2, warp_n = wid & 3;     // 2 x 4 warps
    int g = lane >> 2, t = lane & 3;
    int it = blockIdx.x & 3, jt = blockIdx.x >> 2;
    int b = blockIdx.y;
    int i0 = it * 128, j0 = jt * 128;

    if (tid < 128){
        sEli [tid] = g_eel [b*NN + i0 + tid];
        sEli2[tid] = g_eel2[b*NN + i0 + tid];
        sErj [tid] = g_eer [b*NN + j0 + tid];
        sErj2[tid] = g_eer2[b*NN + j0 + tid];
    }

    uint32_t aaddr[4], baddr[4];
    #pragma unroll
    for (int mt = 0; mt < 4; mt++)
        aaddr[mt] = sm32(Asm + (warp_m*64 + mt*16 + (lane & 15))*PITCH + (lane >> 4)*8);
    #pragma unroll
    for (int nt = 0; nt < 4; nt++)
        baddr[nt] = sm32(Bsm + (warp_n*32 + nt*8 + (lane & 7))*PITCH + ((lane >> 3) & 1)*8);

    float d[4][4][4];
    #pragma unroll
    for (int mt = 0; mt < 4; mt++)
        #pragma unroll
        for (int nt = 0; nt < 4; nt++)
            #pragma unroll
            for (int c = 0; c < 4; c++) d[mt][nt][c] = 0.f;

    const __nv_bfloat16* Eh = g_Ehi + (size_t)b*NN*DD;
    const __nv_bfloat16* El = g_Elo + (size_t)b*NN*DD;
    const __nv_bfloat16* Asrc[3] = {Eh + (size_t)j0*DD, Eh + (size_t)j0*DD, El + (size_t)j0*DD};
    const __nv_bfloat16* Bsrc[3] = {Eh + (size_t)i0*DD, El + (size_t)i0*DD, Eh + (size_t)i0*DD};

    #pragma unroll 1
    for (int s = 0; s < 3; s++){
        if (s) __syncthreads();
        #pragma unroll
        for (int p = 0; p < 8; p++){
            int cid = tid + 256*p;
            int row = cid >> 4, kc = cid & 15;
            cp16(sm32(Asm + row*PITCH + kc*8), Asrc[s] + (size_t)row*DD + kc*8);
            cp16(sm32(Bsm + row*PITCH + kc*8), Bsrc[s] + (size_t)row*DD + kc*8);
        }
        cp_commit();
        cp_wait0();
        __syncthreads();
        #pragma unroll 1
        for (int ks = 0; ks < 8; ks++){
            uint32_t af[4][4], bf[4][2];
            #pragma unroll
            for (int mt = 0; mt < 4; mt++) ldmA(af[mt], aaddr[mt] + ks*32);
            #pragma unroll
            for (int nt = 0; nt < 4; nt++) ldmB(bf[nt], baddr[nt] + ks*32);
            #pragma unroll
            for (int mt = 0; mt < 4; mt++)
                #pragma unroll
                for (int nt = 0; nt < 4; nt++)
                    mma16816(d[mt][nt], af[mt], bf[nt]);
        }
    }

    // epilogue: Pt[j][i] bf16 hi/lo + colsum
    float th = g_th[b];
    __nv_bfloat16* Ph = g_Pthi + (size_t)b*NN*NN;
    __nv_bfloat16* Pl = g_Ptlo + (size_t)b*NN*NN;
    float cs_p[8];
    #pragma unroll
    for (int mt = 0; mt < 4; mt++){
        #pragma unroll
        for (int half = 0; half < 2; half++){
            int jloc = warp_m*64 + mt*16 + g + 8*half;
            int jg = j0 + jloc;
            float Er = sErj[jloc], Er2 = sErj2[jloc];
            float csl = 0.f;
            #pragma unroll
            for (int nt = 0; nt < 4; nt++){
                float pv[2];
                #pragma unroll
                for (int par = 0; par < 2; par++){
                    int iloc = warp_n*32 + nt*8 + 2*t + par;
                    int ig = i0 + iloc;
                    float sv = d[mt][nt][half*2 + par];
                    float p = 0.f;
                    if (sv > th || ig == jg){
                        float q = sEli[iloc] * Er;
                        p = (q > 1.f) ? q : sEli2[iloc] * Er2;
                    }
                    csl += p; pv[par] = p;
                }
                __nv_bfloat16 h0 = __float2bfloat16(pv[0]);
                __nv_bfloat16 h1 = __float2bfloat16(pv[1]);
                __nv_bfloat16 l0 = __float2bfloat16(pv[0] - __bfloat162float(h0));
                __nv_bfloat16 l1 = __float2bfloat16(pv[1] - __bfloat162float(h1));
                size_t addr = (size_t)jg*NN + i0 + warp_n*32 + nt*8 + 2*t;
                *(__nv_bfloat162*)&Ph[addr] = __halves2bfloat162(h0, h1);
                *(__nv_bfloat162*)&Pl[addr] = __halves2bfloat162(l0, l1);
            }
            cs_p[mt*2 + half] = csl;
        }
    }
    #pragma unroll
    for (int h = 0; h < 8; h++){
        cs_p[h] += __shfl_xor_sync(0xFFFFFFFFu, cs_p[h], 1);
        cs_p[h] += __shfl_xor_sync(0xFFFFFFFFu, cs_p[h], 2);
    }
    __syncthreads();
    if (t == 0){
        #pragma unroll
        for (int h = 0; h < 8; h++){
            int mt = h >> 1, half = h & 1;
            int jloc = warp_m*64 + mt*16 + g + 8*half;
            red[jloc*4 + warp_n] = cs_p[h];
        }
    }
    __syncthreads();
    if (tid < 128){
        float tcs = red[tid*4] + red[tid*4+1] + red[tid*4+2] + red[tid*4+3];
        g_cs[(b*4 + it)*NN + j0 + tid] = tcs;
    }
}

// ---------------- HMMA PV: h[j][d] = sum_i Pt[j][i] z[i][d]; /cs,+bias,elu,pool ----------------
#define TILEB (128*PITCH2*2)
#define SMP_CS (4*TILEB)
#define SMP_RED (SMP_CS + 512)
#define SMEM_PV (SMP_RED + 1024)

__global__ void __launch_bounds__(256,2) k_pv_mma(const float* __restrict__ bias){
    extern __shared__ char smem[];
    uint32_t sb = sm32(smem);
    float* sCs = (float*)(smem + SMP_CS);
    float* red = (float*)(smem + SMP_RED);
    int tid = threadIdx.x, wid = tid >> 5, lane = tid & 31;
    int warp_m = wid >> 2, warp_n = wid & 3;
    int g = lane >> 2, t = lane & 3;
    int jt = blockIdx.x, b = blockIdx.y;
    int j0 = jt * 128;

    if (tid < 128){
        int j = j0 + tid;
        sCs[tid] = g_cs[(b*4+0)*NN + j] + g_cs[(b*4+1)*NN + j]
                 + g_cs[(b*4+2)*NN + j] + g_cs[(b*4+3)*NN + j];
    }
    float bi[8];
    #pragma unroll
    for (int nt = 0; nt < 4; nt++)
        #pragma unroll
        for (int par = 0; par < 2; par++)
            bi[nt*2+par] = bias[warp_n*32 + nt*8 + 2*t + par];

    const __nv_bfloat16* srcs[4];
    srcs[0] = g_Pthi + (size_t)b*NN*NN + (size_t)j0*NN;
    srcs[1] = g_Ptlo + (size_t)b*NN*NN + (size_t)j0*NN;
    srcs[2] = g_zThi + (size_t)b*DD*NN;
    srcs[3] = g_zTlo + (size_t)b*DD*NN;

    uint32_t aPh[4], aPl[4], bZh[4], bZl[4];
    #pragma unroll
    for (int mt = 0; mt < 4; mt++){
        int row = warp_m*64 + mt*16 + (lane & 15);
        int c8  = (lane >> 4)*8;
        aPh[mt] = sb + 0*TILEB + (row*PITCH2 + c8)*2;
        aPl[mt] = sb + 1*TILEB + (row*PITCH2 + c8)*2;
    }
    #pragma unroll
    for (int nt = 0; nt < 4; nt++){
        int row = warp_n*32 + nt*8 + (lane & 7);
        int c8  = ((lane >> 3) & 1)*8;
        bZh[nt] = sb + 2*TILEB + (row*PITCH2 + c8)*2;
        bZl[nt] = sb + 3*TILEB + (row*PITCH2 + c8)*2;
    }

    float d[4][4][4];
    #pragma unroll
    for (int mt = 0; mt < 4; mt++)
        #pragma unroll
        for (int nt = 0; nt < 4; nt++)
            #pragma unroll
            for (int c = 0; c < 4; c++) d[mt][nt][c] = 0.f;

    #pragma unroll 1
    for (int c = 0; c < 16; c++){
        if (c) __syncthreads();
        #pragma unroll
        for (int p = 0; p < 8; p++){
            int arr = p >> 1;
            int slot = tid + 256*(p & 1);
            int row = slot >> 2, seg = slot & 3;
            cp16(sb + arr*TILEB + (row*PITCH2 + seg*8)*2,
                 srcs[arr] + (size_t)row*NN + c*32 + seg*8);
        }
        cp_commit();
        cp_wait0();
        __syncthreads();
        #pragma unroll
        for (int ks = 0; ks < 2; ks++){
            uint32_t bh[4][2], bl[4][2];
            #pragma unroll
            for (int nt = 0; nt < 4; nt++){
                ldmB(bh[nt], bZh[nt] + ks*32);
                ldmB(bl[nt], bZl[nt] + ks*32);
            }
            #pragma unroll
            for (int mt = 0; mt < 4; mt++){
                uint32_t ah[4], al[4];
                ldmA(ah, aPh[mt] + ks*32);
                ldmA(al, aPl[mt] + ks*32);
                #pragma unroll
                for (int nt = 0; nt < 4; nt++){
                    mma16816(d[mt][nt], ah, bh[nt]);
                    mma16816(d[mt][nt], ah, bl[nt]);
                    mma16816(d[mt][nt], al, bh[nt]);
                }
            }
        }
    }

    // epilogue: /cs, +bias, elu, pool over j
    float pd[8];
    #pragma unroll
    for (int q = 0; q < 8; q++) pd[q] = 0.f;
    #pragma unroll
    for (int mt = 0; mt < 4; mt++){
        #pragma unroll
        for (int half = 0; half < 2; half++){
            int jloc = warp_m*64 + mt*16 + g + 8*half;
            float inv = 1.f / sCs[jloc];
            #pragma unroll
            for (int nt = 0; nt < 4; nt++)
                #pragma unroll
                for (int par = 0; par < 2; par++){
                    float v = d[mt][nt][half*2+par]*inv + bi[nt*2+par];
                    v = v > 0.f ? v : expm1f(v);
                    pd[nt*2+par] += v;
                }
        }
    }
    #pragma unroll
    for (int q = 0; q < 8; q++){
        pd[q] += __shfl_xor_sync(0xFFFFFFFFu, pd[q], 4);
        pd[q] += __shfl_xor_sync(0xFFFFFFFFu, pd[q], 8);
        pd[q] += __shfl_xor_sync(0xFFFFFFFFu, pd[q], 16);
    }
    __syncthreads();
    if (g == 0){
        #pragma unroll
        for (int nt = 0; nt < 4; nt++)
            #pragma unroll
            for (int par = 0; par < 2; par++)
                red[warp_m*128 + warp_n*32 + nt*8 + 2*t + par] = pd[nt*2+par];
    }
    __syncthreads();
    if (tid < 128)
        g_pool[(b*4 + jt)*DD + tid] = red[tid] + red[128 + tid];
}

// ---------------- final: mean over nodes ----------------
__global__ void k_out(float* __restrict__ out){
    int b = blockIdx.x, d = threadIdx.x;
    float s = g_pool[(b*4+0)*DD + d] + g_pool[(b*4+1)*DD + d]
            + g_pool[(b*4+2)*DD + d] + g_pool[(b*4+3)*DD + d];
    out[b*DD + d] = s * (1.f / (float)NN);
}

extern "C" void kernel_launch(void* const* d_in, const int* in_sizes, int n_in,
                              void* d_out, int out_size){
    const float* E    = (const float*)d_in[0];
    const float* W    = (const float*)d_in[1];
    const float* al   = (const float*)d_in[2];
    const float* ar   = (const float*)d_in[3];
    const float* bias = (const float*)d_in[4];
    float* out = (float*)d_out;

    cudaFuncSetAttribute(k_scores_mma, cudaFuncAttributeMaxDynamicSharedMemorySize, SMEM_MMA);
    cudaFuncSetAttribute(k_pv_mma,     cudaFuncAttributeMaxDynamicSharedMemorySize, SMEM_PV);

    k_T         <<<dim3(16,4,64), dim3(32,8)>>>(E);
    k_thresh    <<<64, 128>>>(E);
    k_z         <<<dim3(4,64),  256>>>(W, al, ar);
    k_zT        <<<dim3(16,4,64), dim3(32,8)>>>();
    k_scores_mma<<<dim3(16,64), 256, SMEM_MMA>>>();
    k_pv_mma    <<<dim3(4,64),  256, SMEM_PV>>>(bias);
    k_out       <<<64, 128>>>(out);
}

// round 9
// speedup vs baseline: 1.4508x; 1.0509x over previous
#include <cuda_runtime.h>
#include <cuda_bf16.h>
#include <math.h>
#include <stdint.h>

#define BB 64
#define NN 512
#define DD 128
#define KT 16
#define PITCH 136   // bf16 elems per smem row (272B): conflict-free ldmatrix
#define PITCH2 40   // bf16 elems per smem row for 32-wide k-chunks (80B)

typedef unsigned long long ull;

__device__ __forceinline__ ull pack2(float lo, float hi){
    ull r; asm("mov.b64 %0, {%1, %2};" : "=l"(r) : "f"(lo), "f"(hi)); return r;
}
__device__ __forceinline__ float2 unpack2(ull v){
    float2 f; asm("mov.b64 {%0, %1}, %2;" : "=f"(f.x), "=f"(f.y) : "l"(v)); return f;
}
__device__ __forceinline__ void fma2(ull &d, ull a, ull b){
    asm("fma.rn.f32x2 %0, %1, %2, %0;" : "+l"(d) : "l"(a), "l"(b));
}
__device__ __forceinline__ unsigned sm32(const void* p){
    return (unsigned)__cvta_generic_to_shared(p);
}
__device__ __forceinline__ void cp16(unsigned dst, const void* src){
    asm volatile("cp.async.cg.shared.global [%0], [%1], 16;" :: "r"(dst), "l"(src));
}
__device__ __forceinline__ void cp_commit(){ asm volatile("cp.async.commit_group;"); }
__device__ __forceinline__ void cp_wait0(){ asm volatile("cp.async.wait_group 0;" ::: "memory"); }
__device__ __forceinline__ void cp_wait1(){ asm volatile("cp.async.wait_group 1;" ::: "memory"); }

// ---- warp-level MMA primitives (standard PTX, compute_103-safe) ----
__device__ __forceinline__ void ldmA(uint32_t* a, uint32_t addr){
    asm volatile("ldmatrix.sync.aligned.m8n8.x4.shared.b16 {%0,%1,%2,%3}, [%4];"
        : "=r"(a[0]), "=r"(a[1]), "=r"(a[2]), "=r"(a[3]) : "r"(addr));
}
__device__ __forceinline__ void ldmB(uint32_t* b, uint32_t addr){
    asm volatile("ldmatrix.sync.aligned.m8n8.x2.shared.b16 {%0,%1}, [%2];"
        : "=r"(b[0]), "=r"(b[1]) : "r"(addr));
}
__device__ __forceinline__ void mma16816(float* d, const uint32_t* a, const uint32_t* b){
    asm volatile("mma.sync.aligned.m16n8k16.row.col.f32.bf16.bf16.f32 "
        "{%0,%1,%2,%3}, {%4,%5,%6,%7}, {%8,%9}, {%0,%1,%2,%3};"
        : "+f"(d[0]), "+f"(d[1]), "+f"(d[2]), "+f"(d[3])
        : "r"(a[0]), "r"(a[1]), "r"(a[2]), "r"(a[3]), "r"(b[0]), "r"(b[1]));
}

// Scratch (static device globals; no allocation)
__device__ float g_ET[BB*DD*NN];            // E^T per batch: [b][d][i]
__device__ float g_z [BB*NN*DD];            // z = E @ W
__device__ __nv_bfloat16 g_Ehi[(size_t)BB*NN*DD];
__device__ __nv_bfloat16 g_Elo[(size_t)BB*NN*DD];
__device__ __nv_bfloat16 g_Pthi[(size_t)BB*NN*NN];  // P^T hi: [b][j][i]
__device__ __nv_bfloat16 g_Ptlo[(size_t)BB*NN*NN];  // P^T lo
__device__ __nv_bfloat16 g_zThi[(size_t)BB*DD*NN];  // z^T hi: [b][d][i]
__device__ __nv_bfloat16 g_zTlo[(size_t)BB*DD*NN];
__device__ float g_eel [BB*NN];
__device__ float g_eel2[BB*NN];
__device__ float g_eer [BB*NN];
__device__ float g_eer2[BB*NN];
__device__ float g_th[BB];
__device__ float g_cs[BB*4*NN];
__device__ float g_pool[BB*4*DD];

// ---- R4 FFMA2 GEMM core (k_z only) ----
#define FMA_BLOCK \
    { ull s; \
      s = pack2(a0.x,a0.x); fma2(acc[0][0],s,B0.x); fma2(acc[0][1],s,B0.y); fma2(acc[0][2],s,B1.x); fma2(acc[0][3],s,B1.y); \
      s = pack2(a0.y,a0.y); fma2(acc[1][0],s,B0.x); fma2(acc[1][1],s,B0.y); fma2(acc[1][2],s,B1.x); fma2(acc[1][3],s,B1.y); \
      s = pack2(a0.z,a0.z); fma2(acc[2][0],s,B0.x); fma2(acc[2][1],s,B0.y); fma2(acc[2][2],s,B1.x); fma2(acc[2][3],s,B1.y); \
      s = pack2(a0.w,a0.w); fma2(acc[3][0],s,B0.x); fma2(acc[3][1],s,B0.y); fma2(acc[3][2],s,B1.x); fma2(acc[3][3],s,B1.y); \
      s = pack2(a1.x,a1.x); fma2(acc[4][0],s,B0.x); fma2(acc[4][1],s,B0.y); fma2(acc[4][2],s,B1.x); fma2(acc[4][3],s,B1.y); \
      s = pack2(a1.y,a1.y); fma2(acc[5][0],s,B0.x); fma2(acc[5][1],s,B0.y); fma2(acc[5][2],s,B1.x); fma2(acc[5][3],s,B1.y); \
      s = pack2(a1.z,a1.z); fma2(acc[6][0],s,B0.x); fma2(acc[6][1],s,B0.y); fma2(acc[6][2],s,B1.x); fma2(acc[6][3],s,B1.y); \
      s = pack2(a1.w,a1.w); fma2(acc[7][0],s,B0.x); fma2(acc[7][1],s,B0.y); fma2(acc[7][2],s,B1.x); fma2(acc[7][3],s,B1.y); }

#define CPAB(bufidx, k0v, Abase, lda, Bbase, ldb) do { \
    int _k0 = (k0v); \
    _Pragma("unroll") \
    for (int _p = 0; _p < 2; _p++){ \
        int _f = tid + 256*_p; int _kk = _f >> 5; int _cc = (_f & 31) * 4; \
        cp16(sm32(&As[bufidx][_kk][_cc]), (Abase) + (size_t)(_k0+_kk)*(lda) + _cc); \
        cp16(sm32(&Bs[bufidx][_kk][_cc]), (Bbase) + (size_t)(_k0+_kk)*(ldb) + _cc); \
    } \
    cp_commit(); \
} while(0)

#define GEMM_CP(NC, Abase, lda, Bbase, ldb) \
    CPAB(0, 0, Abase, lda, Bbase, ldb); \
    cp_wait0(); \
    __syncthreads(); \
    _Pragma("unroll 1") \
    for (int c = 0; c < (NC); c++){ \
        int buf = c & 1; \
        if (c + 1 < (NC)) CPAB(buf^1, (c+1)*KT, Abase, lda, Bbase, ldb); \
        _Pragma("unroll") \
        for (int k = 0; k < KT; k++){ \
            float4 a0 = *(const float4*)&As[buf][k][ty*4]; \
            float4 a1 = *(const float4*)&As[buf][k][64 + ty*4]; \
            ulonglong2 B0 = *(const ulonglong2*)&Bs[buf][k][4*tx]; \
            ulonglong2 B1 = *(const ulonglong2*)&Bs[buf][k][64+4*tx]; \
            FMA_BLOCK \
        } \
        if (c + 1 < (NC)){ cp_wait0(); __syncthreads(); } \
    }

// ---------------- transpose + bf16 split of E ----------------
__global__ void k_T(const float* __restrict__ E){
    __shared__ float t[32][33];
    int b  = blockIdx.z;
    int i0 = blockIdx.x * 32;
    int d0 = blockIdx.y * 32;
    int tx = threadIdx.x, ty = threadIdx.y;   // (32, 8)
    const float* Eb = E + (size_t)b*NN*DD;
    __nv_bfloat16* Ehb = g_Ehi + (size_t)b*NN*DD;
    __nv_bfloat16* Elb = g_Elo + (size_t)b*NN*DD;
    #pragma unroll
    for (int yy = 0; yy < 32; yy += 8){
        size_t idx = (size_t)(i0+ty+yy)*DD + d0 + tx;
        float v = Eb[idx];
        t[ty+yy][tx] = v;
        __nv_bfloat16 h = __float2bfloat16(v);
        Ehb[idx] = h;
        Elb[idx] = __float2bfloat16(v - __bfloat162float(h));
    }
    __syncthreads();
    float* ETb = g_ET + (size_t)b*DD*NN;
    #pragma unroll
    for (int yy = 0; yy < 32; yy += 8)
        ETb[(size_t)(d0+ty+yy)*NN + i0 + tx] = t[tx][ty+yy];
}

// ---------------- thresh[b] = ||sum_i e_i||^2 / N^2 ----------------
__global__ void k_thresh(const float* __restrict__ E){
    int b = blockIdx.x; int t = threadIdx.x;
    const float* Eb = E + (size_t)b*NN*DD;
    float s = 0.f;
    for (int i = 0; i < NN; i++) s += Eb[(size_t)i*DD + t];
    __shared__ float red[DD];
    red[t] = s * s;
    __syncthreads();
    for (int o = 64; o > 0; o >>= 1){
        if (t < o) red[t] += red[t+o];
        __syncthreads();
    }
    if (t == 0) g_th[b] = red[0] * (1.f / ((float)NN * (float)NN));
}

// ---------------- z = E @ W  (+ fused el/er exp tables) ----------------
__global__ void __launch_bounds__(256,2) k_z(const float* __restrict__ W,
                                             const float* __restrict__ attn_l,
                                             const float* __restrict__ attn_r){
    __shared__ float As[2][KT][128];
    __shared__ float Bs[2][KT][128];
    int it = blockIdx.x, b = blockIdx.y;
    int tid = threadIdx.x, tx = tid & 15, ty = tid >> 4;
    const float* ETb = g_ET + (size_t)b*DD*NN;
    int i0 = it * 128;
    const float* Abase = ETb + i0;

    ull acc[8][4];
    #pragma unroll
    for (int r = 0; r < 8; r++)
        #pragma unroll
        for (int p = 0; p < 4; p++) acc[r][p] = 0ull;

    GEMM_CP(DD/KT, Abase, NN, W, DD)

    float al[8], ar[8];
    #pragma unroll
    for (int s = 0; s < 8; s++){
        int d = tx*4 + (s&3) + ((s>>2)<<6);
        al[s] = attn_l[d]; ar[s] = attn_r[d];
    }
    float elp[8], erp[8];
    float* zb = g_z + (size_t)b*NN*DD;
    #pragma unroll
    for (int r = 0; r < 8; r++){
        int i = i0 + ty*4 + (r&3) + ((r>>2)<<6);
        float v[8];
        #pragma unroll
        for (int p = 0; p < 4; p++){ float2 u = unpack2(acc[r][p]); v[p*2] = u.x; v[p*2+1] = u.y; }
        *(float4*)&zb[(size_t)i*DD + tx*4]      = make_float4(v[0],v[1],v[2],v[3]);
        *(float4*)&zb[(size_t)i*DD + 64 + tx*4] = make_float4(v[4],v[5],v[6],v[7]);
        float pe = 0.f, pr = 0.f;
        #pragma unroll
        for (int s = 0; s < 8; s++){ pe += v[s]*al[s]; pr += v[s]*ar[s]; }
        elp[r] = pe; erp[r] = pr;
    }
    __syncthreads();
    float* redl = &As[0][0][0];
    float* redr = redl + 2048;
    #pragma unroll
    for (int r = 0; r < 8; r++){
        int il = ty*4 + (r&3) + ((r>>2)<<6);
        redl[tx*128 + il] = elp[r];
        redr[tx*128 + il] = erp[r];
    }
    __syncthreads();
    if (tid < 128){
        float se = 0.f, sr = 0.f;
        #pragma unroll
        for (int x = 0; x < 16; x++){ se += redl[x*128 + tid]; sr += redr[x*128 + tid]; }
        int gi = b*NN + i0 + tid;
        g_eel [gi] = __expf(se);
        g_eel2[gi] = __expf(0.2f*se);
        g_eer [gi] = __expf(sr);
        g_eer2[gi] = __expf(0.2f*sr);
    }
}

// ---------------- z transpose + bf16 split: zT[d][i] ----------------
__global__ void k_zT(){
    __shared__ float t[32][33];
    int b  = blockIdx.z;
    int i0 = blockIdx.x * 32;
    int d0 = blockIdx.y * 32;
    int tx = threadIdx.x, ty = threadIdx.y;   // (32, 8)
    const float* zb = g_z + (size_t)b*NN*DD;
    #pragma unroll
    for (int yy = 0; yy < 32; yy += 8)
        t[ty+yy][tx] = zb[(size_t)(i0+ty+yy)*DD + d0 + tx];
    __syncthreads();
    __nv_bfloat16* zh = g_zThi + (size_t)b*DD*NN;
    __nv_bfloat16* zl = g_zTlo + (size_t)b*DD*NN;
    #pragma unroll
    for (int yy = 0; yy < 32; yy += 8){
        float v = t[tx][ty+yy];
        size_t idx = (size_t)(d0+ty+yy)*NN + i0 + tx;
        __nv_bfloat16 h = __float2bfloat16(v);
        zh[idx] = h;
        zl[idx] = __float2bfloat16(v - __bfloat162float(h));
    }
}

// ---------------- HMMA scores -> Pt (bf16 hi/lo) + colsum partials ----------------
// 3-tile rotation: term0 = Ah*Bl, term1 = Ah*Bh, term2 = Al*Bh; one-tile swap per transition.
#define TILEB1 (128*PITCH*2)            // 34816
#define SMS_T0 0
#define SMS_T1 TILEB1
#define SMS_T2 (2*TILEB1)
#define SM_ELI  (3*TILEB1)
#define SM_ELI2 (SM_ELI + 512)
#define SM_ERJ  (SM_ELI2 + 512)
#define SM_ERJ2 (SM_ERJ + 512)
#define SM_RED  (SM_ERJ2 + 512)
#define SMEM_MMA (SM_RED + 2048)

__global__ void __launch_bounds__(256,2) k_scores_mma(){
    extern __shared__ char smem[];
    uint32_t sb = sm32(smem);
    float* sEli  = (float*)(smem + SM_ELI);
    float* sEli2 = (float*)(smem + SM_ELI2);
    float* sErj  = (float*)(smem + SM_ERJ);
    float* sErj2 = (float*)(smem + SM_ERJ2);
    float* red   = (float*)(smem + SM_RED);

    int tid = threadIdx.x;
    int wid = tid >> 5, lane = tid & 31;
    int warp_m = wid >> 2, warp_n = wid & 3;     // 2 x 4 warps
    int g = lane >> 2, t = lane & 3;
    int it = blockIdx.x & 3, jt = blockIdx.x >> 2;
    int b = blockIdx.y;
    int i0 = it * 128, j0 = jt * 128;

    if (tid < 128){
        sEli [tid] = g_eel [b*NN + i0 + tid];
        sEli2[tid] = g_eel2[b*NN + i0 + tid];
        sErj [tid] = g_eer [b*NN + j0 + tid];
        sErj2[tid] = g_eer2[b*NN + j0 + tid];
    }

    // fragment byte offsets within a tile
    uint32_t aoff[4], boff[4];
    #pragma unroll
    for (int mt = 0; mt < 4; mt++)
        aoff[mt] = ((warp_m*64 + mt*16 + (lane & 15))*PITCH + (lane >> 4)*8)*2;
    #pragma unroll
    for (int nt = 0; nt < 4; nt++)
        boff[nt] = ((warp_n*32 + nt*8 + (lane & 7))*PITCH + ((lane >> 3) & 1)*8)*2;

    float d[4][4][4];
    #pragma unroll
    for (int mt = 0; mt < 4; mt++)
        #pragma unroll
        for (int nt = 0; nt < 4; nt++)
            #pragma unroll
            for (int c = 0; c < 4; c++) d[mt][nt][c] = 0.f;

    const __nv_bfloat16* Eh = g_Ehi + (size_t)b*NN*DD;
    const __nv_bfloat16* El = g_Elo + (size_t)b*NN*DD;

    #define LDTILE(dstoff, Src) do { \
        _Pragma("unroll") \
        for (int _p = 0; _p < 8; _p++){ \
            int _cid = tid + 256*_p; \
            int _row = _cid >> 4, _kc = _cid & 15; \
            cp16(sb + (dstoff) + (_row*PITCH + _kc*8)*2, (Src) + (size_t)_row*DD + _kc*8); \
        } \
    } while(0)

    #define TERM(at, bt) do { \
        _Pragma("unroll 1") \
        for (int ks = 0; ks < 8; ks++){ \
            uint32_t af[4][4], bf[4][2]; \
            _Pragma("unroll") \
            for (int mt = 0; mt < 4; mt++) ldmA(af[mt], sb + (at) + aoff[mt] + ks*32); \
            _Pragma("unroll") \
            for (int nt = 0; nt < 4; nt++) ldmB(bf[nt], sb + (bt) + boff[nt] + ks*32); \
            _Pragma("unroll") \
            for (int mt = 0; mt < 4; mt++) \
                _Pragma("unroll") \
                for (int nt = 0; nt < 4; nt++) \
                    mma16816(d[mt][nt], af[mt], bf[nt]); \
        } \
    } while(0)

    // G0: T0=Eh_j, T1=El_i    G1: T2=Eh_i    (later G2: T1=El_j)
    LDTILE(SMS_T0, Eh + (size_t)j0*DD);
    LDTILE(SMS_T1, El + (size_t)i0*DD);
    cp_commit();
    LDTILE(SMS_T2, Eh + (size_t)i0*DD);
    cp_commit();

    cp_wait1();          // G0 done (T0, T1)
    __syncthreads();
    TERM(SMS_T0, SMS_T1);            // Eh_j * El_i
    __syncthreads();                 // all warps done reading T1
    LDTILE(SMS_T1, El + (size_t)j0*DD);
    cp_commit();                     // G2
    cp_wait1();          // G1 done (T2)
    __syncthreads();
    TERM(SMS_T0, SMS_T2);            // Eh_j * Eh_i
    cp_wait0();          // G2 done (T1 = El_j)
    __syncthreads();
    TERM(SMS_T1, SMS_T2);            // El_j * Eh_i

    // epilogue: Pt[j][i] bf16 hi/lo + colsum
    float th = g_th[b];
    __nv_bfloat16* Ph = g_Pthi + (size_t)b*NN*NN;
    __nv_bfloat16* Pl = g_Ptlo + (size_t)b*NN*NN;
    float cs_p[8];
    #pragma unroll
    for (int mt = 0; mt < 4; mt++){
        #pragma unroll
        for (int half = 0; half < 2; half++){
            int jloc = warp_m*64 + mt*16 + g + 8*half;
            int jg = j0 + jloc;
            float Er = sErj[jloc], Er2 = sErj2[jloc];
            float csl = 0.f;
            #pragma unroll
            for (int nt = 0; nt < 4; nt++){
                float pv[2];
                #pragma unroll
                for (int par = 0; par < 2; par++){
                    int iloc = warp_n*32 + nt*8 + 2*t + par;
                    int ig = i0 + iloc;
                    float sv = d[mt][nt][half*2 + par];
                    float p = 0.f;
                    if (sv > th || ig == jg){
                        float q = sEli[iloc] * Er;
                        p = (q > 1.f) ? q : sEli2[iloc] * Er2;
                    }
                    csl += p; pv[par] = p;
                }
                __nv_bfloat16 h0 = __float2bfloat16(pv[0]);
                __nv_bfloat16 h1 = __float2bfloat16(pv[1]);
                __nv_bfloat16 l0 = __float2bfloat16(pv[0] - __bfloat162float(h0));
                __nv_bfloat16 l1 = __float2bfloat16(pv[1] - __bfloat162float(h1));
                size_t addr = (size_t)jg*NN + i0 + warp_n*32 + nt*8 + 2*t;
                *(__nv_bfloat162*)&Ph[addr] = __halves2bfloat162(h0, h1);
                *(__nv_bfloat162*)&Pl[addr] = __halves2bfloat162(l0, l1);
            }
            cs_p[mt*2 + half] = csl;
        }
    }
    #pragma unroll
    for (int h = 0; h < 8; h++){
        cs_p[h] += __shfl_xor_sync(0xFFFFFFFFu, cs_p[h], 1);
        cs_p[h] += __shfl_xor_sync(0xFFFFFFFFu, cs_p[h], 2);
    }
    __syncthreads();
    if (t == 0){
        #pragma unroll
        for (int h = 0; h < 8; h++){
            int mt = h >> 1, half = h & 1;
            int jloc = warp_m*64 + mt*16 + g + 8*half;
            red[jloc*4 + warp_n] = cs_p[h];
        }
    }
    __syncthreads();
    if (tid < 128){
        float tcs = red[tid*4] + red[tid*4+1] + red[tid*4+2] + red[tid*4+3];
        g_cs[(b*4 + it)*NN + j0 + tid] = tcs;
    }
    #undef LDTILE
    #undef TERM
}

// ---------------- HMMA PV (double-buffered): h[j][d] = sum_i Pt[j][i] z[i][d] ----------------
#define TILE2B (128*PITCH2*2)           // 10240
#define STAGEB (4*TILE2B)               // 40960
#define SMP_CS (2*STAGEB)               // 81920
#define SMP_RED (SMP_CS + 512)
#define SMEM_PV (SMP_RED + 1024)

__global__ void __launch_bounds__(256,2) k_pv_mma(const float* __restrict__ bias){
    extern __shared__ char smem[];
    uint32_t sb = sm32(smem);
    float* sCs = (float*)(smem + SMP_CS);
    float* red = (float*)(smem + SMP_RED);
    int tid = threadIdx.x, wid = tid >> 5, lane = tid & 31;
    int warp_m = wid >> 2, warp_n = wid & 3;
    int g = lane >> 2, t = lane & 3;
    int jt = blockIdx.x, b = blockIdx.y;
    int j0 = jt * 128;

    if (tid < 128){
        int j = j0 + tid;
        sCs[tid] = g_cs[(b*4+0)*NN + j] + g_cs[(b*4+1)*NN + j]
                 + g_cs[(b*4+2)*NN + j] + g_cs[(b*4+3)*NN + j];
    }
    float bi[8];
    #pragma unroll
    for (int nt = 0; nt < 4; nt++)
        #pragma unroll
        for (int par = 0; par < 2; par++)
            bi[nt*2+par] = bias[warp_n*32 + nt*8 + 2*t + par];

    const __nv_bfloat16* srcs[4];
    srcs[0] = g_Pthi + (size_t)b*NN*NN + (size_t)j0*NN;
    srcs[1] = g_Ptlo + (size_t)b*NN*NN + (size_t)j0*NN;
    srcs[2] = g_zThi + (size_t)b*DD*NN;
    srcs[3] = g_zTlo + (size_t)b*DD*NN;

    // per-stage fragment byte offsets
    uint32_t aPh[4], aPl[4], bZh[4], bZl[4];
    #pragma unroll
    for (int mt = 0; mt < 4; mt++){
        int row = warp_m*64 + mt*16 + (lane & 15);
        int c8  = (lane >> 4)*8;
        aPh[mt] = 0*TILE2B + (row*PITCH2 + c8)*2;
        aPl[mt] = 1*TILE2B + (row*PITCH2 + c8)*2;
    }
    #pragma unroll
    for (int nt = 0; nt < 4; nt++){
        int row = warp_n*32 + nt*8 + (lane & 7);
        int c8  = ((lane >> 3) & 1)*8;
        bZh[nt] = 2*TILE2B + (row*PITCH2 + c8)*2;
        bZl[nt] = 3*TILE2B + (row*PITCH2 + c8)*2;
    }

    float d[4][4][4];
    #pragma unroll
    for (int mt = 0; mt < 4; mt++)
        #pragma unroll
        for (int nt = 0; nt < 4; nt++)
            #pragma unroll
            for (int c = 0; c < 4; c++) d[mt][nt][c] = 0.f;

    #define ISSUE(cc, st) do { \
        _Pragma("unroll") \
        for (int _p = 0; _p < 8; _p++){ \
            int _arr = _p >> 1; \
            int _slot = tid + 256*(_p & 1); \
            int _row = _slot >> 2, _seg = _slot & 3; \
            cp16(sb + (st)*STAGEB + _arr*TILE2B + (_row*PITCH2 + _seg*8)*2, \
                 srcs[_arr] + (size_t)_row*NN + (cc)*32 + _seg*8); \
        } \
        cp_commit(); \
    } while(0)

    ISSUE(0, 0);
    #pragma unroll 1
    for (int c = 0; c < 16; c++){
        int st = c & 1;
        if (c + 1 < 16) ISSUE(c+1, st^1);
        if (c + 1 < 16) cp_wait1(); else cp_wait0();
        __syncthreads();
        uint32_t base = sb + st*STAGEB;
        #pragma unroll
        for (int ks = 0; ks < 2; ks++){
            uint32_t bh[4][2], bl[4][2];
            #pragma unroll
            for (int nt = 0; nt < 4; nt++){
                ldmB(bh[nt], base + bZh[nt] + ks*32);
                ldmB(bl[nt], base + bZl[nt] + ks*32);
            }
            #pragma unroll
            for (int mt = 0; mt < 4; mt++){
                uint32_t ah[4], al[4];
                ldmA(ah, base + aPh[mt] + ks*32);
                ldmA(al, base + aPl[mt] + ks*32);
                #pragma unroll
                for (int nt = 0; nt < 4; nt++){
                    mma16816(d[mt][nt], ah, bh[nt]);
                    mma16816(d[mt][nt], ah, bl[nt]);
                    mma16816(d[mt][nt], al, bh[nt]);
                }
            }
        }
        __syncthreads();
    }
    #undef ISSUE

    // epilogue: /cs, +bias, elu, pool over j
    float pd[8];
    #pragma unroll
    for (int q = 0; q < 8; q++) pd[q] = 0.f;
    #pragma unroll
    for (int mt = 0; mt < 4; mt++){
        #pragma unroll
        for (int half = 0; half < 2; half++){
            int jloc = warp_m*64 + mt*16 + g + 8*half;
            float inv = 1.f / sCs[jloc];
            #pragma unroll
            for (int nt = 0; nt < 4; nt++)
                #pragma unroll
                for (int par = 0; par < 2; par++){
                    float v = d[mt][nt][half*2+par]*inv + bi[nt*2+par];
                    v = v > 0.f ? v : expm1f(v);
                    pd[nt*2+par] += v;
                }
        }
    }
    #pragma unroll
    for (int q = 0; q < 8; q++){
        pd[q] += __shfl_xor_sync(0xFFFFFFFFu, pd[q], 4);
        pd[q] += __shfl_xor_sync(0xFFFFFFFFu, pd[q], 8);
        pd[q] += __shfl_xor_sync(0xFFFFFFFFu, pd[q], 16);
    }
    __syncthreads();
    if (g == 0){
        #pragma unroll
        for (int nt = 0; nt < 4; nt++)
            #pragma unroll
            for (int par = 0; par < 2; par++)
                red[warp_m*128 + warp_n*32 + nt*8 + 2*t + par] = pd[nt*2+par];
    }
    __syncthreads();
    if (tid < 128)
        g_pool[(b*4 + jt)*DD + tid] = red[tid] + red[128 + tid];
}

// ---------------- final: mean over nodes ----------------
__global__ void k_out(float* __restrict__ out){
    int b = blockIdx.x, d = threadIdx.x;
    float s = g_pool[(b*4+0)*DD + d] + g_pool[(b*4+1)*DD + d]
            + g_pool[(b*4+2)*DD + d] + g_pool[(b*4+3)*DD + d];
    out[b*DD + d] = s * (1.f / (float)NN);
}

extern "C" void kernel_launch(void* const* d_in, const int* in_sizes, int n_in,
                              void* d_out, int out_size){
    const float* E    = (const float*)d_in[0];
    const float* W    = (const float*)d_in[1];
    const float* al   = (const float*)d_in[2];
    const float* ar   = (const float*)d_in[3];
    const float* bias = (const float*)d_in[4];
    float* out = (float*)d_out;

    cudaFuncSetAttribute(k_scores_mma, cudaFuncAttributeMaxDynamicSharedMemorySize, SMEM_MMA);
    cudaFuncSetAttribute(k_pv_mma,     cudaFuncAttributeMaxDynamicSharedMemorySize, SMEM_PV);

    k_T         <<<dim3(16,4,64), dim3(32,8)>>>(E);
    k_thresh    <<<64, 128>>>(E);
    k_z         <<<dim3(4,64),  256>>>(W, al, ar);
    k_zT        <<<dim3(16,4,64), dim3(32,8)>>>();
    k_scores_mma<<<dim3(16,64), 256, SMEM_MMA>>>();
    k_pv_mma    <<<dim3(4,64),  256, SMEM_PV>>>(bias);
    k_out       <<<64, 128>>>(out);
}

// round 10
// speedup vs baseline: 1.6448x; 1.1337x over previous
#include <cuda_runtime.h>
#include <cuda_bf16.h>
#include <math.h>
#include <stdint.h>

#define BB 64
#define NN 512
#define DD 128
#define KT 16
#define PITCH 136   // bf16 elems per smem row (272B): conflict-free ldmatrix
#define PITCH2 40   // bf16 elems per smem row for 32-wide k-chunks (80B)

typedef unsigned long long ull;

__device__ __forceinline__ ull pack2(float lo, float hi){
    ull r; asm("mov.b64 %0, {%1, %2};" : "=l"(r) : "f"(lo), "f"(hi)); return r;
}
__device__ __forceinline__ float2 unpack2(ull v){
    float2 f; asm("mov.b64 {%0, %1}, %2;" : "=f"(f.x), "=f"(f.y) : "l"(v)); return f;
}
__device__ __forceinline__ void fma2(ull &d, ull a, ull b){
    asm("fma.rn.f32x2 %0, %1, %2, %0;" : "+l"(d) : "l"(a), "l"(b));
}
__device__ __forceinline__ unsigned sm32(const void* p){
    return (unsigned)__cvta_generic_to_shared(p);
}
__device__ __forceinline__ void cp16(unsigned dst, const void* src){
    asm volatile("cp.async.cg.shared.global [%0], [%1], 16;" :: "r"(dst), "l"(src));
}
__device__ __forceinline__ void cp_commit(){ asm volatile("cp.async.commit_group;"); }
__device__ __forceinline__ void cp_wait0(){ asm volatile("cp.async.wait_group 0;" ::: "memory"); }
__device__ __forceinline__ void cp_wait1(){ asm volatile("cp.async.wait_group 1;" ::: "memory"); }

// ---- warp-level MMA primitives (standard PTX, compute_103-safe) ----
__device__ __forceinline__ void ldmA(uint32_t* a, uint32_t addr){
    asm volatile("ldmatrix.sync.aligned.m8n8.x4.shared.b16 {%0,%1,%2,%3}, [%4];"
        : "=r"(a[0]), "=r"(a[1]), "=r"(a[2]), "=r"(a[3]) : "r"(addr));
}
__device__ __forceinline__ void ldmB(uint32_t* b, uint32_t addr){
    asm volatile("ldmatrix.sync.aligned.m8n8.x2.shared.b16 {%0,%1}, [%2];"
        : "=r"(b[0]), "=r"(b[1]) : "r"(addr));
}
__device__ __forceinline__ void mma16816(float* d, const uint32_t* a, const uint32_t* b){
    asm volatile("mma.sync.aligned.m16n8k16.row.col.f32.bf16.bf16.f32 "
        "{%0,%1,%2,%3}, {%4,%5,%6,%7}, {%8,%9}, {%0,%1,%2,%3};"
        : "+f"(d[0]), "+f"(d[1]), "+f"(d[2]), "+f"(d[3])
        : "r"(a[0]), "r"(a[1]), "r"(a[2]), "r"(a[3]), "r"(b[0]), "r"(b[1]));
}

// Scratch (static device globals; no allocation)
__device__ float g_ET[BB*DD*NN];            // E^T per batch: [b][d][i]
__device__ float g_z [BB*NN*DD];            // z = E @ W
__device__ __nv_bfloat16 g_Ehi[(size_t)BB*NN*DD];
__device__ __nv_bfloat16 g_Elo[(size_t)BB*NN*DD];
__device__ __nv_bfloat16 g_Pthi[(size_t)BB*NN*NN];  // P^T hi: [b][j][i] (bf16, hi only)
__device__ __nv_bfloat16 g_zThi[(size_t)BB*DD*NN];  // z^T hi: [b][d][i]
__device__ __nv_bfloat16 g_zTlo[(size_t)BB*DD*NN];
__device__ float g_eel [BB*NN];
__device__ float g_eel2[BB*NN];
__device__ float g_eer [BB*NN];
__device__ float g_eer2[BB*NN];
__device__ float g_th[BB];
__device__ float g_cs[BB*4*NN];
__device__ float g_pool[BB*4*DD];

// ---- R4 FFMA2 GEMM core (k_z only) ----
#define FMA_BLOCK \
    { ull s; \
      s = pack2(a0.x,a0.x); fma2(acc[0][0],s,B0.x); fma2(acc[0][1],s,B0.y); fma2(acc[0][2],s,B1.x); fma2(acc[0][3],s,B1.y); \
      s = pack2(a0.y,a0.y); fma2(acc[1][0],s,B0.x); fma2(acc[1][1],s,B0.y); fma2(acc[1][2],s,B1.x); fma2(acc[1][3],s,B1.y); \
      s = pack2(a0.z,a0.z); fma2(acc[2][0],s,B0.x); fma2(acc[2][1],s,B0.y); fma2(acc[2][2],s,B1.x); fma2(acc[2][3],s,B1.y); \
      s = pack2(a0.w,a0.w); fma2(acc[3][0],s,B0.x); fma2(acc[3][1],s,B0.y); fma2(acc[3][2],s,B1.x); fma2(acc[3][3],s,B1.y); \
      s = pack2(a1.x,a1.x); fma2(acc[4][0],s,B0.x); fma2(acc[4][1],s,B0.y); fma2(acc[4][2],s,B1.x); fma2(acc[4][3],s,B1.y); \
      s = pack2(a1.y,a1.y); fma2(acc[5][0],s,B0.x); fma2(acc[5][1],s,B0.y); fma2(acc[5][2],s,B1.x); fma2(acc[5][3],s,B1.y); \
      s = pack2(a1.z,a1.z); fma2(acc[6][0],s,B0.x); fma2(acc[6][1],s,B0.y); fma2(acc[6][2],s,B1.x); fma2(acc[6][3],s,B1.y); \
      s = pack2(a1.w,a1.w); fma2(acc[7][0],s,B0.x); fma2(acc[7][1],s,B0.y); fma2(acc[7][2],s,B1.x); fma2(acc[7][3],s,B1.y); }

#define CPAB(bufidx, k0v, Abase, lda, Bbase, ldb) do { \
    int _k0 = (k0v); \
    _Pragma("unroll") \
    for (int _p = 0; _p < 2; _p++){ \
        int _f = tid + 256*_p; int _kk = _f >> 5; int _cc = (_f & 31) * 4; \
        cp16(sm32(&As[bufidx][_kk][_cc]), (Abase) + (size_t)(_k0+_kk)*(lda) + _cc); \
        cp16(sm32(&Bs[bufidx][_kk][_cc]), (Bbase) + (size_t)(_k0+_kk)*(ldb) + _cc); \
    } \
    cp_commit(); \
} while(0)

#define GEMM_CP(NC, Abase, lda, Bbase, ldb) \
    CPAB(0, 0, Abase, lda, Bbase, ldb); \
    cp_wait0(); \
    __syncthreads(); \
    _Pragma("unroll 1") \
    for (int c = 0; c < (NC); c++){ \
        int buf = c & 1; \
        if (c + 1 < (NC)) CPAB(buf^1, (c+1)*KT, Abase, lda, Bbase, ldb); \
        _Pragma("unroll") \
        for (int k = 0; k < KT; k++){ \
            float4 a0 = *(const float4*)&As[buf][k][ty*4]; \
            float4 a1 = *(const float4*)&As[buf][k][64 + ty*4]; \
            ulonglong2 B0 = *(const ulonglong2*)&Bs[buf][k][4*tx]; \
            ulonglong2 B1 = *(const ulonglong2*)&Bs[buf][k][64+4*tx]; \
            FMA_BLOCK \
        } \
        if (c + 1 < (NC)){ cp_wait0(); __syncthreads(); } \
    }

// ---------------- transpose + bf16 split of E ----------------
__global__ void k_T(const float* __restrict__ E){
    __shared__ float t[32][33];
    int b  = blockIdx.z;
    int i0 = blockIdx.x * 32;
    int d0 = blockIdx.y * 32;
    int tx = threadIdx.x, ty = threadIdx.y;   // (32, 8)
    const float* Eb = E + (size_t)b*NN*DD;
    __nv_bfloat16* Ehb = g_Ehi + (size_t)b*NN*DD;
    __nv_bfloat16* Elb = g_Elo + (size_t)b*NN*DD;
    #pragma unroll
    for (int yy = 0; yy < 32; yy += 8){
        size_t idx = (size_t)(i0+ty+yy)*DD + d0 + tx;
        float v = Eb[idx];
        t[ty+yy][tx] = v;
        __nv_bfloat16 h = __float2bfloat16(v);
        Ehb[idx] = h;
        Elb[idx] = __float2bfloat16(v - __bfloat162float(h));
    }
    __syncthreads();
    float* ETb = g_ET + (size_t)b*DD*NN;
    #pragma unroll
    for (int yy = 0; yy < 32; yy += 8)
        ETb[(size_t)(d0+ty+yy)*NN + i0 + tx] = t[tx][ty+yy];
}

// ---------------- thresh[b] = ||sum_i e_i||^2 / N^2 ----------------
__global__ void k_thresh(const float* __restrict__ E){
    int b = blockIdx.x; int t = threadIdx.x;
    const float* Eb = E + (size_t)b*NN*DD;
    float s = 0.f;
    for (int i = 0; i < NN; i++) s += Eb[(size_t)i*DD + t];
    __shared__ float red[DD];
    red[t] = s * s;
    __syncthreads();
    for (int o = 64; o > 0; o >>= 1){
        if (t < o) red[t] += red[t+o];
        __syncthreads();
    }
    if (t == 0) g_th[b] = red[0] * (1.f / ((float)NN * (float)NN));
}

// ---------------- z = E @ W  (+ fused el/er exp tables) ----------------
__global__ void __launch_bounds__(256,2) k_z(const float* __restrict__ W,
                                             const float* __restrict__ attn_l,
                                             const float* __restrict__ attn_r){
    __shared__ float As[2][KT][128];
    __shared__ float Bs[2][KT][128];
    int it = blockIdx.x, b = blockIdx.y;
    int tid = threadIdx.x, tx = tid & 15, ty = tid >> 4;
    const float* ETb = g_ET + (size_t)b*DD*NN;
    int i0 = it * 128;
    const float* Abase = ETb + i0;

    ull acc[8][4];
    #pragma unroll
    for (int r = 0; r < 8; r++)
        #pragma unroll
        for (int p = 0; p < 4; p++) acc[r][p] = 0ull;

    GEMM_CP(DD/KT, Abase, NN, W, DD)

    float al[8], ar[8];
    #pragma unroll
    for (int s = 0; s < 8; s++){
        int d = tx*4 + (s&3) + ((s>>2)<<6);
        al[s] = attn_l[d]; ar[s] = attn_r[d];
    }
    float elp[8], erp[8];
    float* zb = g_z + (size_t)b*NN*DD;
    #pragma unroll
    for (int r = 0; r < 8; r++){
        int i = i0 + ty*4 + (r&3) + ((r>>2)<<6);
        float v[8];
        #pragma unroll
        for (int p = 0; p < 4; p++){ float2 u = unpack2(acc[r][p]); v[p*2] = u.x; v[p*2+1] = u.y; }
        *(float4*)&zb[(size_t)i*DD + tx*4]      = make_float4(v[0],v[1],v[2],v[3]);
        *(float4*)&zb[(size_t)i*DD + 64 + tx*4] = make_float4(v[4],v[5],v[6],v[7]);
        float pe = 0.f, pr = 0.f;
        #pragma unroll
        for (int s = 0; s < 8; s++){ pe += v[s]*al[s]; pr += v[s]*ar[s]; }
        elp[r] = pe; erp[r] = pr;
    }
    __syncthreads();
    float* redl = &As[0][0][0];
    float* redr = redl + 2048;
    #pragma unroll
    for (int r = 0; r < 8; r++){
        int il = ty*4 + (r&3) + ((r>>2)<<6);
        redl[tx*128 + il] = elp[r];
        redr[tx*128 + il] = erp[r];
    }
    __syncthreads();
    if (tid < 128){
        float se = 0.f, sr = 0.f;
        #pragma unroll
        for (int x = 0; x < 16; x++){ se += redl[x*128 + tid]; sr += redr[x*128 + tid]; }
        int gi = b*NN + i0 + tid;
        g_eel [gi] = __expf(se);
        g_eel2[gi] = __expf(0.2f*se);
        g_eer [gi] = __expf(sr);
        g_eer2[gi] = __expf(0.2f*sr);
    }
}

// ---------------- z transpose + bf16 split: zT[d][i] ----------------
__global__ void k_zT(){
    __shared__ float t[32][33];
    int b  = blockIdx.z;
    int i0 = blockIdx.x * 32;
    int d0 = blockIdx.y * 32;
    int tx = threadIdx.x, ty = threadIdx.y;   // (32, 8)
    const float* zb = g_z + (size_t)b*NN*DD;
    #pragma unroll
    for (int yy = 0; yy < 32; yy += 8)
        t[ty+yy][tx] = zb[(size_t)(i0+ty+yy)*DD + d0 + tx];
    __syncthreads();
    __nv_bfloat16* zh = g_zThi + (size_t)b*DD*NN;
    __nv_bfloat16* zl = g_zTlo + (size_t)b*DD*NN;
    #pragma unroll
    for (int yy = 0; yy < 32; yy += 8){
        float v = t[tx][ty+yy];
        size_t idx = (size_t)(d0+ty+yy)*NN + i0 + tx;
        __nv_bfloat16 h = __float2bfloat16(v);
        zh[idx] = h;
        zl[idx] = __float2bfloat16(v - __bfloat162float(h));
    }
}

// ---------------- HMMA scores -> Pt (bf16 hi only) + colsum partials ----------------
// 3-tile rotation: term0 = Ah*Bl, term1 = Ah*Bh, term2 = Al*Bh; one-tile swap per transition.
#define TILEB1 (128*PITCH*2)            // 34816
#define SMS_T0 0
#define SMS_T1 TILEB1
#define SMS_T2 (2*TILEB1)
#define SM_ELI  (3*TILEB1)
#define SM_ELI2 (SM_ELI + 512)
#define SM_ERJ  (SM_ELI2 + 512)
#define SM_ERJ2 (SM_ERJ + 512)
#define SM_RED  (SM_ERJ2 + 512)
#define SMEM_MMA (SM_RED + 2048)

__global__ void __launch_bounds__(256,2) k_scores_mma(){
    extern __shared__ char smem[];
    uint32_t sb = sm32(smem);
    float* sEli  = (float*)(smem + SM_ELI);
    float* sEli2 = (float*)(smem + SM_ELI2);
    float* sErj  = (float*)(smem + SM_ERJ);
    float* sErj2 = (float*)(smem + SM_ERJ2);
    float* red   = (float*)(smem + SM_RED);

    int tid = threadIdx.x;
    int wid = tid >> 5, lane = tid & 31;
    int warp_m = wid >> 2, warp_n = wid & 3;     // 2 x 4 warps
    int g = lane >> 2, t = lane & 3;
    int it = blockIdx.x & 3, jt = blockIdx.x >> 2;
    int b = blockIdx.y;
    int i0 = it * 128, j0 = jt * 128;

    if (tid < 128){
        sEli [tid] = g_eel [b*NN + i0 + tid];
        sEli2[tid] = g_eel2[b*NN + i0 + tid];
        sErj [tid] = g_eer [b*NN + j0 + tid];
        sErj2[tid] = g_eer2[b*NN + j0 + tid];
    }

    uint32_t aoff[4], boff[4];
    #pragma unroll
    for (int mt = 0; mt < 4; mt++)
        aoff[mt] = ((warp_m*64 + mt*16 + (lane & 15))*PITCH + (lane >> 4)*8)*2;
    #pragma unroll
    for (int nt = 0; nt < 4; nt++)
        boff[nt] = ((warp_n*32 + nt*8 + (lane & 7))*PITCH + ((lane >> 3) & 1)*8)*2;

    float d[4][4][4];
    #pragma unroll
    for (int mt = 0; mt < 4; mt++)
        #pragma unroll
        for (int nt = 0; nt < 4; nt++)
            #pragma unroll
            for (int c = 0; c < 4; c++) d[mt][nt][c] = 0.f;

    const __nv_bfloat16* Eh = g_Ehi + (size_t)b*NN*DD;
    const __nv_bfloat16* El = g_Elo + (size_t)b*NN*DD;

    #define LDTILE(dstoff, Src) do { \
        _Pragma("unroll") \
        for (int _p = 0; _p < 8; _p++){ \
            int _cid = tid + 256*_p; \
            int _row = _cid >> 4, _kc = _cid & 15; \
            cp16(sb + (dstoff) + (_row*PITCH + _kc*8)*2, (Src) + (size_t)_row*DD + _kc*8); \
        } \
    } while(0)

    #define TERM(at, bt) do { \
        _Pragma("unroll 1") \
        for (int ks = 0; ks < 8; ks++){ \
            uint32_t af[4][4], bf[4][2]; \
            _Pragma("unroll") \
            for (int mt = 0; mt < 4; mt++) ldmA(af[mt], sb + (at) + aoff[mt] + ks*32); \
            _Pragma("unroll") \
            for (int nt = 0; nt < 4; nt++) ldmB(bf[nt], sb + (bt) + boff[nt] + ks*32); \
            _Pragma("unroll") \
            for (int mt = 0; mt < 4; mt++) \
                _Pragma("unroll") \
                for (int nt = 0; nt < 4; nt++) \
                    mma16816(d[mt][nt], af[mt], bf[nt]); \
        } \
    } while(0)

    // G0: T0=Eh_j, T1=El_i    G1: T2=Eh_i    (later G2: T1=El_j)
    LDTILE(SMS_T0, Eh + (size_t)j0*DD);
    LDTILE(SMS_T1, El + (size_t)i0*DD);
    cp_commit();
    LDTILE(SMS_T2, Eh + (size_t)i0*DD);
    cp_commit();

    cp_wait1();
    __syncthreads();
    TERM(SMS_T0, SMS_T1);            // Eh_j * El_i
    __syncthreads();
    LDTILE(SMS_T1, El + (size_t)j0*DD);
    cp_commit();
    cp_wait1();
    __syncthreads();
    TERM(SMS_T0, SMS_T2);            // Eh_j * Eh_i
    cp_wait0();
    __syncthreads();
    TERM(SMS_T1, SMS_T2);            // El_j * Eh_i

    // epilogue: Pt[j][i] bf16 hi only + colsum
    float th = g_th[b];
    __nv_bfloat16* Ph = g_Pthi + (size_t)b*NN*NN;
    float cs_p[8];
    #pragma unroll
    for (int mt = 0; mt < 4; mt++){
        #pragma unroll
        for (int half = 0; half < 2; half++){
            int jloc = warp_m*64 + mt*16 + g + 8*half;
            int jg = j0 + jloc;
            float Er = sErj[jloc], Er2 = sErj2[jloc];
            float csl = 0.f;
            #pragma unroll
            for (int nt = 0; nt < 4; nt++){
                float pv[2];
                #pragma unroll
                for (int par = 0; par < 2; par++){
                    int iloc = warp_n*32 + nt*8 + 2*t + par;
                    int ig = i0 + iloc;
                    float sv = d[mt][nt][half*2 + par];
                    float p = 0.f;
                    if (sv > th || ig == jg){
                        float q = sEli[iloc] * Er;
                        p = (q > 1.f) ? q : sEli2[iloc] * Er2;
                    }
                    csl += p; pv[par] = p;
                }
                __nv_bfloat16 h0 = __float2bfloat16(pv[0]);
                __nv_bfloat16 h1 = __float2bfloat16(pv[1]);
                size_t addr = (size_t)jg*NN + i0 + warp_n*32 + nt*8 + 2*t;
                *(__nv_bfloat162*)&Ph[addr] = __halves2bfloat162(h0, h1);
            }
            cs_p[mt*2 + half] = csl;
        }
    }
    #pragma unroll
    for (int h = 0; h < 8; h++){
        cs_p[h] += __shfl_xor_sync(0xFFFFFFFFu, cs_p[h], 1);
        cs_p[h] += __shfl_xor_sync(0xFFFFFFFFu, cs_p[h], 2);
    }
    __syncthreads();
    if (t == 0){
        #pragma unroll
        for (int h = 0; h < 8; h++){
            int mt = h >> 1, half = h & 1;
            int jloc = warp_m*64 + mt*16 + g + 8*half;
            red[jloc*4 + warp_n] = cs_p[h];
        }
    }
    __syncthreads();
    if (tid < 128){
        float tcs = red[tid*4] + red[tid*4+1] + red[tid*4+2] + red[tid*4+3];
        g_cs[(b*4 + it)*NN + j0 + tid] = tcs;
    }
    #undef LDTILE
    #undef TERM
}

// ---------------- HMMA PV (double-buffered, P hi only): h[j][d] = sum_i Pt[j][i] z[i][d] ----------------
#define TILE2B (128*PITCH2*2)           // 10240
#define STAGEB (3*TILE2B)               // 30720
#define SMP_CS (2*STAGEB)               // 61440
#define SMP_RED (SMP_CS + 512)
#define SMEM_PV (SMP_RED + 1024)

__global__ void __launch_bounds__(256,2) k_pv_mma(const float* __restrict__ bias){
    extern __shared__ char smem[];
    uint32_t sb = sm32(smem);
    float* sCs = (float*)(smem + SMP_CS);
    float* red = (float*)(smem + SMP_RED);
    int tid = threadIdx.x, wid = tid >> 5, lane = tid & 31;
    int warp_m = wid >> 2, warp_n = wid & 3;
    int g = lane >> 2, t = lane & 3;
    int jt = blockIdx.x, b = blockIdx.y;
    int j0 = jt * 128;

    if (tid < 128){
        int j = j0 + tid;
        sCs[tid] = g_cs[(b*4+0)*NN + j] + g_cs[(b*4+1)*NN + j]
                 + g_cs[(b*4+2)*NN + j] + g_cs[(b*4+3)*NN + j];
    }
    float bi[8];
    #pragma unroll
    for (int nt = 0; nt < 4; nt++)
        #pragma unroll
        for (int par = 0; par < 2; par++)
            bi[nt*2+par] = bias[warp_n*32 + nt*8 + 2*t + par];

    const __nv_bfloat16* srcs[3];
    srcs[0] = g_Pthi + (size_t)b*NN*NN + (size_t)j0*NN;
    srcs[1] = g_zThi + (size_t)b*DD*NN;
    srcs[2] = g_zTlo + (size_t)b*DD*NN;

    // per-stage fragment byte offsets (tile 0 = Ph, 1 = zh, 2 = zl)
    uint32_t aPh[4], bZh[4], bZl[4];
    #pragma unroll
    for (int mt = 0; mt < 4; mt++){
        int row = warp_m*64 + mt*16 + (lane & 15);
        int c8  = (lane >> 4)*8;
        aPh[mt] = 0*TILE2B + (row*PITCH2 + c8)*2;
    }
    #pragma unroll
    for (int nt = 0; nt < 4; nt++){
        int row = warp_n*32 + nt*8 + (lane & 7);
        int c8  = ((lane >> 3) & 1)*8;
        bZh[nt] = 1*TILE2B + (row*PITCH2 + c8)*2;
        bZl[nt] = 2*TILE2B + (row*PITCH2 + c8)*2;
    }

    float d[4][4][4];
    #pragma unroll
    for (int mt = 0; mt < 4; mt++)
        #pragma unroll
        for (int nt = 0; nt < 4; nt++)
            #pragma unroll
            for (int c = 0; c < 4; c++) d[mt][nt][c] = 0.f;

    #define ISSUE(cc, st) do { \
        _Pragma("unroll") \
        for (int _p = 0; _p < 6; _p++){ \
            int _arr = _p >> 1; \
            int _slot = tid + 256*(_p & 1); \
            int _row = _slot >> 2, _seg = _slot & 3; \
            cp16(sb + (st)*STAGEB + _arr*TILE2B + (_row*PITCH2 + _seg*8)*2, \
                 srcs[_arr] + (size_t)_row*NN + (cc)*32 + _seg*8); \
        } \
        cp_commit(); \
    } while(0)

    ISSUE(0, 0);
    #pragma unroll 1
    for (int c = 0; c < 16; c++){
        int st = c & 1;
        if (c + 1 < 16) ISSUE(c+1, st^1);
        if (c + 1 < 16) cp_wait1(); else cp_wait0();
        __syncthreads();
        uint32_t base = sb + st*STAGEB;
        #pragma unroll
        for (int ks = 0; ks < 2; ks++){
            uint32_t bh[4][2], bl[4][2];
            #pragma unroll
            for (int nt = 0; nt < 4; nt++){
                ldmB(bh[nt], base + bZh[nt] + ks*32);
                ldmB(bl[nt], base + bZl[nt] + ks*32);
            }
            #pragma unroll
            for (int mt = 0; mt < 4; mt++){
                uint32_t ah[4];
                ldmA(ah, base + aPh[mt] + ks*32);
                #pragma unroll
                for (int nt = 0; nt < 4; nt++){
                    mma16816(d[mt][nt], ah, bh[nt]);
                    mma16816(d[mt][nt], ah, bl[nt]);
                }
            }
        }
        __syncthreads();
    }
    #undef ISSUE

    // epilogue: /cs, +bias, elu, pool over j
    float pd[8];
    #pragma unroll
    for (int q = 0; q < 8; q++) pd[q] = 0.f;
    #pragma unroll
    for (int mt = 0; mt < 4; mt++){
        #pragma unroll
        for (int half = 0; half < 2; half++){
            int jloc = warp_m*64 + mt*16 + g + 8*half;
            float inv = 1.f / sCs[jloc];
            #pragma unroll
            for (int nt = 0; nt < 4; nt++)
                #pragma unroll
                for (int par = 0; par < 2; par++){
                    float v = d[mt][nt][half*2+par]*inv + bi[nt*2+par];
                    v = v > 0.f ? v : expm1f(v);
                    pd[nt*2+par] += v;
                }
        }
    }
    #pragma unroll
    for (int q = 0; q < 8; q++){
        pd[q] += __shfl_xor_sync(0xFFFFFFFFu, pd[q], 4);
        pd[q] += __shfl_xor_sync(0xFFFFFFFFu, pd[q], 8);
        pd[q] += __shfl_xor_sync(0xFFFFFFFFu, pd[q], 16);
    }
    __syncthreads();
    if (g == 0){
        #pragma unroll
        for (int nt = 0; nt < 4; nt++)
            #pragma unroll
            for (int par = 0; par < 2; par++)
                red[warp_m*128 + warp_n*32 + nt*8 + 2*t + par] = pd[nt*2+par];
    }
    __syncthreads();
    if (tid < 128)
        g_pool[(b*4 + jt)*DD + tid] = red[tid] + red[128 + tid];
}

// ---------------- final: mean over nodes ----------------
__global__ void k_out(float* __restrict__ out){
    int b = blockIdx.x, d = threadIdx.x;
    float s = g_pool[(b*4+0)*DD + d] + g_pool[(b*4+1)*DD + d]
            + g_pool[(b*4+2)*DD + d] + g_pool[(b*4+3)*DD + d];
    out[b*DD + d] = s * (1.f / (float)NN);
}

extern "C" void kernel_launch(void* const* d_in, const int* in_sizes, int n_in,
                              void* d_out, int out_size){
    const float* E    = (const float*)d_in[0];
    const float* W    = (const float*)d_in[1];
    const float* al   = (const float*)d_in[2];
    const float* ar   = (const float*)d_in[3];
    const float* bias = (const float*)d_in[4];
    float* out = (float*)d_out;

    cudaFuncSetAttribute(k_scores_mma, cudaFuncAttributeMaxDynamicSharedMemorySize, SMEM_MMA);
    cudaFuncSetAttribute(k_pv_mma,     cudaFuncAttributeMaxDynamicSharedMemorySize, SMEM_PV);

    k_T         <<<dim3(16,4,64), dim3(32,8)>>>(E);
    k_thresh    <<<64, 128>>>(E);
    k_z         <<<dim3(4,64),  256>>>(W, al, ar);
    k_zT        <<<dim3(16,4,64), dim3(32,8)>>>();
    k_scores_mma<<<dim3(16,64), 256, SMEM_MMA>>>();
    k_pv_mma    <<<dim3(4,64),  256, SMEM_PV>>>(bias);
    k_out       <<<64, 128>>>(out);
}

// round 11
// speedup vs baseline: 1.8874x; 1.1475x over previous
#include <cuda_runtime.h>
#include <cuda_bf16.h>
#include <math.h>
#include <stdint.h>

#define BB 64
#define NN 512
#define DD 128
#define PITCH 136   // bf16 elems per smem row (272B): conflict-free ldmatrix
#define PITCH2 40   // bf16 elems per smem row for 32-wide k-chunks (80B)

typedef unsigned long long ull;

__device__ __forceinline__ unsigned sm32(const void* p){
    return (unsigned)__cvta_generic_to_shared(p);
}
__device__ __forceinline__ void cp16(unsigned dst, const void* src){
    asm volatile("cp.async.cg.shared.global [%0], [%1], 16;" :: "r"(dst), "l"(src));
}
__device__ __forceinline__ void cp_commit(){ asm volatile("cp.async.commit_group;"); }
__device__ __forceinline__ void cp_wait0(){ asm volatile("cp.async.wait_group 0;" ::: "memory"); }
__device__ __forceinline__ void cp_wait1(){ asm volatile("cp.async.wait_group 1;" ::: "memory"); }

// ---- warp-level MMA primitives (standard PTX, compute_103-safe) ----
__device__ __forceinline__ void ldmA(uint32_t* a, uint32_t addr){
    asm volatile("ldmatrix.sync.aligned.m8n8.x4.shared.b16 {%0,%1,%2,%3}, [%4];"
        : "=r"(a[0]), "=r"(a[1]), "=r"(a[2]), "=r"(a[3]) : "r"(addr));
}
__device__ __forceinline__ void ldmB(uint32_t* b, uint32_t addr){
    asm volatile("ldmatrix.sync.aligned.m8n8.x2.shared.b16 {%0,%1}, [%2];"
        : "=r"(b[0]), "=r"(b[1]) : "r"(addr));
}
__device__ __forceinline__ void mma16816(float* d, const uint32_t* a, const uint32_t* b){
    asm volatile("mma.sync.aligned.m16n8k16.row.col.f32.bf16.bf16.f32 "
        "{%0,%1,%2,%3}, {%4,%5,%6,%7}, {%8,%9}, {%0,%1,%2,%3};"
        : "+f"(d[0]), "+f"(d[1]), "+f"(d[2]), "+f"(d[3])
        : "r"(a[0]), "r"(a[1]), "r"(a[2]), "r"(a[3]), "r"(b[0]), "r"(b[1]));
}

// Scratch (static device globals; no allocation)
__device__ __nv_bfloat16 g_Ehi[(size_t)BB*NN*DD];   // E hi: [b][i][d]
__device__ __nv_bfloat16 g_Elo[(size_t)BB*NN*DD];   // E lo
__device__ __nv_bfloat16 g_Wthi[DD*DD];             // W^T hi: [d][k]
__device__ __nv_bfloat16 g_Wtlo[DD*DD];             // W^T lo
__device__ __nv_bfloat16 g_Pthi[(size_t)BB*NN*NN];  // P^T hi: [b][j][i]
__device__ __nv_bfloat16 g_zThi[(size_t)BB*DD*NN];  // z^T hi: [b][d][i]
__device__ __nv_bfloat16 g_zTlo[(size_t)BB*DD*NN];  // z^T lo
__device__ float g_eel [BB*NN];
__device__ float g_eel2[BB*NN];
__device__ float g_eer [BB*NN];
__device__ float g_eer2[BB*NN];
__device__ float g_th[BB];
__device__ float g_cs[BB*4*NN];
__device__ float g_pool[BB*4*DD];

// ---------------- E -> bf16 hi/lo split (no transpose needed) ----------------
__global__ void k_split(const float* __restrict__ E){
    size_t idx = ((size_t)blockIdx.x*256 + threadIdx.x)*4;
    float4 v = *(const float4*)(E + idx);
    __nv_bfloat16 h0 = __float2bfloat16(v.x), h1 = __float2bfloat16(v.y);
    __nv_bfloat16 h2 = __float2bfloat16(v.z), h3 = __float2bfloat16(v.w);
    __nv_bfloat162 hi01 = __halves2bfloat162(h0, h1), hi23 = __halves2bfloat162(h2, h3);
    __nv_bfloat162 lo01 = __halves2bfloat162(
        __float2bfloat16(v.x - __bfloat162float(h0)), __float2bfloat16(v.y - __bfloat162float(h1)));
    __nv_bfloat162 lo23 = __halves2bfloat162(
        __float2bfloat16(v.z - __bfloat162float(h2)), __float2bfloat16(v.w - __bfloat162float(h3)));
    *(__nv_bfloat162*)&g_Ehi[idx]   = hi01;
    *(__nv_bfloat162*)&g_Ehi[idx+2] = hi23;
    *(__nv_bfloat162*)&g_Elo[idx]   = lo01;
    *(__nv_bfloat162*)&g_Elo[idx+2] = lo23;
}

// ---------------- W -> W^T bf16 hi/lo ----------------
__global__ void k_Wt(const float* __restrict__ W){
    __shared__ float t[32][33];
    int k0 = blockIdx.x * 32;
    int d0 = blockIdx.y * 32;
    int tx = threadIdx.x, ty = threadIdx.y;   // (32, 8)
    #pragma unroll
    for (int yy = 0; yy < 32; yy += 8)
        t[ty+yy][tx] = W[(size_t)(k0+ty+yy)*DD + d0 + tx];
    __syncthreads();
    #pragma unroll
    for (int yy = 0; yy < 32; yy += 8){
        float v = t[tx][ty+yy];                         // W[k0+tx][d0+ty+yy]
        size_t idx = (size_t)(d0+ty+yy)*DD + k0 + tx;   // Wt[d][k]
        __nv_bfloat16 h = __float2bfloat16(v);
        g_Wthi[idx] = h;
        g_Wtlo[idx] = __float2bfloat16(v - __bfloat162float(h));
    }
}

// ---------------- thresh[b] = ||sum_i e_i||^2 / N^2 ----------------
__global__ void k_thresh(const float* __restrict__ E){
    int b = blockIdx.x; int t = threadIdx.x;
    const float* Eb = E + (size_t)b*NN*DD;
    float s = 0.f;
    for (int i = 0; i < NN; i++) s += Eb[(size_t)i*DD + t];
    __shared__ float red[DD];
    red[t] = s * s;
    __syncthreads();
    for (int o = 64; o > 0; o >>= 1){
        if (t < o) red[t] += red[t+o];
        __syncthreads();
    }
    if (t == 0) g_th[b] = red[0] * (1.f / ((float)NN * (float)NN));
}

// ---------------- shared tile-load / MMA-term macros ----------------
#define TILEB1 (128*PITCH*2)            // 34816
#define SMS_T0 0
#define SMS_T1 TILEB1
#define SMS_T2 (2*TILEB1)

#define LDTILE(dstoff, Src) do { \
    _Pragma("unroll") \
    for (int _p = 0; _p < 8; _p++){ \
        int _cid = tid + 256*_p; \
        int _row = _cid >> 4, _kc = _cid & 15; \
        cp16(sb + (dstoff) + (_row*PITCH + _kc*8)*2, (Src) + (size_t)_row*DD + _kc*8); \
    } \
} while(0)

#define TERM(at, bt) do { \
    _Pragma("unroll 1") \
    for (int ks = 0; ks < 8; ks++){ \
        uint32_t af[4][4], bf[4][2]; \
        _Pragma("unroll") \
        for (int mt = 0; mt < 4; mt++) ldmA(af[mt], sb + (at) + aoff[mt] + ks*32); \
        _Pragma("unroll") \
        for (int nt = 0; nt < 4; nt++) ldmB(bf[nt], sb + (bt) + boff[nt] + ks*32); \
        _Pragma("unroll") \
        for (int mt = 0; mt < 4; mt++) \
            _Pragma("unroll") \
            for (int nt = 0; nt < 4; nt++) \
                mma16816(d[mt][nt], af[mt], bf[nt]); \
    } \
} while(0)

// ---------------- HMMA z^T: D[m=d][n=i] = sum_k Wt[d][k] E[i][k]; + el/er exp tables ----------------
#define SMZ_RED (3*TILEB1)
#define SMEM_Z  (SMZ_RED + 4096)

__global__ void __launch_bounds__(256,2) k_z_mma(const float* __restrict__ attn_l,
                                                 const float* __restrict__ attn_r){
    extern __shared__ char smem[];
    uint32_t sb = sm32(smem);
    float* rel = (float*)(smem + SMZ_RED);          // [2][128]
    float* rer = rel + 256;                         // [2][128]

    int tid = threadIdx.x;
    int wid = tid >> 5, lane = tid & 31;
    int warp_m = wid >> 2, warp_n = wid & 3;
    int g = lane >> 2, t = lane & 3;
    int it = blockIdx.x, b = blockIdx.y;
    int i0 = it * 128;

    uint32_t aoff[4], boff[4];
    #pragma unroll
    for (int mt = 0; mt < 4; mt++)
        aoff[mt] = ((warp_m*64 + mt*16 + (lane & 15))*PITCH + (lane >> 4)*8)*2;
    #pragma unroll
    for (int nt = 0; nt < 4; nt++)
        boff[nt] = ((warp_n*32 + nt*8 + (lane & 7))*PITCH + ((lane >> 3) & 1)*8)*2;

    float d[4][4][4];
    #pragma unroll
    for (int mt = 0; mt < 4; mt++)
        #pragma unroll
        for (int nt = 0; nt < 4; nt++)
            #pragma unroll
            for (int c = 0; c < 4; c++) d[mt][nt][c] = 0.f;

    const __nv_bfloat16* Eh = g_Ehi + (size_t)b*NN*DD + (size_t)i0*DD;
    const __nv_bfloat16* El = g_Elo + (size_t)b*NN*DD + (size_t)i0*DD;

    // al/ar per thread's 8 d-rows
    float al8[8], ar8[8];
    #pragma unroll
    for (int mt = 0; mt < 4; mt++)
        #pragma unroll
        for (int half = 0; half < 2; half++){
            int dloc = warp_m*64 + mt*16 + g + 8*half;
            al8[mt*2+half] = attn_l[dloc];
            ar8[mt*2+half] = attn_r[dloc];
        }

    // rotation: T0=Wth, T1=El_i -> term0; T2=Eh_i; reload T1<-Wtl; term1=T0xT2; term2=T1xT2
    LDTILE(SMS_T0, g_Wthi);
    LDTILE(SMS_T1, El);
    cp_commit();
    LDTILE(SMS_T2, Eh);
    cp_commit();

    cp_wait1();
    __syncthreads();
    TERM(SMS_T0, SMS_T1);            // Wth * El
    __syncthreads();
    LDTILE(SMS_T1, g_Wtlo);
    cp_commit();
    cp_wait1();
    __syncthreads();
    TERM(SMS_T0, SMS_T2);            // Wth * Eh
    cp_wait0();
    __syncthreads();
    TERM(SMS_T1, SMS_T2);            // Wtl * Eh

    // epilogue: store zT hi/lo; accumulate el/er partials
    __nv_bfloat16* zh = g_zThi + (size_t)b*DD*NN;
    __nv_bfloat16* zl = g_zTlo + (size_t)b*DD*NN;
    float pel[8], per_[8];
    #pragma unroll
    for (int q = 0; q < 8; q++){ pel[q] = 0.f; per_[q] = 0.f; }
    #pragma unroll
    for (int mt = 0; mt < 4; mt++){
        #pragma unroll
        for (int half = 0; half < 2; half++){
            int dloc = warp_m*64 + mt*16 + g + 8*half;
            float wl = al8[mt*2+half], wr = ar8[mt*2+half];
            #pragma unroll
            for (int nt = 0; nt < 4; nt++){
                float v0 = d[mt][nt][half*2 + 0];
                float v1 = d[mt][nt][half*2 + 1];
                pel[nt*2+0] += wl*v0; pel[nt*2+1] += wl*v1;
                per_[nt*2+0] += wr*v0; per_[nt*2+1] += wr*v1;
                __nv_bfloat16 h0 = __float2bfloat16(v0);
                __nv_bfloat16 h1 = __float2bfloat16(v1);
                __nv_bfloat16 l0 = __float2bfloat16(v0 - __bfloat162float(h0));
                __nv_bfloat16 l1 = __float2bfloat16(v1 - __bfloat162float(h1));
                size_t addr = (size_t)dloc*NN + i0 + warp_n*32 + nt*8 + 2*t;
                *(__nv_bfloat162*)&zh[addr] = __halves2bfloat162(h0, h1);
                *(__nv_bfloat162*)&zl[addr] = __halves2bfloat162(l0, l1);
            }
        }
    }
    // reduce over g (lane bits 2..4)
    #pragma unroll
    for (int q = 0; q < 8; q++){
        pel[q] += __shfl_xor_sync(0xFFFFFFFFu, pel[q], 4);
        pel[q] += __shfl_xor_sync(0xFFFFFFFFu, pel[q], 8);
        pel[q] += __shfl_xor_sync(0xFFFFFFFFu, pel[q], 16);
        per_[q] += __shfl_xor_sync(0xFFFFFFFFu, per_[q], 4);
        per_[q] += __shfl_xor_sync(0xFFFFFFFFu, per_[q], 8);
        per_[q] += __shfl_xor_sync(0xFFFFFFFFu, per_[q], 16);
    }
    __syncthreads();
    if (g == 0){
        #pragma unroll
        for (int nt = 0; nt < 4; nt++)
            #pragma unroll
            for (int par = 0; par < 2; par++){
                int iloc = warp_n*32 + nt*8 + 2*t + par;
                rel[warp_m*128 + iloc] = pel[nt*2+par];
                rer[warp_m*128 + iloc] = per_[nt*2+par];
            }
    }
    __syncthreads();
    if (tid < 128){
        float se = rel[tid] + rel[128 + tid];
        float sr = rer[tid] + rer[128 + tid];
        int gi = b*NN + i0 + tid;
        g_eel [gi] = __expf(se);
        g_eel2[gi] = __expf(0.2f*se);
        g_eer [gi] = __expf(sr);
        g_eer2[gi] = __expf(0.2f*sr);
    }
}

// ---------------- HMMA scores -> Pt (bf16 hi only) + colsum partials ----------------
#define SM_ELI  (3*TILEB1)
#define SM_ELI2 (SM_ELI + 512)
#define SM_ERJ  (SM_ELI2 + 512)
#define SM_ERJ2 (SM_ERJ + 512)
#define SM_RED  (SM_ERJ2 + 512)
#define SMEM_MMA (SM_RED + 2048)

__global__ void __launch_bounds__(256,2) k_scores_mma(){
    extern __shared__ char smem[];
    uint32_t sb = sm32(smem);
    float* sEli  = (float*)(smem + SM_ELI);
    float* sEli2 = (float*)(smem + SM_ELI2);
    float* sErj  = (float*)(smem + SM_ERJ);
    float* sErj2 = (float*)(smem + SM_ERJ2);
    float* red   = (float*)(smem + SM_RED);

    int tid = threadIdx.x;
    int wid = tid >> 5, lane = tid & 31;
    int warp_m = wid >> 2, warp_n = wid & 3;
    int g = lane >> 2, t = lane & 3;
    int it = blockIdx.x & 3, jt = blockIdx.x >> 2;
    int b = blockIdx.y;
    int i0 = it * 128, j0 = jt * 128;

    if (tid < 128){
        sEli [tid] = g_eel [b*NN + i0 + tid];
        sEli2[tid] = g_eel2[b*NN + i0 + tid];
        sErj [tid] = g_eer [b*NN + j0 + tid];
        sErj2[tid] = g_eer2[b*NN + j0 + tid];
    }

    uint32_t aoff[4], boff[4];
    #pragma unroll
    for (int mt = 0; mt < 4; mt++)
        aoff[mt] = ((warp_m*64 + mt*16 + (lane & 15))*PITCH + (lane >> 4)*8)*2;
    #pragma unroll
    for (int nt = 0; nt < 4; nt++)
        boff[nt] = ((warp_n*32 + nt*8 + (lane & 7))*PITCH + ((lane >> 3) & 1)*8)*2;

    float d[4][4][4];
    #pragma unroll
    for (int mt = 0; mt < 4; mt++)
        #pragma unroll
        for (int nt = 0; nt < 4; nt++)
            #pragma unroll
            for (int c = 0; c < 4; c++) d[mt][nt][c] = 0.f;

    const __nv_bfloat16* Eh = g_Ehi + (size_t)b*NN*DD;
    const __nv_bfloat16* El = g_Elo + (size_t)b*NN*DD;

    LDTILE(SMS_T0, Eh + (size_t)j0*DD);
    LDTILE(SMS_T1, El + (size_t)i0*DD);
    cp_commit();
    LDTILE(SMS_T2, Eh + (size_t)i0*DD);
    cp_commit();

    cp_wait1();
    __syncthreads();
    TERM(SMS_T0, SMS_T1);            // Eh_j * El_i
    __syncthreads();
    LDTILE(SMS_T1, El + (size_t)j0*DD);
    cp_commit();
    cp_wait1();
    __syncthreads();
    TERM(SMS_T0, SMS_T2);            // Eh_j * Eh_i
    cp_wait0();
    __syncthreads();
    TERM(SMS_T1, SMS_T2);            // El_j * Eh_i

    // epilogue: Pt[j][i] bf16 hi only + colsum
    float th = g_th[b];
    __nv_bfloat16* Ph = g_Pthi + (size_t)b*NN*NN;
    float cs_p[8];
    #pragma unroll
    for (int mt = 0; mt < 4; mt++){
        #pragma unroll
        for (int half = 0; half < 2; half++){
            int jloc = warp_m*64 + mt*16 + g + 8*half;
            int jg = j0 + jloc;
            float Er = sErj[jloc], Er2 = sErj2[jloc];
            float csl = 0.f;
            #pragma unroll
            for (int nt = 0; nt < 4; nt++){
                float pv[2];
                #pragma unroll
                for (int par = 0; par < 2; par++){
                    int iloc = warp_n*32 + nt*8 + 2*t + par;
                    int ig = i0 + iloc;
                    float sv = d[mt][nt][half*2 + par];
                    float p = 0.f;
                    if (sv > th || ig == jg){
                        float q = sEli[iloc] * Er;
                        p = (q > 1.f) ? q : sEli2[iloc] * Er2;
                    }
                    csl += p; pv[par] = p;
                }
                __nv_bfloat16 h0 = __float2bfloat16(pv[0]);
                __nv_bfloat16 h1 = __float2bfloat16(pv[1]);
                size_t addr = (size_t)jg*NN + i0 + warp_n*32 + nt*8 + 2*t;
                *(__nv_bfloat162*)&Ph[addr] = __halves2bfloat162(h0, h1);
            }
            cs_p[mt*2 + half] = csl;
        }
    }
    #pragma unroll
    for (int h = 0; h < 8; h++){
        cs_p[h] += __shfl_xor_sync(0xFFFFFFFFu, cs_p[h], 1);
        cs_p[h] += __shfl_xor_sync(0xFFFFFFFFu, cs_p[h], 2);
    }
    __syncthreads();
    if (t == 0){
        #pragma unroll
        for (int h = 0; h < 8; h++){
            int mt = h >> 1, half = h & 1;
            int jloc = warp_m*64 + mt*16 + g + 8*half;
            red[jloc*4 + warp_n] = cs_p[h];
        }
    }
    __syncthreads();
    if (tid < 128){
        float tcs = red[tid*4] + red[tid*4+1] + red[tid*4+2] + red[tid*4+3];
        g_cs[(b*4 + it)*NN + j0 + tid] = tcs;
    }
}

// ---------------- HMMA PV (double-buffered, P hi only): h[j][d] = sum_i Pt[j][i] z[i][d] ----------------
#define TILE2B (128*PITCH2*2)           // 10240
#define STAGEB (3*TILE2B)               // 30720
#define SMP_CS (2*STAGEB)               // 61440
#define SMP_RED (SMP_CS + 512)
#define SMEM_PV (SMP_RED + 1024)

__global__ void __launch_bounds__(256,2) k_pv_mma(const float* __restrict__ bias){
    extern __shared__ char smem[];
    uint32_t sb = sm32(smem);
    float* sCs = (float*)(smem + SMP_CS);
    float* red = (float*)(smem + SMP_RED);
    int tid = threadIdx.x, wid = tid >> 5, lane = tid & 31;
    int warp_m = wid >> 2, warp_n = wid & 3;
    int g = lane >> 2, t = lane & 3;
    int jt = blockIdx.x, b = blockIdx.y;
    int j0 = jt * 128;

    if (tid < 128){
        int j = j0 + tid;
        sCs[tid] = g_cs[(b*4+0)*NN + j] + g_cs[(b*4+1)*NN + j]
                 + g_cs[(b*4+2)*NN + j] + g_cs[(b*4+3)*NN + j];
    }
    float bi[8];
    #pragma unroll
    for (int nt = 0; nt < 4; nt++)
        #pragma unroll
        for (int par = 0; par < 2; par++)
            bi[nt*2+par] = bias[warp_n*32 + nt*8 + 2*t + par];

    const __nv_bfloat16* srcs[3];
    srcs[0] = g_Pthi + (size_t)b*NN*NN + (size_t)j0*NN;
    srcs[1] = g_zThi + (size_t)b*DD*NN;
    srcs[2] = g_zTlo + (size_t)b*DD*NN;

    uint32_t aPh[4], bZh[4], bZl[4];
    #pragma unroll
    for (int mt = 0; mt < 4; mt++){
        int row = warp_m*64 + mt*16 + (lane & 15);
        int c8  = (lane >> 4)*8;
        aPh[mt] = 0*TILE2B + (row*PITCH2 + c8)*2;
    }
    #pragma unroll
    for (int nt = 0; nt < 4; nt++){
        int row = warp_n*32 + nt*8 + (lane & 7);
        int c8  = ((lane >> 3) & 1)*8;
        bZh[nt] = 1*TILE2B + (row*PITCH2 + c8)*2;
        bZl[nt] = 2*TILE2B + (row*PITCH2 + c8)*2;
    }

    float d[4][4][4];
    #pragma unroll
    for (int mt = 0; mt < 4; mt++)
        #pragma unroll
        for (int nt = 0; nt < 4; nt++)
            #pragma unroll
            for (int c = 0; c < 4; c++) d[mt][nt][c] = 0.f;

    #define ISSUE(cc, st) do { \
        _Pragma("unroll") \
        for (int _p = 0; _p < 6; _p++){ \
            int _arr = _p >> 1; \
            int _slot = tid + 256*(_p & 1); \
            int _row = _slot >> 2, _seg = _slot & 3; \
            cp16(sb + (st)*STAGEB + _arr*TILE2B + (_row*PITCH2 + _seg*8)*2, \
                 srcs[_arr] + (size_t)_row*NN + (cc)*32 + _seg*8); \
        } \
        cp_commit(); \
    } while(0)

    ISSUE(0, 0);
    #pragma unroll 1
    for (int c = 0; c < 16; c++){
        int st = c & 1;
        if (c + 1 < 16) ISSUE(c+1, st^1);
        if (c + 1 < 16) cp_wait1(); else cp_wait0();
        __syncthreads();
        uint32_t base = sb + st*STAGEB;
        #pragma unroll
        for (int ks = 0; ks < 2; ks++){
            uint32_t bh[4][2], bl[4][2];
            #pragma unroll
            for (int nt = 0; nt < 4; nt++){
                ldmB(bh[nt], base + bZh[nt] + ks*32);
                ldmB(bl[nt], base + bZl[nt] + ks*32);
            }
            #pragma unroll
            for (int mt = 0; mt < 4; mt++){
                uint32_t ah[4];
                ldmA(ah, base + aPh[mt] + ks*32);
                #pragma unroll
                for (int nt = 0; nt < 4; nt++){
                    mma16816(d[mt][nt], ah, bh[nt]);
                    mma16816(d[mt][nt], ah, bl[nt]);
                }
            }
        }
        __syncthreads();
    }
    #undef ISSUE

    float pd[8];
    #pragma unroll
    for (int q = 0; q < 8; q++) pd[q] = 0.f;
    #pragma unroll
    for (int mt = 0; mt < 4; mt++){
        #pragma unroll
        for (int half = 0; half < 2; half++){
            int jloc = warp_m*64 + mt*16 + g + 8*half;
            float inv = 1.f / sCs[jloc];
            #pragma unroll
            for (int nt = 0; nt < 4; nt++)
                #pragma unroll
                for (int par = 0; par < 2; par++){
                    float v = d[mt][nt][half*2+par]*inv + bi[nt*2+par];
                    v = v > 0.f ? v : expm1f(v);
                    pd[nt*2+par] += v;
                }
        }
    }
    #pragma unroll
    for (int q = 0; q < 8; q++){
        pd[q] += __shfl_xor_sync(0xFFFFFFFFu, pd[q], 4);
        pd[q] += __shfl_xor_sync(0xFFFFFFFFu, pd[q], 8);
        pd[q] += __shfl_xor_sync(0xFFFFFFFFu, pd[q], 16);
    }
    __syncthreads();
    if (g == 0){
        #pragma unroll
        for (int nt = 0; nt < 4; nt++)
            #pragma unroll
            for (int par = 0; par < 2; par++)
                red[warp_m*128 + warp_n*32 + nt*8 + 2*t + par] = pd[nt*2+par];
    }
    __syncthreads();
    if (tid < 128)
        g_pool[(b*4 + jt)*DD + tid] = red[tid] + red[128 + tid];
}

// ---------------- final: mean over nodes ----------------
__global__ void k_out(float* __restrict__ out){
    int b = blockIdx.x, d = threadIdx.x;
    float s = g_pool[(b*4+0)*DD + d] + g_pool[(b*4+1)*DD + d]
            + g_pool[(b*4+2)*DD + d] + g_pool[(b*4+3)*DD + d];
    out[b*DD + d] = s * (1.f / (float)NN);
}

extern "C" void kernel_launch(void* const* d_in, const int* in_sizes, int n_in,
                              void* d_out, int out_size){
    const float* E    = (const float*)d_in[0];
    const float* W    = (const float*)d_in[1];
    const float* al   = (const float*)d_in[2];
    const float* ar   = (const float*)d_in[3];
    const float* bias = (const float*)d_in[4];
    float* out = (float*)d_out;

    cudaFuncSetAttribute(k_z_mma,      cudaFuncAttributeMaxDynamicSharedMemorySize, SMEM_Z);
    cudaFuncSetAttribute(k_scores_mma, cudaFuncAttributeMaxDynamicSharedMemorySize, SMEM_MMA);
    cudaFuncSetAttribute(k_pv_mma,     cudaFuncAttributeMaxDynamicSharedMemorySize, SMEM_PV);

    k_split     <<<4096, 256>>>(E);
    k_Wt        <<<dim3(4,4), dim3(32,8)>>>(W);
    k_thresh    <<<64, 128>>>(E);
    k_z_mma     <<<dim3(4,64),  256, SMEM_Z>>>(al, ar);
    k_scores_mma<<<dim3(16,64), 256, SMEM_MMA>>>();
    k_pv_mma    <<<dim3(4,64),  256, SMEM_PV>>>(bias);
    k_out       <<<64, 128>>>(out);
}

// round 12
// speedup vs baseline: 1.9200x; 1.0173x over previous
#include <cuda_runtime.h>
#include <cuda_bf16.h>
#include <math.h>
#include <stdint.h>

#define BB 64
#define NN 512
#define DD 128
#define PITCH 136   // bf16 elems per smem row (272B): conflict-free ldmatrix
#define PITCH2 40   // bf16 elems per smem row for 32-wide k-chunks (80B)

typedef unsigned long long ull;

__device__ __forceinline__ unsigned sm32(const void* p){
    return (unsigned)__cvta_generic_to_shared(p);
}
__device__ __forceinline__ void cp16(unsigned dst, const void* src){
    asm volatile("cp.async.cg.shared.global [%0], [%1], 16;" :: "r"(dst), "l"(src));
}
__device__ __forceinline__ void cp_commit(){ asm volatile("cp.async.commit_group;"); }
__device__ __forceinline__ void cp_wait0(){ asm volatile("cp.async.wait_group 0;" ::: "memory"); }
__device__ __forceinline__ void cp_wait1(){ asm volatile("cp.async.wait_group 1;" ::: "memory"); }

// ---- warp-level MMA primitives (standard PTX, compute_103-safe) ----
__device__ __forceinline__ void ldmA(uint32_t* a, uint32_t addr){
    asm volatile("ldmatrix.sync.aligned.m8n8.x4.shared.b16 {%0,%1,%2,%3}, [%4];"
        : "=r"(a[0]), "=r"(a[1]), "=r"(a[2]), "=r"(a[3]) : "r"(addr));
}
__device__ __forceinline__ void ldmB(uint32_t* b, uint32_t addr){
    asm volatile("ldmatrix.sync.aligned.m8n8.x2.shared.b16 {%0,%1}, [%2];"
        : "=r"(b[0]), "=r"(b[1]) : "r"(addr));
}
__device__ __forceinline__ void mma16816(float* d, const uint32_t* a, const uint32_t* b){
    asm volatile("mma.sync.aligned.m16n8k16.row.col.f32.bf16.bf16.f32 "
        "{%0,%1,%2,%3}, {%4,%5,%6,%7}, {%8,%9}, {%0,%1,%2,%3};"
        : "+f"(d[0]), "+f"(d[1]), "+f"(d[2]), "+f"(d[3])
        : "r"(a[0]), "r"(a[1]), "r"(a[2]), "r"(a[3]), "r"(b[0]), "r"(b[1]));
}

// Scratch (static device globals; no allocation)
__device__ __nv_bfloat16 g_Ehi[(size_t)BB*NN*DD];   // E hi: [b][i][d]
__device__ __nv_bfloat16 g_Elo[(size_t)BB*NN*DD];   // E lo
__device__ __nv_bfloat16 g_Wthi[DD*DD];             // W^T hi: [d][k]
__device__ __nv_bfloat16 g_Wtlo[DD*DD];             // W^T lo
__device__ __nv_bfloat16 g_Pthi[(size_t)BB*NN*NN];  // P^T hi: [b][j][i]
__device__ __nv_bfloat16 g_zThi[(size_t)BB*DD*NN];  // z^T hi: [b][d][i]
__device__ __nv_bfloat16 g_zTlo[(size_t)BB*DD*NN];  // z^T lo
__device__ float g_eel [BB*NN];
__device__ float g_eel2[BB*NN];
__device__ float g_eer [BB*NN];
__device__ float g_eer2[BB*NN];
__device__ float g_th[BB];
__device__ float g_cs[BB*4*NN];
__device__ float g_pool[BB*4*DD];

// ---------------- E -> bf16 hi/lo split ----------------
__global__ void k_split(const float* __restrict__ E){
    size_t idx = ((size_t)blockIdx.x*256 + threadIdx.x)*4;
    float4 v = *(const float4*)(E + idx);
    __nv_bfloat16 h0 = __float2bfloat16(v.x), h1 = __float2bfloat16(v.y);
    __nv_bfloat16 h2 = __float2bfloat16(v.z), h3 = __float2bfloat16(v.w);
    __nv_bfloat162 hi01 = __halves2bfloat162(h0, h1), hi23 = __halves2bfloat162(h2, h3);
    __nv_bfloat162 lo01 = __halves2bfloat162(
        __float2bfloat16(v.x - __bfloat162float(h0)), __float2bfloat16(v.y - __bfloat162float(h1)));
    __nv_bfloat162 lo23 = __halves2bfloat162(
        __float2bfloat16(v.z - __bfloat162float(h2)), __float2bfloat16(v.w - __bfloat162float(h3)));
    *(__nv_bfloat162*)&g_Ehi[idx]   = hi01;
    *(__nv_bfloat162*)&g_Ehi[idx+2] = hi23;
    *(__nv_bfloat162*)&g_Elo[idx]   = lo01;
    *(__nv_bfloat162*)&g_Elo[idx+2] = lo23;
}

// ---------------- W -> W^T bf16 hi/lo ----------------
__global__ void k_Wt(const float* __restrict__ W){
    __shared__ float t[32][33];
    int k0 = blockIdx.x * 32;
    int d0 = blockIdx.y * 32;
    int tx = threadIdx.x, ty = threadIdx.y;   // (32, 8)
    #pragma unroll
    for (int yy = 0; yy < 32; yy += 8)
        t[ty+yy][tx] = W[(size_t)(k0+ty+yy)*DD + d0 + tx];
    __syncthreads();
    #pragma unroll
    for (int yy = 0; yy < 32; yy += 8){
        float v = t[tx][ty+yy];
        size_t idx = (size_t)(d0+ty+yy)*DD + k0 + tx;
        __nv_bfloat16 h = __float2bfloat16(v);
        g_Wthi[idx] = h;
        g_Wtlo[idx] = __float2bfloat16(v - __bfloat162float(h));
    }
}

// ---------------- thresh[b] = ||sum_i e_i||^2 / N^2 ----------------
__global__ void k_thresh(const float* __restrict__ E){
    int b = blockIdx.x; int t = threadIdx.x;
    const float* Eb = E + (size_t)b*NN*DD;
    float s = 0.f;
    for (int i = 0; i < NN; i++) s += Eb[(size_t)i*DD + t];
    __shared__ float red[DD];
    red[t] = s * s;
    __syncthreads();
    for (int o = 64; o > 0; o >>= 1){
        if (t < o) red[t] += red[t+o];
        __syncthreads();
    }
    if (t == 0) g_th[b] = red[0] * (1.f / ((float)NN * (float)NN));
}

// ---------------- shared tile-load / MMA-term macros ----------------
#define TILEB1 (128*PITCH*2)            // 34816
#define SMS_T0 0
#define SMS_T1 TILEB1
#define SMS_T2 (2*TILEB1)

#define LDTILE(dstoff, Src) do { \
    _Pragma("unroll") \
    for (int _p = 0; _p < 8; _p++){ \
        int _cid = tid + 256*_p; \
        int _row = _cid >> 4, _kc = _cid & 15; \
        cp16(sb + (dstoff) + (_row*PITCH + _kc*8)*2, (Src) + (size_t)_row*DD + _kc*8); \
    } \
} while(0)

// unroll 2: overlap next k-step's ldmatrix with current k-step's MMAs
#define TERM(at, bt) do { \
    _Pragma("unroll 2") \
    for (int ks = 0; ks < 8; ks++){ \
        uint32_t af[4][4], bf[4][2]; \
        _Pragma("unroll") \
        for (int mt = 0; mt < 4; mt++) ldmA(af[mt], sb + (at) + aoff[mt] + ks*32); \
        _Pragma("unroll") \
        for (int nt = 0; nt < 4; nt++) ldmB(bf[nt], sb + (bt) + boff[nt] + ks*32); \
        _Pragma("unroll") \
        for (int mt = 0; mt < 4; mt++) \
            _Pragma("unroll") \
            for (int nt = 0; nt < 4; nt++) \
                mma16816(d[mt][nt], af[mt], bf[nt]); \
    } \
} while(0)

// ---------------- HMMA z^T: D[m=d][n=i] = sum_k Wt[d][k] E[i][k]; + el/er exp tables ----------------
#define SMZ_RED (3*TILEB1)
#define SMEM_Z  (SMZ_RED + 4096)

__global__ void __launch_bounds__(256,2) k_z_mma(const float* __restrict__ attn_l,
                                                 const float* __restrict__ attn_r){
    extern __shared__ char smem[];
    uint32_t sb = sm32(smem);
    float* rel = (float*)(smem + SMZ_RED);
    float* rer = rel + 256;

    int tid = threadIdx.x;
    int wid = tid >> 5, lane = tid & 31;
    int warp_m = wid >> 2, warp_n = wid & 3;
    int g = lane >> 2, t = lane & 3;
    int it = blockIdx.x, b = blockIdx.y;
    int i0 = it * 128;

    uint32_t aoff[4], boff[4];
    #pragma unroll
    for (int mt = 0; mt < 4; mt++)
        aoff[mt] = ((warp_m*64 + mt*16 + (lane & 15))*PITCH + (lane >> 4)*8)*2;
    #pragma unroll
    for (int nt = 0; nt < 4; nt++)
        boff[nt] = ((warp_n*32 + nt*8 + (lane & 7))*PITCH + ((lane >> 3) & 1)*8)*2;

    float d[4][4][4];
    #pragma unroll
    for (int mt = 0; mt < 4; mt++)
        #pragma unroll
        for (int nt = 0; nt < 4; nt++)
            #pragma unroll
            for (int c = 0; c < 4; c++) d[mt][nt][c] = 0.f;

    const __nv_bfloat16* Eh = g_Ehi + (size_t)b*NN*DD + (size_t)i0*DD;
    const __nv_bfloat16* El = g_Elo + (size_t)b*NN*DD + (size_t)i0*DD;

    float al8[8], ar8[8];
    #pragma unroll
    for (int mt = 0; mt < 4; mt++)
        #pragma unroll
        for (int half = 0; half < 2; half++){
            int dloc = warp_m*64 + mt*16 + g + 8*half;
            al8[mt*2+half] = attn_l[dloc];
            ar8[mt*2+half] = attn_r[dloc];
        }

    LDTILE(SMS_T0, g_Wthi);
    LDTILE(SMS_T1, El);
    cp_commit();
    LDTILE(SMS_T2, Eh);
    cp_commit();

    cp_wait1();
    __syncthreads();
    TERM(SMS_T0, SMS_T1);            // Wth * El
    __syncthreads();
    LDTILE(SMS_T1, g_Wtlo);
    cp_commit();
    cp_wait1();
    __syncthreads();
    TERM(SMS_T0, SMS_T2);            // Wth * Eh
    cp_wait0();
    __syncthreads();
    TERM(SMS_T1, SMS_T2);            // Wtl * Eh

    __nv_bfloat16* zh = g_zThi + (size_t)b*DD*NN;
    __nv_bfloat16* zl = g_zTlo + (size_t)b*DD*NN;
    float pel[8], per_[8];
    #pragma unroll
    for (int q = 0; q < 8; q++){ pel[q] = 0.f; per_[q] = 0.f; }
    #pragma unroll
    for (int mt = 0; mt < 4; mt++){
        #pragma unroll
        for (int half = 0; half < 2; half++){
            int dloc = warp_m*64 + mt*16 + g + 8*half;
            float wl = al8[mt*2+half], wr = ar8[mt*2+half];
            #pragma unroll
            for (int nt = 0; nt < 4; nt++){
                float v0 = d[mt][nt][half*2 + 0];
                float v1 = d[mt][nt][half*2 + 1];
                pel[nt*2+0] += wl*v0; pel[nt*2+1] += wl*v1;
                per_[nt*2+0] += wr*v0; per_[nt*2+1] += wr*v1;
                __nv_bfloat16 h0 = __float2bfloat16(v0);
                __nv_bfloat16 h1 = __float2bfloat16(v1);
                __nv_bfloat16 l0 = __float2bfloat16(v0 - __bfloat162float(h0));
                __nv_bfloat16 l1 = __float2bfloat16(v1 - __bfloat162float(h1));
                size_t addr = (size_t)dloc*NN + i0 + warp_n*32 + nt*8 + 2*t;
                *(__nv_bfloat162*)&zh[addr] = __halves2bfloat162(h0, h1);
                *(__nv_bfloat162*)&zl[addr] = __halves2bfloat162(l0, l1);
            }
        }
    }
    #pragma unroll
    for (int q = 0; q < 8; q++){
        pel[q] += __shfl_xor_sync(0xFFFFFFFFu, pel[q], 4);
        pel[q] += __shfl_xor_sync(0xFFFFFFFFu, pel[q], 8);
        pel[q] += __shfl_xor_sync(0xFFFFFFFFu, pel[q], 16);
        per_[q] += __shfl_xor_sync(0xFFFFFFFFu, per_[q], 4);
        per_[q] += __shfl_xor_sync(0xFFFFFFFFu, per_[q], 8);
        per_[q] += __shfl_xor_sync(0xFFFFFFFFu, per_[q], 16);
    }
    __syncthreads();
    if (g == 0){
        #pragma unroll
        for (int nt = 0; nt < 4; nt++)
            #pragma unroll
            for (int par = 0; par < 2; par++){
                int iloc = warp_n*32 + nt*8 + 2*t + par;
                rel[warp_m*128 + iloc] = pel[nt*2+par];
                rer[warp_m*128 + iloc] = per_[nt*2+par];
            }
    }
    __syncthreads();
    if (tid < 128){
        float se = rel[tid] + rel[128 + tid];
        float sr = rer[tid] + rer[128 + tid];
        int gi = b*NN + i0 + tid;
        g_eel [gi] = __expf(se);
        g_eel2[gi] = __expf(0.2f*se);
        g_eer [gi] = __expf(sr);
        g_eer2[gi] = __expf(0.2f*sr);
    }
}

// ---------------- HMMA scores -> Pt (bf16 hi only) + colsum partials ----------------
#define SM_ELI  (3*TILEB1)
#define SM_ELI2 (SM_ELI + 512)
#define SM_ERJ  (SM_ELI2 + 512)
#define SM_ERJ2 (SM_ERJ + 512)
#define SM_RED  (SM_ERJ2 + 512)
#define SMEM_MMA (SM_RED + 2048)

__global__ void __launch_bounds__(256,2) k_scores_mma(){
    extern __shared__ char smem[];
    uint32_t sb = sm32(smem);
    float* sEli  = (float*)(smem + SM_ELI);
    float* sEli2 = (float*)(smem + SM_ELI2);
    float* sErj  = (float*)(smem + SM_ERJ);
    float* sErj2 = (float*)(smem + SM_ERJ2);
    float* red   = (float*)(smem + SM_RED);

    int tid = threadIdx.x;
    int wid = tid >> 5, lane = tid & 31;
    int warp_m = wid >> 2, warp_n = wid & 3;
    int g = lane >> 2, t = lane & 3;
    int it = blockIdx.x & 3, jt = blockIdx.x >> 2;
    int b = blockIdx.y;
    int i0 = it * 128, j0 = jt * 128;

    if (tid < 128){
        sEli [tid] = g_eel [b*NN + i0 + tid];
        sEli2[tid] = g_eel2[b*NN + i0 + tid];
        sErj [tid] = g_eer [b*NN + j0 + tid];
        sErj2[tid] = g_eer2[b*NN + j0 + tid];
    }

    uint32_t aoff[4], boff[4];
    #pragma unroll
    for (int mt = 0; mt < 4; mt++)
        aoff[mt] = ((warp_m*64 + mt*16 + (lane & 15))*PITCH + (lane >> 4)*8)*2;
    #pragma unroll
    for (int nt = 0; nt < 4; nt++)
        boff[nt] = ((warp_n*32 + nt*8 + (lane & 7))*PITCH + ((lane >> 3) & 1)*8)*2;

    float d[4][4][4];
    #pragma unroll
    for (int mt = 0; mt < 4; mt++)
        #pragma unroll
        for (int nt = 0; nt < 4; nt++)
            #pragma unroll
            for (int c = 0; c < 4; c++) d[mt][nt][c] = 0.f;

    const __nv_bfloat16* Eh = g_Ehi + (size_t)b*NN*DD;
    const __nv_bfloat16* El = g_Elo + (size_t)b*NN*DD;

    LDTILE(SMS_T0, Eh + (size_t)j0*DD);
    LDTILE(SMS_T1, El + (size_t)i0*DD);
    cp_commit();
    LDTILE(SMS_T2, Eh + (size_t)i0*DD);
    cp_commit();

    cp_wait1();
    __syncthreads();
    TERM(SMS_T0, SMS_T1);            // Eh_j * El_i
    __syncthreads();
    LDTILE(SMS_T1, El + (size_t)j0*DD);
    cp_commit();
    cp_wait1();
    __syncthreads();
    TERM(SMS_T0, SMS_T2);            // Eh_j * Eh_i
    cp_wait0();
    __syncthreads();
    TERM(SMS_T1, SMS_T2);            // El_j * Eh_i

    float th = g_th[b];
    __nv_bfloat16* Ph = g_Pthi + (size_t)b*NN*NN;
    float cs_p[8];
    #pragma unroll
    for (int mt = 0; mt < 4; mt++){
        #pragma unroll
        for (int half = 0; half < 2; half++){
            int jloc = warp_m*64 + mt*16 + g + 8*half;
            int jg = j0 + jloc;
            float Er = sErj[jloc], Er2 = sErj2[jloc];
            float csl = 0.f;
            #pragma unroll
            for (int nt = 0; nt < 4; nt++){
                float pv[2];
                #pragma unroll
                for (int par = 0; par < 2; par++){
                    int iloc = warp_n*32 + nt*8 + 2*t + par;
                    int ig = i0 + iloc;
                    float sv = d[mt][nt][half*2 + par];
                    float p = 0.f;
                    if (sv > th || ig == jg){
                        float q = sEli[iloc] * Er;
                        p = (q > 1.f) ? q : sEli2[iloc] * Er2;
                    }
                    csl += p; pv[par] = p;
                }
                __nv_bfloat16 h0 = __float2bfloat16(pv[0]);
                __nv_bfloat16 h1 = __float2bfloat16(pv[1]);
                size_t addr = (size_t)jg*NN + i0 + warp_n*32 + nt*8 + 2*t;
                *(__nv_bfloat162*)&Ph[addr] = __halves2bfloat162(h0, h1);
            }
            cs_p[mt*2 + half] = csl;
        }
    }
    #pragma unroll
    for (int h = 0; h < 8; h++){
        cs_p[h] += __shfl_xor_sync(0xFFFFFFFFu, cs_p[h], 1);
        cs_p[h] += __shfl_xor_sync(0xFFFFFFFFu, cs_p[h], 2);
    }
    __syncthreads();
    if (t == 0){
        #pragma unroll
        for (int h = 0; h < 8; h++){
            int mt = h >> 1, half = h & 1;
            int jloc = warp_m*64 + mt*16 + g + 8*half;
            red[jloc*4 + warp_n] = cs_p[h];
        }
    }
    __syncthreads();
    if (tid < 128){
        float tcs = red[tid*4] + red[tid*4+1] + red[tid*4+2] + red[tid*4+3];
        g_cs[(b*4 + it)*NN + j0 + tid] = tcs;
    }
}

// ---------------- HMMA PV (3-stage pipeline, 1 sync/chunk): h[j][d] = sum_i Pt[j][i] z[i][d] ----------------
#define TILE2B (128*PITCH2*2)           // 10240
#define STAGEB (3*TILE2B)               // 30720
#define SMP_CS (3*STAGEB)               // 92160
#define SMP_RED (SMP_CS + 512)
#define SMEM_PV (SMP_RED + 1024)

__global__ void __launch_bounds__(256,2) k_pv_mma(const float* __restrict__ bias){
    extern __shared__ char smem[];
    uint32_t sb = sm32(smem);
    float* sCs = (float*)(smem + SMP_CS);
    float* red = (float*)(smem + SMP_RED);
    int tid = threadIdx.x, wid = tid >> 5, lane = tid & 31;
    int warp_m = wid >> 2, warp_n = wid & 3;
    int g = lane >> 2, t = lane & 3;
    int jt = blockIdx.x, b = blockIdx.y;
    int j0 = jt * 128;

    if (tid < 128){
        int j = j0 + tid;
        sCs[tid] = g_cs[(b*4+0)*NN + j] + g_cs[(b*4+1)*NN + j]
                 + g_cs[(b*4+2)*NN + j] + g_cs[(b*4+3)*NN + j];
    }
    float bi[8];
    #pragma unroll
    for (int nt = 0; nt < 4; nt++)
        #pragma unroll
        for (int par = 0; par < 2; par++)
            bi[nt*2+par] = bias[warp_n*32 + nt*8 + 2*t + par];

    const __nv_bfloat16* srcs[3];
    srcs[0] = g_Pthi + (size_t)b*NN*NN + (size_t)j0*NN;
    srcs[1] = g_zThi + (size_t)b*DD*NN;
    srcs[2] = g_zTlo + (size_t)b*DD*NN;

    uint32_t aPh[4], bZh[4], bZl[4];
    #pragma unroll
    for (int mt = 0; mt < 4; mt++){
        int row = warp_m*64 + mt*16 + (lane & 15);
        int c8  = (lane >> 4)*8;
        aPh[mt] = 0*TILE2B + (row*PITCH2 + c8)*2;
    }
    #pragma unroll
    for (int nt = 0; nt < 4; nt++){
        int row = warp_n*32 + nt*8 + (lane & 7);
        int c8  = ((lane >> 3) & 1)*8;
        bZh[nt] = 1*TILE2B + (row*PITCH2 + c8)*2;
        bZl[nt] = 2*TILE2B + (row*PITCH2 + c8)*2;
    }

    float d[4][4][4];
    #pragma unroll
    for (int mt = 0; mt < 4; mt++)
        #pragma unroll
        for (int nt = 0; nt < 4; nt++)
            #pragma unroll
            for (int c = 0; c < 4; c++) d[mt][nt][c] = 0.f;

    #define ISSUE(cc, st) do { \
        _Pragma("unroll") \
        for (int _p = 0; _p < 6; _p++){ \
            int _arr = _p >> 1; \
            int _slot = tid + 256*(_p & 1); \
            int _row = _slot >> 2, _seg = _slot & 3; \
            cp16(sb + (st)*STAGEB + _arr*TILE2B + (_row*PITCH2 + _seg*8)*2, \
                 srcs[_arr] + (size_t)_row*NN + (cc)*32 + _seg*8); \
        } \
        cp_commit(); \
    } while(0)

    ISSUE(0, 0);
    ISSUE(1, 1);
    #pragma unroll 1
    for (int c = 0; c < 16; c++){
        int st = c % 3;
        if (c < 15) cp_wait1(); else cp_wait0();
        __syncthreads();
        uint32_t base = sb + st*STAGEB;
        #pragma unroll 2
        for (int ks = 0; ks < 2; ks++){
            uint32_t bh[4][2], bl[4][2];
            #pragma unroll
            for (int nt = 0; nt < 4; nt++){
                ldmB(bh[nt], base + bZh[nt] + ks*32);
                ldmB(bl[nt], base + bZl[nt] + ks*32);
            }
            #pragma unroll
            for (int mt = 0; mt < 4; mt++){
                uint32_t ah[4];
                ldmA(ah, base + aPh[mt] + ks*32);
                #pragma unroll
                for (int nt = 0; nt < 4; nt++){
                    mma16816(d[mt][nt], ah, bh[nt]);
                    mma16816(d[mt][nt], ah, bl[nt]);
                }
            }
        }
        if (c + 2 < 16) ISSUE(c+2, (c+2)%3);
    }
    #undef ISSUE

    float pd[8];
    #pragma unroll
    for (int q = 0; q < 8; q++) pd[q] = 0.f;
    #pragma unroll
    for (int mt = 0; mt < 4; mt++){
        #pragma unroll
        for (int half = 0; half < 2; half++){
            int jloc = warp_m*64 + mt*16 + g + 8*half;
            float inv = 1.f / sCs[jloc];
            #pragma unroll
            for (int nt = 0; nt < 4; nt++)
                #pragma unroll
                for (int par = 0; par < 2; par++){
                    float v = d[mt][nt][half*2+par]*inv + bi[nt*2+par];
                    v = v > 0.f ? v : expm1f(v);
                    pd[nt*2+par] += v;
                }
        }
    }
    #pragma unroll
    for (int q = 0; q < 8; q++){
        pd[q] += __shfl_xor_sync(0xFFFFFFFFu, pd[q], 4);
        pd[q] += __shfl_xor_sync(0xFFFFFFFFu, pd[q], 8);
        pd[q] += __shfl_xor_sync(0xFFFFFFFFu, pd[q], 16);
    }
    __syncthreads();
    if (g == 0){
        #pragma unroll
        for (int nt = 0; nt < 4; nt++)
            #pragma unroll
            for (int par = 0; par < 2; par++)
                red[warp_m*128 + warp_n*32 + nt*8 + 2*t + par] = pd[nt*2+par];
    }
    __syncthreads();
    if (tid < 128)
        g_pool[(b*4 + jt)*DD + tid] = red[tid] + red[128 + tid];
}

// ---------------- final: mean over nodes ----------------
__global__ void k_out(float* __restrict__ out){
    int b = blockIdx.x, d = threadIdx.x;
    float s = g_pool[(b*4+0)*DD + d] + g_pool[(b*4+1)*DD + d]
            + g_pool[(b*4+2)*DD + d] + g_pool[(b*4+3)*DD + d];
    out[b*DD + d] = s * (1.f / (float)NN);
}

extern "C" void kernel_launch(void* const* d_in, const int* in_sizes, int n_in,
                              void* d_out, int out_size){
    const float* E    = (const float*)d_in[0];
    const float* W    = (const float*)d_in[1];
    const float* al   = (const float*)d_in[2];
    const float* ar   = (const float*)d_in[3];
    const float* bias = (const float*)d_in[4];
    float* out = (float*)d_out;

    cudaFuncSetAttribute(k_z_mma,      cudaFuncAttributeMaxDynamicSharedMemorySize, SMEM_Z);
    cudaFuncSetAttribute(k_scores_mma, cudaFuncAttributeMaxDynamicSharedMemorySize, SMEM_MMA);
    cudaFuncSetAttribute(k_pv_mma,     cudaFuncAttributeMaxDynamicSharedMemorySize, SMEM_PV);

    k_split     <<<4096, 256>>>(E);
    k_Wt        <<<dim3(4,4), dim3(32,8)>>>(W);
    k_thresh    <<<64, 128>>>(E);
    k_z_mma     <<<dim3(4,64),  256, SMEM_Z>>>(al, ar);
    k_scores_mma<<<dim3(16,64), 256, SMEM_MMA>>>();
    k_pv_mma    <<<dim3(4,64),  256, SMEM_PV>>>(bias);
    k_out       <<<64, 128>>>(out);
}

// round 13
// speedup vs baseline: 1.9787x; 1.0306x over previous
#include <cuda_runtime.h>
#include <cuda_bf16.h>
#include <math.h>
#include <stdint.h>

#define BB 64
#define NN 512
#define DD 128
#define PITCH 136   // bf16 elems per smem row (272B): conflict-free ldmatrix
#define PITCH2 40   // bf16 elems per smem row for 32-wide k-chunks (80B)

typedef unsigned long long ull;

__device__ __forceinline__ unsigned sm32(const void* p){
    return (unsigned)__cvta_generic_to_shared(p);
}
__device__ __forceinline__ void cp16(unsigned dst, const void* src){
    asm volatile("cp.async.cg.shared.global [%0], [%1], 16;" :: "r"(dst), "l"(src));
}
__device__ __forceinline__ void cp_commit(){ asm volatile("cp.async.commit_group;"); }
__device__ __forceinline__ void cp_wait0(){ asm volatile("cp.async.wait_group 0;" ::: "memory"); }
__device__ __forceinline__ void cp_wait1(){ asm volatile("cp.async.wait_group 1;" ::: "memory"); }

// ---- warp-level MMA primitives (standard PTX, compute_103-safe) ----
__device__ __forceinline__ void ldmA(uint32_t* a, uint32_t addr){
    asm volatile("ldmatrix.sync.aligned.m8n8.x4.shared.b16 {%0,%1,%2,%3}, [%4];"
        : "=r"(a[0]), "=r"(a[1]), "=r"(a[2]), "=r"(a[3]) : "r"(addr));
}
__device__ __forceinline__ void ldmB(uint32_t* b, uint32_t addr){
    asm volatile("ldmatrix.sync.aligned.m8n8.x2.shared.b16 {%0,%1}, [%2];"
        : "=r"(b[0]), "=r"(b[1]) : "r"(addr));
}
__device__ __forceinline__ void mma16816(float* d, const uint32_t* a, const uint32_t* b){
    asm volatile("mma.sync.aligned.m16n8k16.row.col.f32.bf16.bf16.f32 "
        "{%0,%1,%2,%3}, {%4,%5,%6,%7}, {%8,%9}, {%0,%1,%2,%3};"
        : "+f"(d[0]), "+f"(d[1]), "+f"(d[2]), "+f"(d[3])
        : "r"(a[0]), "r"(a[1]), "r"(a[2]), "r"(a[3]), "r"(b[0]), "r"(b[1]));
}
__device__ __forceinline__ uint32_t packbf(float lo, float hi){
    __nv_bfloat162 v = __halves2bfloat162(__float2bfloat16(lo), __float2bfloat16(hi));
    return *(uint32_t*)&v;
}

// Scratch (static device globals; no allocation)
__device__ __nv_bfloat16 g_Ehi[(size_t)BB*NN*DD];   // E hi: [b][i][d]
__device__ __nv_bfloat16 g_Elo[(size_t)BB*NN*DD];   // E lo
__device__ __nv_bfloat16 g_Wthi[DD*DD];             // W^T hi: [d][k]
__device__ __nv_bfloat16 g_Wtlo[DD*DD];             // W^T lo
__device__ __nv_bfloat16 g_zThi[(size_t)BB*DD*NN];  // z^T hi: [b][d][i]
__device__ __nv_bfloat16 g_zTlo[(size_t)BB*DD*NN];  // z^T lo
__device__ float g_eel [BB*NN];
__device__ float g_eel2[BB*NN];
__device__ float g_eer [BB*NN];
__device__ float g_eer2[BB*NN];
__device__ float g_th[BB];
__device__ float g_pool[BB*4*DD];

// ---------------- E -> bf16 hi/lo split ----------------
__global__ void k_split(const float* __restrict__ E){
    size_t idx = ((size_t)blockIdx.x*256 + threadIdx.x)*4;
    float4 v = *(const float4*)(E + idx);
    __nv_bfloat16 h0 = __float2bfloat16(v.x), h1 = __float2bfloat16(v.y);
    __nv_bfloat16 h2 = __float2bfloat16(v.z), h3 = __float2bfloat16(v.w);
    __nv_bfloat162 hi01 = __halves2bfloat162(h0, h1), hi23 = __halves2bfloat162(h2, h3);
    __nv_bfloat162 lo01 = __halves2bfloat162(
        __float2bfloat16(v.x - __bfloat162float(h0)), __float2bfloat16(v.y - __bfloat162float(h1)));
    __nv_bfloat162 lo23 = __halves2bfloat162(
        __float2bfloat16(v.z - __bfloat162float(h2)), __float2bfloat16(v.w - __bfloat162float(h3)));
    *(__nv_bfloat162*)&g_Ehi[idx]   = hi01;
    *(__nv_bfloat162*)&g_Ehi[idx+2] = hi23;
    *(__nv_bfloat162*)&g_Elo[idx]   = lo01;
    *(__nv_bfloat162*)&g_Elo[idx+2] = lo23;
}

// ---------------- W -> W^T bf16 hi/lo ----------------
__global__ void k_Wt(const float* __restrict__ W){
    __shared__ float t[32][33];
    int k0 = blockIdx.x * 32;
    int d0 = blockIdx.y * 32;
    int tx = threadIdx.x, ty = threadIdx.y;   // (32, 8)
    #pragma unroll
    for (int yy = 0; yy < 32; yy += 8)
        t[ty+yy][tx] = W[(size_t)(k0+ty+yy)*DD + d0 + tx];
    __syncthreads();
    #pragma unroll
    for (int yy = 0; yy < 32; yy += 8){
        float v = t[tx][ty+yy];
        size_t idx = (size_t)(d0+ty+yy)*DD + k0 + tx;
        __nv_bfloat16 h = __float2bfloat16(v);
        g_Wthi[idx] = h;
        g_Wtlo[idx] = __float2bfloat16(v - __bfloat162float(h));
    }
}

// ---------------- thresh[b] = ||sum_i e_i||^2 / N^2 ----------------
__global__ void k_thresh(const float* __restrict__ E){
    int b = blockIdx.x; int t = threadIdx.x;
    const float* Eb = E + (size_t)b*NN*DD;
    float s = 0.f;
    for (int i = 0; i < NN; i++) s += Eb[(size_t)i*DD + t];
    __shared__ float red[DD];
    red[t] = s * s;
    __syncthreads();
    for (int o = 64; o > 0; o >>= 1){
        if (t < o) red[t] += red[t+o];
        __syncthreads();
    }
    if (t == 0) g_th[b] = red[0] * (1.f / ((float)NN * (float)NN));
}

// ---------------- shared tile-load / MMA-term macros ----------------
#define TILEB1 (128*PITCH*2)            // 34816

#define LDTILE(dstoff, Src) do { \
    _Pragma("unroll") \
    for (int _p = 0; _p < 8; _p++){ \
        int _cid = tid + 256*_p; \
        int _row = _cid >> 4, _kc = _cid & 15; \
        cp16(sb + (dstoff) + (_row*PITCH + _kc*8)*2, (Src) + (size_t)_row*DD + _kc*8); \
    } \
} while(0)

#define TERM(at, bt) do { \
    _Pragma("unroll 2") \
    for (int ks = 0; ks < 8; ks++){ \
        uint32_t af[4][4], bf[4][2]; \
        _Pragma("unroll") \
        for (int mt = 0; mt < 4; mt++) ldmA(af[mt], sb + (at) + aoff[mt] + ks*32); \
        _Pragma("unroll") \
        for (int nt = 0; nt < 4; nt++) ldmB(bf[nt], sb + (bt) + boff[nt] + ks*32); \
        _Pragma("unroll") \
        for (int mt = 0; mt < 4; mt++) \
            _Pragma("unroll") \
            for (int nt = 0; nt < 4; nt++) \
                mma16816(d[mt][nt], af[mt], bf[nt]); \
    } \
} while(0)

// ---------------- HMMA z^T: D[m=d][n=i] = sum_k Wt[d][k] E[i][k]; + el/er exp tables ----------------
#define SMS_T0 0
#define SMS_T1 TILEB1
#define SMS_T2 (2*TILEB1)
#define SMZ_RED (3*TILEB1)
#define SMEM_Z  (SMZ_RED + 4096)

__global__ void __launch_bounds__(256,2) k_z_mma(const float* __restrict__ attn_l,
                                                 const float* __restrict__ attn_r){
    extern __shared__ char smem[];
    uint32_t sb = sm32(smem);
    float* rel = (float*)(smem + SMZ_RED);
    float* rer = rel + 256;

    int tid = threadIdx.x;
    int wid = tid >> 5, lane = tid & 31;
    int warp_m = wid >> 2, warp_n = wid & 3;
    int g = lane >> 2, t = lane & 3;
    int it = blockIdx.x, b = blockIdx.y;
    int i0 = it * 128;

    uint32_t aoff[4], boff[4];
    #pragma unroll
    for (int mt = 0; mt < 4; mt++)
        aoff[mt] = ((warp_m*64 + mt*16 + (lane & 15))*PITCH + (lane >> 4)*8)*2;
    #pragma unroll
    for (int nt = 0; nt < 4; nt++)
        boff[nt] = ((warp_n*32 + nt*8 + (lane & 7))*PITCH + ((lane >> 3) & 1)*8)*2;

    float d[4][4][4];
    #pragma unroll
    for (int mt = 0; mt < 4; mt++)
        #pragma unroll
        for (int nt = 0; nt < 4; nt++)
            #pragma unroll
            for (int c = 0; c < 4; c++) d[mt][nt][c] = 0.f;

    const __nv_bfloat16* Eh = g_Ehi + (size_t)b*NN*DD + (size_t)i0*DD;
    const __nv_bfloat16* El = g_Elo + (size_t)b*NN*DD + (size_t)i0*DD;

    float al8[8], ar8[8];
    #pragma unroll
    for (int mt = 0; mt < 4; mt++)
        #pragma unroll
        for (int half = 0; half < 2; half++){
            int dloc = warp_m*64 + mt*16 + g + 8*half;
            al8[mt*2+half] = attn_l[dloc];
            ar8[mt*2+half] = attn_r[dloc];
        }

    LDTILE(SMS_T0, g_Wthi);
    LDTILE(SMS_T1, El);
    cp_commit();
    LDTILE(SMS_T2, Eh);
    cp_commit();

    cp_wait1();
    __syncthreads();
    TERM(SMS_T0, SMS_T1);            // Wth * El
    __syncthreads();
    LDTILE(SMS_T1, g_Wtlo);
    cp_commit();
    cp_wait1();
    __syncthreads();
    TERM(SMS_T0, SMS_T2);            // Wth * Eh
    cp_wait0();
    __syncthreads();
    TERM(SMS_T1, SMS_T2);            // Wtl * Eh

    __nv_bfloat16* zh = g_zThi + (size_t)b*DD*NN;
    __nv_bfloat16* zl = g_zTlo + (size_t)b*DD*NN;
    float pel[8], per_[8];
    #pragma unroll
    for (int q = 0; q < 8; q++){ pel[q] = 0.f; per_[q] = 0.f; }
    #pragma unroll
    for (int mt = 0; mt < 4; mt++){
        #pragma unroll
        for (int half = 0; half < 2; half++){
            int dloc = warp_m*64 + mt*16 + g + 8*half;
            float wl = al8[mt*2+half], wr = ar8[mt*2+half];
            #pragma unroll
            for (int nt = 0; nt < 4; nt++){
                float v0 = d[mt][nt][half*2 + 0];
                float v1 = d[mt][nt][half*2 + 1];
                pel[nt*2+0] += wl*v0; pel[nt*2+1] += wl*v1;
                per_[nt*2+0] += wr*v0; per_[nt*2+1] += wr*v1;
                __nv_bfloat16 h0 = __float2bfloat16(v0);
                __nv_bfloat16 h1 = __float2bfloat16(v1);
                __nv_bfloat16 l0 = __float2bfloat16(v0 - __bfloat162float(h0));
                __nv_bfloat16 l1 = __float2bfloat16(v1 - __bfloat162float(h1));
                size_t addr = (size_t)dloc*NN + i0 + warp_n*32 + nt*8 + 2*t;
                *(__nv_bfloat162*)&zh[addr] = __halves2bfloat162(h0, h1);
                *(__nv_bfloat162*)&zl[addr] = __halves2bfloat162(l0, l1);
            }
        }
    }
    #pragma unroll
    for (int q = 0; q < 8; q++){
        pel[q] += __shfl_xor_sync(0xFFFFFFFFu, pel[q], 4);
        pel[q] += __shfl_xor_sync(0xFFFFFFFFu, pel[q], 8);
        pel[q] += __shfl_xor_sync(0xFFFFFFFFu, pel[q], 16);
        per_[q] += __shfl_xor_sync(0xFFFFFFFFu, per_[q], 4);
        per_[q] += __shfl_xor_sync(0xFFFFFFFFu, per_[q], 8);
        per_[q] += __shfl_xor_sync(0xFFFFFFFFu, per_[q], 16);
    }
    __syncthreads();
    if (g == 0){
        #pragma unroll
        for (int nt = 0; nt < 4; nt++)
            #pragma unroll
            for (int par = 0; par < 2; par++){
                int iloc = warp_n*32 + nt*8 + 2*t + par;
                rel[warp_m*128 + iloc] = pel[nt*2+par];
                rer[warp_m*128 + iloc] = per_[nt*2+par];
            }
    }
    __syncthreads();
    if (tid < 128){
        float se = rel[tid] + rel[128 + tid];
        float sr = rer[tid] + rer[128 + tid];
        int gi = b*NN + i0 + tid;
        g_eel [gi] = __expf(se);
        g_eel2[gi] = __expf(0.2f*se);
        g_eer [gi] = __expf(sr);
        g_eer2[gi] = __expf(0.2f*sr);
    }
}

// ---------------- FUSED scores+PV (flash-style, P never leaves registers) ----------------
// Per CTA (jt,b): warps own 16 j rows each. Loop 16 i-chunks of 32:
//   S[16j x 32i] = Ehj*Ehi + Ehj*Eli + Elj*Ehi  (3 HMMA terms, k=d=128)
//   P = mask/exp in regs (cs accumulated), C-frag -> A-frag reuse,
//   h[16j x 128d] += P * (zThi + zTlo)[d][i-chunk]
#define SPV_JH  0
#define SPV_JL  TILEB1                   // 34816
#define SPV_EIH (2*TILEB1)               // 69632
#define SPV_EIL (SPV_EIH + 8704)         // 78336
#define SPV_ZH  (SPV_EIL + 8704)         // 87040
#define SPV_ZL  (SPV_ZH + 10240)         // 97280
#define SPV_ELI (SPV_ZL + 10240)         // 107520
#define SPV_ELI2 (SPV_ELI + 2048)        // 109568
#define SPV_RED SPV_EIH                  // reuse (post-loop only)
#define SMEM_SPV (SPV_ELI2 + 2048)       // 111616

__global__ void __launch_bounds__(256,2) k_spv(const float* __restrict__ bias){
    extern __shared__ char smem[];
    uint32_t sb = sm32(smem);
    float* sEli  = (float*)(smem + SPV_ELI);
    float* sEli2 = (float*)(smem + SPV_ELI2);
    float* red   = (float*)(smem + SPV_RED);

    int tid = threadIdx.x;
    int w = tid >> 5, lane = tid & 31;
    int g = lane >> 2, t = lane & 3;
    int jt = blockIdx.x, b = blockIdx.y;
    int j0 = jt * 128;

    // exp(el) tables for all i
    #pragma unroll
    for (int p = 0; p < 2; p++){
        sEli [tid + 256*p] = g_eel [b*NN + tid + 256*p];
        sEli2[tid + 256*p] = g_eel2[b*NN + tid + 256*p];
    }

    // per-thread j rows + their er values
    int jg0 = j0 + w*16 + g;           // row for c0,c1 ; jg0+8 for c2,c3
    float Er0  = g_eer [b*NN + jg0],     Er1  = g_eer [b*NN + jg0 + 8];
    float Er20 = g_eer2[b*NN + jg0],     Er21 = g_eer2[b*NN + jg0 + 8];
    float th = g_th[b];

    // fragment offsets
    uint32_t aoffJ = ((w*16 + (lane & 15))*PITCH + (lane >> 4)*8)*2;
    uint32_t boffE = (((lane & 7))*PITCH + ((lane >> 3) & 1)*8)*2;     // + nt*8*PITCH*2
    uint32_t boffZ = (((lane & 7))*PITCH2 + ((lane >> 3) & 1)*8)*2;    // + nt_d*8*PITCH2*2 + kt*32

    const __nv_bfloat16* Ehb = g_Ehi + (size_t)b*NN*DD;
    const __nv_bfloat16* Elb = g_Elo + (size_t)b*NN*DD;
    const __nv_bfloat16* zh  = g_zThi + (size_t)b*DD*NN;
    const __nv_bfloat16* zl  = g_zTlo + (size_t)b*DD*NN;

    // issue J tiles + chunk 0 (single group)
    LDTILE(SPV_JH, Ehb + (size_t)j0*DD);
    LDTILE(SPV_JL, Elb + (size_t)j0*DD);

    #define ISSUE_CHUNK(icv) do { \
        const __nv_bfloat16* _eh = Ehb + (size_t)((icv)*32)*DD; \
        const __nv_bfloat16* _el = Elb + (size_t)((icv)*32)*DD; \
        _Pragma("unroll") \
        for (int _p = 0; _p < 2; _p++){ \
            int _cid = tid + 256*_p; \
            int _row = _cid >> 4, _kc = _cid & 15; \
            cp16(sb + SPV_EIH + (_row*PITCH + _kc*8)*2, _eh + (size_t)_row*DD + _kc*8); \
            cp16(sb + SPV_EIL + (_row*PITCH + _kc*8)*2, _el + (size_t)_row*DD + _kc*8); \
        } \
        _Pragma("unroll") \
        for (int _p = 0; _p < 2; _p++){ \
            int _cid = tid + 256*_p; \
            int _row = _cid >> 2, _seg = _cid & 3; \
            cp16(sb + SPV_ZH + (_row*PITCH2 + _seg*8)*2, zh + (size_t)_row*NN + (icv)*32 + _seg*8); \
            cp16(sb + SPV_ZL + (_row*PITCH2 + _seg*8)*2, zl + (size_t)_row*NN + (icv)*32 + _seg*8); \
        } \
        cp_commit(); \
    } while(0)

    ISSUE_CHUNK(0);

    float hacc[16][4];
    #pragma unroll
    for (int q = 0; q < 16; q++)
        #pragma unroll
        for (int c = 0; c < 4; c++) hacc[q][c] = 0.f;
    float cs0 = 0.f, cs1 = 0.f;

    #pragma unroll 1
    for (int ic = 0; ic < 16; ic++){
        cp_wait0();
        __syncthreads();

        // ---- S = Ehj*Ehi + Ehj*Eli + Elj*Ehi  (m16 x n32, k=128)
        float s[4][4];
        #pragma unroll
        for (int nt = 0; nt < 4; nt++)
            #pragma unroll
            for (int c = 0; c < 4; c++) s[nt][c] = 0.f;

        #define STERM(ab, bb) do { \
            _Pragma("unroll 2") \
            for (int ks = 0; ks < 8; ks++){ \
                uint32_t af[4]; \
                ldmA(af, sb + (ab) + aoffJ + ks*32); \
                _Pragma("unroll") \
                for (int nt = 0; nt < 4; nt++){ \
                    uint32_t bf[2]; \
                    ldmB(bf, sb + (bb) + boffE + nt*(8*PITCH*2) + ks*32); \
                    mma16816(s[nt], af, bf); \
                } \
            } \
        } while(0)

        STERM(SPV_JH, SPV_EIH);
        STERM(SPV_JH, SPV_EIL);
        STERM(SPV_JL, SPV_EIH);
        #undef STERM

        // ---- mask/exp -> P in regs; cs accumulate
        int ibase = ic*32;
        #pragma unroll
        for (int nt = 0; nt < 4; nt++){
            #pragma unroll
            for (int c = 0; c < 4; c++){
                int ig = ibase + nt*8 + 2*t + (c & 1);
                int jg = jg0 + 8*(c >> 1);
                float sv = s[nt][c];
                float p = 0.f;
                if (sv > th || ig == jg){
                    float q = sEli[ig] * ((c >> 1) ? Er1 : Er0);
                    p = (q > 1.f) ? q : sEli2[ig] * ((c >> 1) ? Er21 : Er20);
                }
                if (c >> 1) cs1 += p; else cs0 += p;
                s[nt][c] = p;
            }
        }

        // ---- C-frag -> A-frag: pf[kt] covers k=i 16
        uint32_t pf[2][4];
        #pragma unroll
        for (int kt = 0; kt < 2; kt++){
            pf[kt][0] = packbf(s[2*kt][0],   s[2*kt][1]);
            pf[kt][1] = packbf(s[2*kt][2],   s[2*kt][3]);
            pf[kt][2] = packbf(s[2*kt+1][0], s[2*kt+1][1]);
            pf[kt][3] = packbf(s[2*kt+1][2], s[2*kt+1][3]);
        }

        // ---- PV: h[16j][128d] += P * (zh + zl)
        #pragma unroll
        for (int kt = 0; kt < 2; kt++){
            #pragma unroll
            for (int ntd = 0; ntd < 16; ntd++){
                uint32_t bh[2], bl[2];
                ldmB(bh, sb + SPV_ZH + boffZ + ntd*(8*PITCH2*2) + kt*32);
                ldmB(bl, sb + SPV_ZL + boffZ + ntd*(8*PITCH2*2) + kt*32);
                mma16816(hacc[ntd], pf[kt], bh);
                mma16816(hacc[ntd], pf[kt], bl);
            }
        }

        __syncthreads();
        if (ic + 1 < 16) ISSUE_CHUNK(ic+1);
    }
    #undef ISSUE_CHUNK

    // ---- final: cs reduce, /cs, +bias, elu, pool over j
    cs0 += __shfl_xor_sync(0xFFFFFFFFu, cs0, 1);
    cs0 += __shfl_xor_sync(0xFFFFFFFFu, cs0, 2);
    cs1 += __shfl_xor_sync(0xFFFFFFFFu, cs1, 1);
    cs1 += __shfl_xor_sync(0xFFFFFFFFu, cs1, 2);
    float inv0 = 1.f / cs0, inv1 = 1.f / cs1;

    #pragma unroll
    for (int ntd = 0; ntd < 16; ntd++){
        float pd0, pd1;
        {
            float v0 = hacc[ntd][0]*inv0 + bias[ntd*8 + 2*t];
            float v1 = hacc[ntd][1]*inv0 + bias[ntd*8 + 2*t + 1];
            float v2 = hacc[ntd][2]*inv1 + bias[ntd*8 + 2*t];
            float v3 = hacc[ntd][3]*inv1 + bias[ntd*8 + 2*t + 1];
            v0 = v0 > 0.f ? v0 : expm1f(v0);
            v1 = v1 > 0.f ? v1 : expm1f(v1);
            v2 = v2 > 0.f ? v2 : expm1f(v2);
            v3 = v3 > 0.f ? v3 : expm1f(v3);
            pd0 = v0 + v2; pd1 = v1 + v3;
        }
        pd0 += __shfl_xor_sync(0xFFFFFFFFu, pd0, 4);
        pd0 += __shfl_xor_sync(0xFFFFFFFFu, pd0, 8);
        pd0 += __shfl_xor_sync(0xFFFFFFFFu, pd0, 16);
        pd1 += __shfl_xor_sync(0xFFFFFFFFu, pd1, 4);
        pd1 += __shfl_xor_sync(0xFFFFFFFFu, pd1, 8);
        pd1 += __shfl_xor_sync(0xFFFFFFFFu, pd1, 16);
        if (g == 0){
            red[w*128 + ntd*8 + 2*t]     = pd0;
            red[w*128 + ntd*8 + 2*t + 1] = pd1;
        }
    }
    __syncthreads();
    if (tid < 128){
        float tt = 0.f;
        #pragma unroll
        for (int x = 0; x < 8; x++) tt += red[x*128 + tid];
        g_pool[(b*4 + jt)*DD + tid] = tt;
    }
}

// ---------------- final: mean over nodes ----------------
__global__ void k_out(float* __restrict__ out){
    int b = blockIdx.x, d = threadIdx.x;
    float s = g_pool[(b*4+0)*DD + d] + g_pool[(b*4+1)*DD + d]
            + g_pool[(b*4+2)*DD + d] + g_pool[(b*4+3)*DD + d];
    out[b*DD + d] = s * (1.f / (float)NN);
}

extern "C" void kernel_launch(void* const* d_in, const int* in_sizes, int n_in,
                              void* d_out, int out_size){
    const float* E    = (const float*)d_in[0];
    const float* W    = (const float*)d_in[1];
    const float* al   = (const float*)d_in[2];
    const float* ar   = (const float*)d_in[3];
    const float* bias = (const float*)d_in[4];
    float* out = (float*)d_out;

    cudaFuncSetAttribute(k_z_mma, cudaFuncAttributeMaxDynamicSharedMemorySize, SMEM_Z);
    cudaFuncSetAttribute(k_spv,   cudaFuncAttributeMaxDynamicSharedMemorySize, SMEM_SPV);

    k_split <<<4096, 256>>>(E);
    k_Wt    <<<dim3(4,4), dim3(32,8)>>>(W);
    k_thresh<<<64, 128>>>(E);
    k_z_mma <<<dim3(4,64), 256, SMEM_Z>>>(al, ar);
    k_spv   <<<dim3(4,64), 256, SMEM_SPV>>>(bias);
    k_out   <<<64, 128>>>(out);
}

// round 14
// speedup vs baseline: 2.1931x; 1.1083x over previous
#include <cuda_runtime.h>
#include <cuda_bf16.h>
#include <math.h>
#include <stdint.h>

#define BB 64
#define NN 512
#define DD 128
#define PITCH 136   // bf16 elems per smem row (272B): conflict-free ldmatrix
#define PITCH2 40   // bf16 elems per smem row for 32-wide k-chunks (80B)

typedef unsigned long long ull;

__device__ __forceinline__ unsigned sm32(const void* p){
    return (unsigned)__cvta_generic_to_shared(p);
}
__device__ __forceinline__ void cp16(unsigned dst, const void* src){
    asm volatile("cp.async.cg.shared.global [%0], [%1], 16;" :: "r"(dst), "l"(src));
}
__device__ __forceinline__ void cp_commit(){ asm volatile("cp.async.commit_group;"); }
__device__ __forceinline__ void cp_wait0(){ asm volatile("cp.async.wait_group 0;" ::: "memory"); }
__device__ __forceinline__ void cp_wait1(){ asm volatile("cp.async.wait_group 1;" ::: "memory"); }

// ---- warp-level MMA primitives ----
__device__ __forceinline__ void ldmA(uint32_t* a, uint32_t addr){
    asm volatile("ldmatrix.sync.aligned.m8n8.x4.shared.b16 {%0,%1,%2,%3}, [%4];"
        : "=r"(a[0]), "=r"(a[1]), "=r"(a[2]), "=r"(a[3]) : "r"(addr));
}
__device__ __forceinline__ void ldmB4(uint32_t* b, uint32_t addr){
    asm volatile("ldmatrix.sync.aligned.m8n8.x4.shared.b16 {%0,%1,%2,%3}, [%4];"
        : "=r"(b[0]), "=r"(b[1]), "=r"(b[2]), "=r"(b[3]) : "r"(addr));
}
__device__ __forceinline__ void ldmB(uint32_t* b, uint32_t addr){
    asm volatile("ldmatrix.sync.aligned.m8n8.x2.shared.b16 {%0,%1}, [%2];"
        : "=r"(b[0]), "=r"(b[1]) : "r"(addr));
}
__device__ __forceinline__ void mma16816(float* d, const uint32_t* a, const uint32_t* b){
    asm volatile("mma.sync.aligned.m16n8k16.row.col.f32.bf16.bf16.f32 "
        "{%0,%1,%2,%3}, {%4,%5,%6,%7}, {%8,%9}, {%0,%1,%2,%3};"
        : "+f"(d[0]), "+f"(d[1]), "+f"(d[2]), "+f"(d[3])
        : "r"(a[0]), "r"(a[1]), "r"(a[2]), "r"(a[3]), "r"(b[0]), "r"(b[1]));
}
__device__ __forceinline__ uint32_t packbf(float lo, float hi){
    __nv_bfloat162 v = __halves2bfloat162(__float2bfloat16(lo), __float2bfloat16(hi));
    return *(uint32_t*)&v;
}

// Scratch (static device globals; no allocation)
__device__ __nv_bfloat16 g_Ehi[(size_t)BB*NN*DD];
__device__ __nv_bfloat16 g_Elo[(size_t)BB*NN*DD];
__device__ __nv_bfloat16 g_Wthi[DD*DD];
__device__ __nv_bfloat16 g_Wtlo[DD*DD];
__device__ __nv_bfloat16 g_zThi[(size_t)BB*DD*NN];
__device__ __nv_bfloat16 g_zTlo[(size_t)BB*DD*NN];
__device__ float g_psum[BB*8*DD];          // per-chunk column partial sums of E
__device__ float g_eel [BB*NN];
__device__ float g_eel2[BB*NN];
__device__ float g_eer [BB*NN];
__device__ float g_eer2[BB*NN];
__device__ float g_th[BB];
__device__ float g_pool[BB*4*DD];

// ---------------- E -> bf16 hi/lo split + column partial sums ----------------
__global__ void k_split(const float* __restrict__ E){
    __shared__ float4 red[8][32];
    int b = blockIdx.y, rc = blockIdx.x;           // rows rc*64 .. rc*64+63
    int tid = threadIdx.x;
    int r = tid >> 5, d4 = tid & 31;
    const float* Eb = E + (size_t)b*NN*DD + (size_t)rc*64*DD;
    __nv_bfloat16* Eh = g_Ehi + (size_t)b*NN*DD + (size_t)rc*64*DD;
    __nv_bfloat16* El = g_Elo + (size_t)b*NN*DD + (size_t)rc*64*DD;
    float4 ps = make_float4(0.f,0.f,0.f,0.f);
    #pragma unroll
    for (int q = 0; q < 8; q++){
        size_t off = (size_t)(r + q*8)*DD + d4*4;
        float4 v = *(const float4*)(Eb + off);
        __nv_bfloat16 h0 = __float2bfloat16(v.x), h1 = __float2bfloat16(v.y);
        __nv_bfloat16 h2 = __float2bfloat16(v.z), h3 = __float2bfloat16(v.w);
        *(__nv_bfloat162*)&Eh[off]   = __halves2bfloat162(h0, h1);
        *(__nv_bfloat162*)&Eh[off+2] = __halves2bfloat162(h2, h3);
        *(__nv_bfloat162*)&El[off]   = __halves2bfloat162(
            __float2bfloat16(v.x - __bfloat162float(h0)), __float2bfloat16(v.y - __bfloat162float(h1)));
        *(__nv_bfloat162*)&El[off+2] = __halves2bfloat162(
            __float2bfloat16(v.z - __bfloat162float(h2)), __float2bfloat16(v.w - __bfloat162float(h3)));
        ps.x += v.x; ps.y += v.y; ps.z += v.z; ps.w += v.w;
    }
    red[r][d4] = ps;
    __syncthreads();
    if (r == 0){
        float4 s = red[0][d4];
        #pragma unroll
        for (int q = 1; q < 8; q++){
            s.x += red[q][d4].x; s.y += red[q][d4].y;
            s.z += red[q][d4].z; s.w += red[q][d4].w;
        }
        *(float4*)&g_psum[(b*8 + rc)*DD + d4*4] = s;
    }
}

// ---------------- W -> W^T bf16 hi/lo ----------------
__global__ void k_Wt(const float* __restrict__ W){
    __shared__ float t[32][33];
    int k0 = blockIdx.x * 32;
    int d0 = blockIdx.y * 32;
    int tx = threadIdx.x, ty = threadIdx.y;
    #pragma unroll
    for (int yy = 0; yy < 32; yy += 8)
        t[ty+yy][tx] = W[(size_t)(k0+ty+yy)*DD + d0 + tx];
    __syncthreads();
    #pragma unroll
    for (int yy = 0; yy < 32; yy += 8){
        float v = t[tx][ty+yy];
        size_t idx = (size_t)(d0+ty+yy)*DD + k0 + tx;
        __nv_bfloat16 h = __float2bfloat16(v);
        g_Wthi[idx] = h;
        g_Wtlo[idx] = __float2bfloat16(v - __bfloat162float(h));
    }
}

// ---------------- thresh from partial sums ----------------
__global__ void k_thresh(){
    int b = blockIdx.x; int t = threadIdx.x;  // 128 threads
    float s = 0.f;
    #pragma unroll
    for (int q = 0; q < 8; q++) s += g_psum[(b*8 + q)*DD + t];
    __shared__ float red[DD];
    red[t] = s * s;
    __syncthreads();
    for (int o = 64; o > 0; o >>= 1){
        if (t < o) red[t] += red[t+o];
        __syncthreads();
    }
    if (t == 0) g_th[b] = red[0] * (1.f / ((float)NN * (float)NN));
}

// ---------------- shared tile-load / MMA-term macros ----------------
#define TILEB1 (128*PITCH*2)            // 34816

#define LDTILE(dstoff, Src) do { \
    _Pragma("unroll") \
    for (int _p = 0; _p < 8; _p++){ \
        int _cid = tid + 256*_p; \
        int _row = _cid >> 4, _kc = _cid & 15; \
        cp16(sb + (dstoff) + (_row*PITCH + _kc*8)*2, (Src) + (size_t)_row*DD + _kc*8); \
    } \
} while(0)

#define TERM(at, bt) do { \
    _Pragma("unroll 2") \
    for (int ks = 0; ks < 8; ks++){ \
        uint32_t af[4][4], bf[4][2]; \
        _Pragma("unroll") \
        for (int mt = 0; mt < 4; mt++) ldmA(af[mt], sb + (at) + aoff[mt] + ks*32); \
        _Pragma("unroll") \
        for (int nt = 0; nt < 4; nt++) ldmB(bf[nt], sb + (bt) + boff[nt] + ks*32); \
        _Pragma("unroll") \
        for (int mt = 0; mt < 4; mt++) \
            _Pragma("unroll") \
            for (int nt = 0; nt < 4; nt++) \
                mma16816(d[mt][nt], af[mt], bf[nt]); \
    } \
} while(0)

// ---------------- HMMA z^T (unchanged from R12) ----------------
#define SMS_T0 0
#define SMS_T1 TILEB1
#define SMS_T2 (2*TILEB1)
#define SMZ_RED (3*TILEB1)
#define SMEM_Z  (SMZ_RED + 4096)

__global__ void __launch_bounds__(256,2) k_z_mma(const float* __restrict__ attn_l,
                                                 const float* __restrict__ attn_r){
    extern __shared__ char smem[];
    uint32_t sb = sm32(smem);
    float* rel = (float*)(smem + SMZ_RED);
    float* rer = rel + 256;

    int tid = threadIdx.x;
    int wid = tid >> 5, lane = tid & 31;
    int warp_m = wid >> 2, warp_n = wid & 3;
    int g = lane >> 2, t = lane & 3;
    int it = blockIdx.x, b = blockIdx.y;
    int i0 = it * 128;

    uint32_t aoff[4], boff[4];
    #pragma unroll
    for (int mt = 0; mt < 4; mt++)
        aoff[mt] = ((warp_m*64 + mt*16 + (lane & 15))*PITCH + (lane >> 4)*8)*2;
    #pragma unroll
    for (int nt = 0; nt < 4; nt++)
        boff[nt] = ((warp_n*32 + nt*8 + (lane & 7))*PITCH + ((lane >> 3) & 1)*8)*2;

    float d[4][4][4];
    #pragma unroll
    for (int mt = 0; mt < 4; mt++)
        #pragma unroll
        for (int nt = 0; nt < 4; nt++)
            #pragma unroll
            for (int c = 0; c < 4; c++) d[mt][nt][c] = 0.f;

    const __nv_bfloat16* Eh = g_Ehi + (size_t)b*NN*DD + (size_t)i0*DD;
    const __nv_bfloat16* El = g_Elo + (size_t)b*NN*DD + (size_t)i0*DD;

    float al8[8], ar8[8];
    #pragma unroll
    for (int mt = 0; mt < 4; mt++)
        #pragma unroll
        for (int half = 0; half < 2; half++){
            int dloc = warp_m*64 + mt*16 + g + 8*half;
            al8[mt*2+half] = attn_l[dloc];
            ar8[mt*2+half] = attn_r[dloc];
        }

    LDTILE(SMS_T0, g_Wthi);
    LDTILE(SMS_T1, El);
    cp_commit();
    LDTILE(SMS_T2, Eh);
    cp_commit();

    cp_wait1();
    __syncthreads();
    TERM(SMS_T0, SMS_T1);
    __syncthreads();
    LDTILE(SMS_T1, g_Wtlo);
    cp_commit();
    cp_wait1();
    __syncthreads();
    TERM(SMS_T0, SMS_T2);
    cp_wait0();
    __syncthreads();
    TERM(SMS_T1, SMS_T2);

    __nv_bfloat16* zh = g_zThi + (size_t)b*DD*NN;
    __nv_bfloat16* zl = g_zTlo + (size_t)b*DD*NN;
    float pel[8], per_[8];
    #pragma unroll
    for (int q = 0; q < 8; q++){ pel[q] = 0.f; per_[q] = 0.f; }
    #pragma unroll
    for (int mt = 0; mt < 4; mt++){
        #pragma unroll
        for (int half = 0; half < 2; half++){
            int dloc = warp_m*64 + mt*16 + g + 8*half;
            float wl = al8[mt*2+half], wr = ar8[mt*2+half];
            #pragma unroll
            for (int nt = 0; nt < 4; nt++){
                float v0 = d[mt][nt][half*2 + 0];
                float v1 = d[mt][nt][half*2 + 1];
                pel[nt*2+0] += wl*v0; pel[nt*2+1] += wl*v1;
                per_[nt*2+0] += wr*v0; per_[nt*2+1] += wr*v1;
                __nv_bfloat16 h0 = __float2bfloat16(v0);
                __nv_bfloat16 h1 = __float2bfloat16(v1);
                __nv_bfloat16 l0 = __float2bfloat16(v0 - __bfloat162float(h0));
                __nv_bfloat16 l1 = __float2bfloat16(v1 - __bfloat162float(h1));
                size_t addr = (size_t)dloc*NN + i0 + warp_n*32 + nt*8 + 2*t;
                *(__nv_bfloat162*)&zh[addr] = __halves2bfloat162(h0, h1);
                *(__nv_bfloat162*)&zl[addr] = __halves2bfloat162(l0, l1);
            }
        }
    }
    #pragma unroll
    for (int q = 0; q < 8; q++){
        pel[q] += __shfl_xor_sync(0xFFFFFFFFu, pel[q], 4);
        pel[q] += __shfl_xor_sync(0xFFFFFFFFu, pel[q], 8);
        pel[q] += __shfl_xor_sync(0xFFFFFFFFu, pel[q], 16);
        per_[q] += __shfl_xor_sync(0xFFFFFFFFu, per_[q], 4);
        per_[q] += __shfl_xor_sync(0xFFFFFFFFu, per_[q], 8);
        per_[q] += __shfl_xor_sync(0xFFFFFFFFu, per_[q], 16);
    }
    __syncthreads();
    if (g == 0){
        #pragma unroll
        for (int nt = 0; nt < 4; nt++)
            #pragma unroll
            for (int par = 0; par < 2; par++){
                int iloc = warp_n*32 + nt*8 + 2*t + par;
                rel[warp_m*128 + iloc] = pel[nt*2+par];
                rer[warp_m*128 + iloc] = per_[nt*2+par];
            }
    }
    __syncthreads();
    if (tid < 128){
        float se = rel[tid] + rel[128 + tid];
        float sr = rer[tid] + rer[128 + tid];
        int gi = b*NN + i0 + tid;
        g_eel [gi] = __expf(se);
        g_eel2[gi] = __expf(0.2f*se);
        g_eer [gi] = __expf(sr);
        g_eer2[gi] = __expf(0.2f*sr);
    }
}

// ---------------- FUSED scores+PV (x4 B-loads, shared A-frags) ----------------
#define SPV_JH  0
#define SPV_JL  TILEB1
#define SPV_EIH (2*TILEB1)
#define SPV_EIL (SPV_EIH + 8704)
#define SPV_ZH  (SPV_EIL + 8704)
#define SPV_ZL  (SPV_ZH + 10240)
#define SPV_ELI (SPV_ZL + 10240)
#define SPV_ELI2 (SPV_ELI + 2048)
#define SPV_RED SPV_EIH
#define SMEM_SPV (SPV_ELI2 + 2048)

__global__ void __launch_bounds__(256,2) k_spv(const float* __restrict__ bias){
    extern __shared__ char smem[];
    uint32_t sb = sm32(smem);
    float* sEli  = (float*)(smem + SPV_ELI);
    float* sEli2 = (float*)(smem + SPV_ELI2);
    float* red   = (float*)(smem + SPV_RED);

    int tid = threadIdx.x;
    int w = tid >> 5, lane = tid & 31;
    int g = lane >> 2, t = lane & 3;
    int jt = blockIdx.x, b = blockIdx.y;
    int j0 = jt * 128;

    #pragma unroll
    for (int p = 0; p < 2; p++){
        sEli [tid + 256*p] = g_eel [b*NN + tid + 256*p];
        sEli2[tid + 256*p] = g_eel2[b*NN + tid + 256*p];
    }

    int jg0 = j0 + w*16 + g;
    float Er0  = g_eer [b*NN + jg0],     Er1  = g_eer [b*NN + jg0 + 8];
    float Er20 = g_eer2[b*NN + jg0],     Er21 = g_eer2[b*NN + jg0 + 8];
    float th = g_th[b];

    uint32_t aoffJ  = ((w*16 + (lane & 15))*PITCH + (lane >> 4)*8)*2;
    // x4 B: lanes 0-15 -> first n8 group, lanes 16-31 -> next n8 group
    uint32_t boffE4 = (((lane & 7) + ((lane >> 4) << 3))*PITCH  + ((lane >> 3) & 1)*8)*2;
    uint32_t boffZ4 = (((lane & 7) + ((lane >> 4) << 3))*PITCH2 + ((lane >> 3) & 1)*8)*2;

    const __nv_bfloat16* Ehb = g_Ehi + (size_t)b*NN*DD;
    const __nv_bfloat16* Elb = g_Elo + (size_t)b*NN*DD;
    const __nv_bfloat16* zh  = g_zThi + (size_t)b*DD*NN;
    const __nv_bfloat16* zl  = g_zTlo + (size_t)b*DD*NN;

    LDTILE(SPV_JH, Ehb + (size_t)j0*DD);
    LDTILE(SPV_JL, Elb + (size_t)j0*DD);

    #define ISSUE_CHUNK(icv) do { \
        const __nv_bfloat16* _eh = Ehb + (size_t)((icv)*32)*DD; \
        const __nv_bfloat16* _el = Elb + (size_t)((icv)*32)*DD; \
        _Pragma("unroll") \
        for (int _p = 0; _p < 2; _p++){ \
            int _cid = tid + 256*_p; \
            int _row = _cid >> 4, _kc = _cid & 15; \
            cp16(sb + SPV_EIH + (_row*PITCH + _kc*8)*2, _eh + (size_t)_row*DD + _kc*8); \
            cp16(sb + SPV_EIL + (_row*PITCH + _kc*8)*2, _el + (size_t)_row*DD + _kc*8); \
        } \
        _Pragma("unroll") \
        for (int _p = 0; _p < 2; _p++){ \
            int _cid = tid + 256*_p; \
            int _row = _cid >> 2, _seg = _cid & 3; \
            cp16(sb + SPV_ZH + (_row*PITCH2 + _seg*8)*2, zh + (size_t)_row*NN + (icv)*32 + _seg*8); \
            cp16(sb + SPV_ZL + (_row*PITCH2 + _seg*8)*2, zl + (size_t)_row*NN + (icv)*32 + _seg*8); \
        } \
        cp_commit(); \
    } while(0)

    ISSUE_CHUNK(0);

    float hacc[16][4];
    #pragma unroll
    for (int q = 0; q < 16; q++)
        #pragma unroll
        for (int c = 0; c < 4; c++) hacc[q][c] = 0.f;
    float cs0 = 0.f, cs1 = 0.f;

    #pragma unroll 1
    for (int ic = 0; ic < 16; ic++){
        cp_wait0();
        __syncthreads();

        // ---- S = Ehj*Ehi + Ehj*Eli + Elj*Ehi  (shared A-frags, x4 B-loads)
        float s[4][4];
        #pragma unroll
        for (int nt = 0; nt < 4; nt++)
            #pragma unroll
            for (int c = 0; c < 4; c++) s[nt][c] = 0.f;

        #pragma unroll 2
        for (int ks = 0; ks < 8; ks++){
            uint32_t aH[4], aL[4];
            ldmA(aH, sb + SPV_JH + aoffJ + ks*32);
            ldmA(aL, sb + SPV_JL + aoffJ + ks*32);
            uint32_t bH0[4], bH1[4], bL0[4], bL1[4];
            ldmB4(bH0, sb + SPV_EIH + boffE4 + ks*32);
            ldmB4(bH1, sb + SPV_EIH + boffE4 + 16*PITCH*2 + ks*32);
            ldmB4(bL0, sb + SPV_EIL + boffE4 + ks*32);
            ldmB4(bL1, sb + SPV_EIL + boffE4 + 16*PITCH*2 + ks*32);
            mma16816(s[0], aH, &bH0[0]); mma16816(s[1], aH, &bH0[2]);
            mma16816(s[2], aH, &bH1[0]); mma16816(s[3], aH, &bH1[2]);
            mma16816(s[0], aH, &bL0[0]); mma16816(s[1], aH, &bL0[2]);
            mma16816(s[2], aH, &bL1[0]); mma16816(s[3], aH, &bL1[2]);
            mma16816(s[0], aL, &bH0[0]); mma16816(s[1], aL, &bH0[2]);
            mma16816(s[2], aL, &bH1[0]); mma16816(s[3], aL, &bH1[2]);
        }

        // ---- mask/exp -> P in regs; cs accumulate
        int ibase = ic*32;
        #pragma unroll
        for (int nt = 0; nt < 4; nt++){
            #pragma unroll
            for (int c = 0; c < 4; c++){
                int ig = ibase + nt*8 + 2*t + (c & 1);
                int jg = jg0 + 8*(c >> 1);
                float sv = s[nt][c];
                float p = 0.f;
                if (sv > th || ig == jg){
                    float q = sEli[ig] * ((c >> 1) ? Er1 : Er0);
                    p = (q > 1.f) ? q : sEli2[ig] * ((c >> 1) ? Er21 : Er20);
                }
                if (c >> 1) cs1 += p; else cs0 += p;
                s[nt][c] = p;
            }
        }

        // ---- C-frag -> A-frag
        uint32_t pf[2][4];
        #pragma unroll
        for (int kt = 0; kt < 2; kt++){
            pf[kt][0] = packbf(s[2*kt][0],   s[2*kt][1]);
            pf[kt][1] = packbf(s[2*kt][2],   s[2*kt][3]);
            pf[kt][2] = packbf(s[2*kt+1][0], s[2*kt+1][1]);
            pf[kt][3] = packbf(s[2*kt+1][2], s[2*kt+1][3]);
        }

        // ---- PV: h += P * (zh + zl), x4 B-loads cover ntd pairs
        #pragma unroll
        for (int kt = 0; kt < 2; kt++){
            #pragma unroll
            for (int ntp = 0; ntp < 8; ntp++){
                uint32_t bh[4], bl[4];
                ldmB4(bh, sb + SPV_ZH + boffZ4 + ntp*(16*PITCH2*2) + kt*32);
                ldmB4(bl, sb + SPV_ZL + boffZ4 + ntp*(16*PITCH2*2) + kt*32);
                mma16816(hacc[2*ntp],   pf[kt], &bh[0]);
                mma16816(hacc[2*ntp+1], pf[kt], &bh[2]);
                mma16816(hacc[2*ntp],   pf[kt], &bl[0]);
                mma16816(hacc[2*ntp+1], pf[kt], &bl[2]);
            }
        }

        __syncthreads();
        if (ic + 1 < 16) ISSUE_CHUNK(ic+1);
    }
    #undef ISSUE_CHUNK

    // ---- final: cs reduce, /cs, +bias, elu, pool over j
    cs0 += __shfl_xor_sync(0xFFFFFFFFu, cs0, 1);
    cs0 += __shfl_xor_sync(0xFFFFFFFFu, cs0, 2);
    cs1 += __shfl_xor_sync(0xFFFFFFFFu, cs1, 1);
    cs1 += __shfl_xor_sync(0xFFFFFFFFu, cs1, 2);
    float inv0 = 1.f / cs0, inv1 = 1.f / cs1;

    #pragma unroll
    for (int ntd = 0; ntd < 16; ntd++){
        float pd0, pd1;
        {
            float v0 = hacc[ntd][0]*inv0 + bias[ntd*8 + 2*t];
            float v1 = hacc[ntd][1]*inv0 + bias[ntd*8 + 2*t + 1];
            float v2 = hacc[ntd][2]*inv1 + bias[ntd*8 + 2*t];
            float v3 = hacc[ntd][3]*inv1 + bias[ntd*8 + 2*t + 1];
            v0 = v0 > 0.f ? v0 : expm1f(v0);
            v1 = v1 > 0.f ? v1 : expm1f(v1);
            v2 = v2 > 0.f ? v2 : expm1f(v2);
            v3 = v3 > 0.f ? v3 : expm1f(v3);
            pd0 = v0 + v2; pd1 = v1 + v3;
        }
        pd0 += __shfl_xor_sync(0xFFFFFFFFu, pd0, 4);
        pd0 += __shfl_xor_sync(0xFFFFFFFFu, pd0, 8);
        pd0 += __shfl_xor_sync(0xFFFFFFFFu, pd0, 16);
        pd1 += __shfl_xor_sync(0xFFFFFFFFu, pd1, 4);
        pd1 += __shfl_xor_sync(0xFFFFFFFFu, pd1, 8);
        pd1 += __shfl_xor_sync(0xFFFFFFFFu, pd1, 16);
        if (g == 0){
            red[w*128 + ntd*8 + 2*t]     = pd0;
            red[w*128 + ntd*8 + 2*t + 1] = pd1;
        }
    }
    __syncthreads();
    if (tid < 128){
        float tt = 0.f;
        #pragma unroll
        for (int x = 0; x < 8; x++) tt += red[x*128 + tid];
        g_pool[(b*4 + jt)*DD + tid] = tt;
    }
}

// ---------------- final: mean over nodes ----------------
__global__ void k_out(float* __restrict__ out){
    int b = blockIdx.x, d = threadIdx.x;
    float s = g_pool[(b*4+0)*DD + d] + g_pool[(b*4+1)*DD + d]
            + g_pool[(b*4+2)*DD + d] + g_pool[(b*4+3)*DD + d];
    out[b*DD + d] = s * (1.f / (float)NN);
}

extern "C" void kernel_launch(void* const* d_in, const int* in_sizes, int n_in,
                              void* d_out, int out_size){
    const float* E    = (const float*)d_in[0];
    const float* W    = (const float*)d_in[1];
    const float* al   = (const float*)d_in[2];
    const float* ar   = (const float*)d_in[3];
    const float* bias = (const float*)d_in[4];
    float* out = (float*)d_out;

    cudaFuncSetAttribute(k_z_mma, cudaFuncAttributeMaxDynamicSharedMemorySize, SMEM_Z);
    cudaFuncSetAttribute(k_spv,   cudaFuncAttributeMaxDynamicSharedMemorySize, SMEM_SPV);

    k_split <<<dim3(8,64), 256>>>(E);
    k_Wt    <<<dim3(4,4), dim3(32,8)>>>(W);
    k_thresh<<<64, 128>>>();
    k_z_mma <<<dim3(4,64), 256, SMEM_Z>>>(al, ar);
    k_spv   <<<dim3(4,64), 256, SMEM_SPV>>>(bias);
    k_out   <<<64, 128>>>(out);
}